// round 2
// baseline (speedup 1.0000x reference)
#include <cuda_runtime.h>
#include <math.h>

#define S   256
#define SB  255     // number of scan steps (S-1)
#define B   4096
#define H   256
#define E   32
#define MM  20
#define G4  1024    // 4*H
#define KTOT 532    // MM + H + H

// ---- scratch (static device globals; allocation-free) ----
__device__ float g_T  [(size_t)SB*B*H];   // time gate per step
__device__ float g_hs1[(size_t)SB*B*H];   // shared-path hidden per step
__device__ float g_H1 [(size_t)SB*B*H];   // private hidden per step
__device__ float g_c  [(size_t)B*H];      // private cell state (carried)
__device__ float g_pre[(size_t)B*G4];     // per-step gate preactivations

__device__ __forceinline__ float sigmoidf_(float x) { return 1.f / (1.f + expf(-x)); }

// ============================================================
// K1: parallel precompute of T[t] and hs1[t] for all (t, b)
// grid (SB, B), block 256 (one thread per hidden unit j)
// ============================================================
__global__ void k_pre(const float* __restrict__ val_seq, const float* __restrict__ delta,
                      const float* __restrict__ W_d,  const float* __restrict__ b_d,
                      const float* __restrict__ W_xt, const float* __restrict__ W_dt,
                      const float* __restrict__ b_t,
                      const float* __restrict__ W_x_s, const float* __restrict__ b_s)
{
    int t = blockIdx.x;
    int b = blockIdx.y;
    int j = threadIdx.x;           // 0..255

    __shared__ float sx[MM];
    __shared__ float sdemb[E];
    if (j < MM) sx[j] = val_seq[(size_t)t*B*MM + (size_t)b*MM + j];
    if (j < E) {
        float d = delta[(size_t)t*B + b];
        sdemb[j] = tanhf(d * W_d[j] + b_d[j]);
    }
    __syncthreads();

    // time gate T = sigmoid(x@W_xt + sigmoid(demb@W_dt) + b_t)
    float tx = b_t[j];
    #pragma unroll
    for (int k = 0; k < MM; k++) tx += sx[k] * W_xt[k*H + j];
    float td = 0.f;
    #pragma unroll
    for (int e = 0; e < E; e++) td += sdemb[e] * W_dt[e*H + j];
    float T = sigmoidf_(tx + sigmoidf_(td));

    // shared path: pre_s = x@W_x_s + b_s (hs=0); cs=0 so f-gate drops out
    float is = b_s[j], os = b_s[j + 2*H], gs = b_s[j + 3*H];
    #pragma unroll
    for (int k = 0; k < MM; k++) {
        float xv = sx[k];
        const float* w = W_x_s + (size_t)k*G4;
        is += xv * w[j];
        os += xv * w[j + 2*H];
        gs += xv * w[j + 3*H];
    }
    float cns = sigmoidf_(is) * T * tanhf(gs);
    float hs1 = sigmoidf_(os) * tanhf(cns);

    size_t idx = (size_t)t*B*H + (size_t)b*H + j;
    g_T[idx]   = T;
    g_hs1[idx] = hs1;
}

// ============================================================
// K2: per-step GEMM  pre[B,1024] = [x | hs1 | h_prev] @ [W_x_p; W_s_p; W_h_p] + b_p
// 64x64 block tile, 256 threads, 4x4 microtile, K tiles of 16
// ============================================================
#define BMT 64
#define BNT 64
#define BKT 16

__global__ void k_gemm(const float* __restrict__ val_seq,
                       const float* __restrict__ W_x_p,
                       const float* __restrict__ W_h_p,
                       const float* __restrict__ W_s_p,
                       const float* __restrict__ b_p,
                       int t)
{
    __shared__ float As[BKT][BMT];   // transposed: [k][row]
    __shared__ float Bs[BKT][BNT];   // [k][col]

    int row0 = blockIdx.x * BMT;
    int col0 = blockIdx.y * BNT;
    int tid  = threadIdx.x;          // 0..255
    int tx   = tid & 15, ty = tid >> 4;

    const float* x_t   = val_seq + (size_t)t*B*MM;
    const float* hs1_t = g_hs1   + (size_t)t*B*H;
    const float* hp    = (t > 0) ? (g_H1 + (size_t)(t-1)*B*H) : nullptr;

    float acc[4][4] = {};

    for (int k0 = 0; k0 < KTOT; k0 += BKT) {
        // load A tile (BMT x BKT = 1024 elems, 4 per thread)
        #pragma unroll
        for (int i = 0; i < 4; i++) {
            int e = tid + i*256;
            int r = e >> 4;          // row within tile
            int k = e & 15;
            int kk = k0 + k;
            int row = row0 + r;
            float v = 0.f;
            if (kk < MM)            v = x_t[(size_t)row*MM + kk];
            else if (kk < MM + H)   v = hs1_t[(size_t)row*H + (kk - MM)];
            else if (kk < KTOT)     v = hp ? hp[(size_t)row*H + (kk - MM - H)] : 0.f;
            As[k][r] = v;
        }
        // load B tile (BKT x BNT)
        #pragma unroll
        for (int i = 0; i < 4; i++) {
            int e = tid + i*256;
            int k = e >> 6;          // e / 64
            int c = e & 63;
            int kk = k0 + k;
            int col = col0 + c;
            float v = 0.f;
            if (kk < MM)            v = W_x_p[(size_t)kk*G4 + col];
            else if (kk < MM + H)   v = W_s_p[(size_t)(kk - MM)*G4 + col];
            else if (kk < KTOT)     v = W_h_p[(size_t)(kk - MM - H)*G4 + col];
            Bs[k][c] = v;
        }
        __syncthreads();

        #pragma unroll
        for (int k = 0; k < BKT; k++) {
            float4 a  = *(const float4*)&As[k][ty*4];
            float4 bv = *(const float4*)&Bs[k][tx*4];
            float av[4] = {a.x, a.y, a.z, a.w};
            float bb[4] = {bv.x, bv.y, bv.z, bv.w};
            #pragma unroll
            for (int i = 0; i < 4; i++)
                #pragma unroll
                for (int jj = 0; jj < 4; jj++)
                    acc[i][jj] += av[i] * bb[jj];
        }
        __syncthreads();
    }

    #pragma unroll
    for (int i = 0; i < 4; i++) {
        int row = row0 + ty*4 + i;
        #pragma unroll
        for (int jj = 0; jj < 4; jj++) {
            int col = col0 + tx*4 + jj;
            g_pre[(size_t)row*G4 + col] = acc[i][jj] + b_p[col];
        }
    }
}

// ============================================================
// K3: per-step elementwise cell update
// ============================================================
__global__ void k_cell(int t)
{
    int idx = blockIdx.x * blockDim.x + threadIdx.x;   // over B*H
    int b = idx >> 8;
    int j = idx & 255;
    const float* pre = g_pre + (size_t)b*G4;
    float i_ = pre[j], f_ = pre[j + H], o_ = pre[j + 2*H], g_ = pre[j + 3*H];
    float T = g_T[(size_t)t*B*H + idx];
    float cprev = (t > 0) ? g_c[idx] : 0.f;
    float cn = sigmoidf_(f_) * cprev + sigmoidf_(i_) * T * tanhf(g_);
    g_c[idx] = cn;
    g_H1[(size_t)t*B*H + idx] = sigmoidf_(o_) * tanhf(cn);
}

// ============================================================
// K4: parallel output heads for all (t, b): softmax(h1@Wc+bc), h1@Wm+bm
// grid (SB, B/32), block 256
// ============================================================
#define RPB 32
__global__ void k_out(const float* __restrict__ Wc, const float* __restrict__ bc,
                      const float* __restrict__ Wm, const float* __restrict__ bm,
                      float* __restrict__ out)
{
    int t  = blockIdx.x;
    int b0 = blockIdx.y * RPB;

    __shared__ float sh[RPB][H];      // 32 KB
    __shared__ float sl[RPB][25];

    const float* h1 = g_H1 + (size_t)t*B*H + (size_t)b0*H;
    for (int e = threadIdx.x; e < RPB*H; e += blockDim.x)
        sh[e >> 8][e & 255] = h1[e];
    __syncthreads();

    for (int o = threadIdx.x; o < RPB*25; o += blockDim.x) {
        int r = o / 25, j = o % 25;
        const float* hrow = sh[r];
        float s;
        if (j < 3) {
            s = bc[j];
            #pragma unroll 8
            for (int k = 0; k < H; k++) s += hrow[k] * Wc[k*3 + j];
        } else {
            int jj = j - 3;
            s = bm[jj];
            #pragma unroll 8
            for (int k = 0; k < H; k++) s += hrow[k] * Wm[k*22 + jj];
        }
        sl[r][j] = s;
    }
    __syncthreads();

    float* out_cat = out;
    float* out_val = out + (size_t)SB*B*3;
    for (int o = threadIdx.x; o < RPB*25; o += blockDim.x) {
        int r = o / 25, j = o % 25;
        int b = b0 + r;
        if (j < 3) {
            float l0 = sl[r][0], l1 = sl[r][1], l2 = sl[r][2];
            float m  = fmaxf(l0, fmaxf(l1, l2));
            float e0 = expf(l0 - m), e1 = expf(l1 - m), e2 = expf(l2 - m);
            float inv = 1.f / (e0 + e1 + e2);
            float v = (j == 0 ? e0 : (j == 1 ? e1 : e2)) * inv;
            out_cat[(size_t)t*B*3 + (size_t)b*3 + j] = v;
        } else {
            out_val[(size_t)t*B*22 + (size_t)b*22 + (j - 3)] = sl[r][j];
        }
    }
}

// ============================================================
// launch
// ============================================================
extern "C" void kernel_launch(void* const* d_in, const int* in_sizes, int n_in,
                              void* d_out, int out_size)
{
    // metadata order (setup_inputs dict order):
    // 0 cat_seq (unused), 1 val_seq, 2 delta, 3 W_d, 4 b_d, 5 W_xt, 6 W_dt, 7 b_t,
    // 8 W_x_s, 9 W_h_s (unused), 10 b_s, 11 W_x_p, 12 W_h_p, 13 W_s_p, 14 b_p,
    // 15 Wc, 16 bc, 17 Wm, 18 bm, 19 task_name (unused)
    const float* val_seq = (const float*)d_in[1];
    const float* delta   = (const float*)d_in[2];
    const float* W_d     = (const float*)d_in[3];
    const float* b_d     = (const float*)d_in[4];
    const float* W_xt    = (const float*)d_in[5];
    const float* W_dt    = (const float*)d_in[6];
    const float* b_t     = (const float*)d_in[7];
    const float* W_x_s   = (const float*)d_in[8];
    const float* b_s     = (const float*)d_in[10];
    const float* W_x_p   = (const float*)d_in[11];
    const float* W_h_p   = (const float*)d_in[12];
    const float* W_s_p   = (const float*)d_in[13];
    const float* b_p     = (const float*)d_in[14];
    const float* Wc      = (const float*)d_in[15];
    const float* bc      = (const float*)d_in[16];
    const float* Wm      = (const float*)d_in[17];
    const float* bm      = (const float*)d_in[18];
    float* out = (float*)d_out;

    // Phase 1: parallel precompute of T and hs1 for all steps
    k_pre<<<dim3(SB, B), 256>>>(val_seq, delta, W_d, b_d, W_xt, W_dt, b_t, W_x_s, b_s);

    // Phase 2: sequential recurrence (only h @ W_h_p is truly sequential)
    for (int t = 0; t < SB; t++) {
        k_gemm<<<dim3(B/BMT, G4/BNT), 256>>>(val_seq, W_x_p, W_h_p, W_s_p, b_p, t);
        k_cell<<<(B*H)/256, 256>>>(t);
    }

    // Phase 3: parallel output heads
    k_out<<<dim3(SB, B/RPB), 256>>>(Wc, bc, Wm, bm, out);
}

// round 4
// speedup vs baseline: 3.1257x; 3.1257x over previous
#include <cuda_runtime.h>
#include <cuda_bf16.h>
#include <math.h>
#include <stdint.h>

#define S    256
#define SB   255
#define B    4096
#define H    256
#define E    32
#define MM   20
#define G4   1024
#define KTOT 544          // 20 x | 256 hs1 | 1 one | 11 zero | 256 h_prev
#define KSTAT 288
#define MT   128
#define NT   256
#define KCH  32

// ---------------- scratch (static device globals; allocation-free) ----------------
__device__ __align__(256) float g_T  [(size_t)SB*H*B];     // [t][j][b]
__device__ __align__(256) float g_Ap [(size_t)SB*KSTAT*B]; // [t][k][b] static A rows
__device__ __align__(256) float g_H1t[(size_t)SB*H*B];     // [t][j][b] private hidden
__device__ __align__(256) float g_c  [(size_t)H*B];        // [j][b] cell state
__device__ __align__(256) __nv_bfloat16 g_Wb_hi[(size_t)KTOT*G4]; // [k][n'], gate-interleaved
__device__ __align__(256) __nv_bfloat16 g_Wb_lo[(size_t)KTOT*G4];

__device__ __forceinline__ float sigmoidf_(float x) { return 1.f / (1.f + expf(-x)); }

__device__ __forceinline__ uint32_t smem_u32(const void* p) {
    uint32_t a;
    asm("{ .reg .u64 t; cvta.to.shared.u64 t, %1; cvt.u32.u64 %0, t; }" : "=r"(a) : "l"(p));
    return a;
}
__device__ __forceinline__ void ldsm4(uint32_t* r, uint32_t addr) {
    asm volatile("ldmatrix.sync.aligned.m8n8.x4.shared.b16 {%0,%1,%2,%3}, [%4];"
        : "=r"(r[0]), "=r"(r[1]), "=r"(r[2]), "=r"(r[3]) : "r"(addr));
}
__device__ __forceinline__ void ldsm4t(uint32_t* r, uint32_t addr) {
    asm volatile("ldmatrix.sync.aligned.m8n8.x4.trans.shared.b16 {%0,%1,%2,%3}, [%4];"
        : "=r"(r[0]), "=r"(r[1]), "=r"(r[2]), "=r"(r[3]) : "r"(addr));
}
__device__ __forceinline__ void mma_bf16(float* d, const uint32_t* a, const uint32_t* b) {
    asm volatile("mma.sync.aligned.m16n8k16.row.col.f32.bf16.bf16.f32 "
        "{%0,%1,%2,%3}, {%4,%5,%6,%7}, {%8,%9}, {%0,%1,%2,%3};"
        : "+f"(d[0]), "+f"(d[1]), "+f"(d[2]), "+f"(d[3])
        : "r"(a[0]), "r"(a[1]), "r"(a[2]), "r"(a[3]), "r"(b[0]), "r"(b[1]));
}

// ============================================================
// k_packw: pack weights [k][n'] bf16 hi/lo; n' = j*4 + gate (source col = gate*256 + j)
// rows: 0-19 W_x_p | 20-275 W_s_p | 276 bias | 277-287 zero | 288-543 W_h_p
// ============================================================
__global__ void k_packw(const float* __restrict__ W_x_p, const float* __restrict__ W_h_p,
                        const float* __restrict__ W_s_p, const float* __restrict__ b_p)
{
    int idx = blockIdx.x * blockDim.x + threadIdx.x;
    if (idx >= KTOT * G4) return;
    int k  = idx >> 10;
    int np = idx & 1023;
    int j = np >> 2, g = np & 3;
    int col = g * H + j;
    float v;
    if (k < MM)            v = W_x_p[(size_t)k * G4 + col];
    else if (k < MM + H)   v = W_s_p[(size_t)(k - MM) * G4 + col];
    else if (k == 276)     v = b_p[col];
    else if (k < KSTAT)    v = 0.f;
    else                   v = W_h_p[(size_t)(k - KSTAT) * G4 + col];
    __nv_bfloat16 hv = __float2bfloat16(v);
    g_Wb_hi[idx] = hv;
    g_Wb_lo[idx] = __float2bfloat16(v - __bfloat162float(hv));
}

// ============================================================
// k_pre: T[t][j][b] and static A rows (x, hs1, bias, zero) in [t][k][b] layout
// grid (SB, B/64), block 256
// ============================================================
__global__ void k_pre(const float* __restrict__ val_seq, const float* __restrict__ delta,
                      const float* __restrict__ W_d,  const float* __restrict__ b_d,
                      const float* __restrict__ W_xt, const float* __restrict__ W_dt,
                      const float* __restrict__ b_t,
                      const float* __restrict__ W_x_s, const float* __restrict__ b_s)
{
    __shared__ float sx[64][20];
    __shared__ float sde[64][32];
    __shared__ float sT[256][16];
    __shared__ float sH[256][16];
    int t = blockIdx.x;
    int b0 = blockIdx.y * 64;
    int tid = threadIdx.x;

    for (int e = tid; e < 64 * 20; e += 256) {
        int b = e / 20, k = e % 20;
        sx[b][k] = val_seq[((size_t)t * B + b0 + b) * MM + k];
    }
    for (int e = tid; e < 64 * 32; e += 256) {
        int b = e >> 5, ee = e & 31;
        float dd = delta[(size_t)t * B + b0 + b];
        sde[b][ee] = tanhf(dd * W_d[ee] + b_d[ee]);
    }
    __syncthreads();

    int j = tid;
    float wxt[20], wdt[32], wi[20], wo[20], wg[20];
    #pragma unroll
    for (int k = 0; k < 20; k++) wxt[k] = W_xt[k * H + j];
    #pragma unroll
    for (int e = 0; e < 32; e++) wdt[e] = W_dt[e * H + j];
    #pragma unroll
    for (int k = 0; k < 20; k++) {
        wi[k] = W_x_s[k * G4 + j];
        wo[k] = W_x_s[k * G4 + 2 * H + j];
        wg[k] = W_x_s[k * G4 + 3 * H + j];
    }
    float bt = b_t[j], bi = b_s[j], bo = b_s[2 * H + j], bg = b_s[3 * H + j];

    for (int bc = 0; bc < 4; bc++) {
        #pragma unroll 1
        for (int bl = 0; bl < 16; bl++) {
            int b = bc * 16 + bl;
            float tx = bt, td = 0.f, ai = bi, ao = bo, ag = bg;
            #pragma unroll
            for (int k = 0; k < 20; k++) {
                float xv = sx[b][k];
                tx += xv * wxt[k]; ai += xv * wi[k]; ao += xv * wo[k]; ag += xv * wg[k];
            }
            #pragma unroll
            for (int e = 0; e < 32; e++) td += sde[b][e] * wdt[e];
            float T = sigmoidf_(tx + sigmoidf_(td));
            float cns = sigmoidf_(ai) * T * tanhf(ag);
            sT[j][bl] = T;
            sH[j][bl] = sigmoidf_(ao) * tanhf(cns);
        }
        __syncthreads();
        size_t bb = (size_t)b0 + bc * 16;
        for (int e = tid; e < 256 * 16; e += 256) {
            int jj = e >> 4, bl = e & 15;
            g_T [((size_t)t * H + jj) * B + bb + bl]          = sT[jj][bl];
            g_Ap[((size_t)t * KSTAT + MM + jj) * B + bb + bl] = sH[jj][bl];
        }
        for (int e = tid; e < 32 * 16; e += 256) {
            int k = e >> 4, bl = e & 15;
            int row = (k < MM) ? k : (256 + k);   // rows 276..287 for k=20..31
            float v = (k < MM) ? sx[bc * 16 + bl][k] : (k == MM ? 1.f : 0.f);
            g_Ap[((size_t)t * KSTAT + row) * B + bb + bl] = v;
        }
        __syncthreads();
    }
}

// ============================================================
// k_step: per-step bf16 split-precision mma.sync GEMM + fused cell update
// grid (32, 4), 512 threads (16 warps: 4M x 4N), warp tile 32x64
// ============================================================
#define APAD 40     // A row stride in bf16 elems (80B -> conflict-free ldmatrix)
#define BPAD 264    // B row stride in bf16 elems (528B -> conflict-free ldmatrix)
#define ST_A_HI 0
#define ST_A_LO (MT * APAD * 2)             // 10240
#define ST_B_HI (2 * MT * APAD * 2)         // 20480
#define ST_B_LO (ST_B_HI + KCH * BPAD * 2)  // 37376
#define STAGE   (ST_B_LO + KCH * BPAD * 2)  // 54272

__global__ void __launch_bounds__(512, 1) k_step(int t)
{
    extern __shared__ __align__(16) char sm[];
    int tid = threadIdx.x, lane = tid & 31, wid = tid >> 5;
    int wm = wid & 3, wn = wid >> 2;
    int m0 = blockIdx.x * MT, n0 = blockIdx.y * NT;
    uint32_t smb = smem_u32(sm);
    int nch = (t == 0) ? 9 : 17;
    const float* __restrict__ Ap = g_Ap + (size_t)t * KSTAT * B;
    const float* __restrict__ Hp = g_H1t + ((size_t)t - 1) * H * B;  // deref'd only when t>0

    float acc[2][8][4];
    #pragma unroll
    for (int a = 0; a < 2; a++)
        #pragma unroll
        for (int b = 0; b < 8; b++)
            #pragma unroll
            for (int c = 0; c < 4; c++) acc[a][b][c] = 0.f;

    float pa[8];
    uint4 pbh[2], pbl[2];
    int a_m = tid & 127, a_c0 = tid >> 7;

    // ---- prefetch chunk 0 ----
    #pragma unroll
    for (int i = 0; i < 8; i++) {
        int kk = a_c0 + i * 4;                      // chunk 0 => kk < 32 < KSTAT
        pa[i] = Ap[(size_t)kk * B + m0 + a_m];
    }
    #pragma unroll
    for (int i = 0; i < 2; i++) {
        int u = tid + i * 512;
        int n8 = u & 31, kk2 = u >> 5;
        size_t gi = (size_t)kk2 * G4 + n0 + n8 * 8;
        pbh[i] = *(const uint4*)(g_Wb_hi + gi);
        pbl[i] = *(const uint4*)(g_Wb_lo + gi);
    }
    // ---- store chunk 0 ----
    {
        char* st = sm;
        #pragma unroll
        for (int i = 0; i < 8; i++) {
            int cc = a_c0 + i * 4;
            float v = pa[i];
            __nv_bfloat16 hv = __float2bfloat16(v);
            ((__nv_bfloat16*)(st + ST_A_HI))[a_m * APAD + cc] = hv;
            ((__nv_bfloat16*)(st + ST_A_LO))[a_m * APAD + cc] = __float2bfloat16(v - __bfloat162float(hv));
        }
        #pragma unroll
        for (int i = 0; i < 2; i++) {
            int u = tid + i * 512;
            int n8 = u & 31, kk2 = u >> 5;
            *(uint4*)(st + ST_B_HI + (kk2 * BPAD + n8 * 8) * 2) = pbh[i];
            *(uint4*)(st + ST_B_LO + (kk2 * BPAD + n8 * 8) * 2) = pbl[i];
        }
    }
    __syncthreads();

    // per-lane ldmatrix offsets
    uint32_t a_loff = (uint32_t)(((wm * 32 + (lane & 15)) * APAD + ((lane >> 4) * 8)) * 2);
    uint32_t b_loff = (uint32_t)((((lane & 7) + ((lane >> 3) & 1) * 8) * BPAD + wn * 64 + (lane >> 4) * 8) * 2);

    for (int c = 0; c < nch; c++) {
        // prefetch chunk c+1
        if (c + 1 < nch) {
            int kk0 = (c + 1) * KCH;
            #pragma unroll
            for (int i = 0; i < 8; i++) {
                int kk = kk0 + a_c0 + i * 4;
                const float* src = (kk < KSTAT) ? (Ap + (size_t)kk * B) : (Hp + (size_t)(kk - KSTAT) * B);
                pa[i] = src[m0 + a_m];
            }
            #pragma unroll
            for (int i = 0; i < 2; i++) {
                int u = tid + i * 512;
                int n8 = u & 31, kk2 = u >> 5;
                size_t gi = (size_t)(kk0 + kk2) * G4 + n0 + n8 * 8;
                pbh[i] = *(const uint4*)(g_Wb_hi + gi);
                pbl[i] = *(const uint4*)(g_Wb_lo + gi);
            }
        }

        // MMA on chunk c
        uint32_t sb = smb + (uint32_t)(c & 1) * STAGE;
        #pragma unroll
        for (int kf = 0; kf < 2; kf++) {
            uint32_t ah[2][4], al[2][4];
            #pragma unroll
            for (int mf = 0; mf < 2; mf++) {
                uint32_t ao = sb + a_loff + (uint32_t)((mf * 16 * APAD + kf * 16) * 2);
                ldsm4(ah[mf], ao + ST_A_HI);
                ldsm4(al[mf], ao + ST_A_LO);
            }
            #pragma unroll
            for (int nfp = 0; nfp < 4; nfp++) {
                uint32_t bo = sb + b_loff + (uint32_t)((kf * 16 * BPAD + nfp * 16) * 2);
                uint32_t bh[4], bl[4];
                ldsm4t(bh, bo + ST_B_HI);
                ldsm4t(bl, bo + ST_B_LO);
                #pragma unroll
                for (int mf = 0; mf < 2; mf++) {
                    mma_bf16(acc[mf][2 * nfp],     ah[mf], bh);
                    mma_bf16(acc[mf][2 * nfp],     ah[mf], bl);
                    mma_bf16(acc[mf][2 * nfp],     al[mf], bh);
                    mma_bf16(acc[mf][2 * nfp + 1], ah[mf], bh + 2);
                    mma_bf16(acc[mf][2 * nfp + 1], ah[mf], bl + 2);
                    mma_bf16(acc[mf][2 * nfp + 1], al[mf], bh + 2);
                }
            }
        }

        // store chunk c+1 to the other buffer
        if (c + 1 < nch) {
            char* st = sm + ((c + 1) & 1) * STAGE;
            #pragma unroll
            for (int i = 0; i < 8; i++) {
                int cc = a_c0 + i * 4;
                float v = pa[i];
                __nv_bfloat16 hv = __float2bfloat16(v);
                ((__nv_bfloat16*)(st + ST_A_HI))[a_m * APAD + cc] = hv;
                ((__nv_bfloat16*)(st + ST_A_LO))[a_m * APAD + cc] = __float2bfloat16(v - __bfloat162float(hv));
            }
            #pragma unroll
            for (int i = 0; i < 2; i++) {
                int u = tid + i * 512;
                int n8 = u & 31, kk2 = u >> 5;
                *(uint4*)(st + ST_B_HI + (kk2 * BPAD + n8 * 8) * 2) = pbh[i];
                *(uint4*)(st + ST_B_LO + (kk2 * BPAD + n8 * 8) * 2) = pbl[i];
            }
        }
        __syncthreads();
    }

    // ---- fused cell epilogue ----
    // acc frag (m16n8): d0=(r,c0) d1=(r,c0+1) d2=(r+8,c0) d3=(r+8,c0+1), c0=(lane%4)*2
    // gate interleave n' = j*4+g: lane pair (xor 1) covers the 4 gates of one j
    int odd = lane & 1;
    int cpair = (lane >> 1) & 1;
    int r_lane = lane >> 2;
    #pragma unroll
    for (int mf = 0; mf < 2; mf++) {
        int row_e = wm * 32 + mf * 16 + r_lane + (odd ? 8 : 0);
        int bglob = m0 + row_e;
        #pragma unroll
        for (int nt = 0; nt < 8; nt++) {
            float d0 = acc[mf][nt][0], d1 = acc[mf][nt][1];
            float d2 = acc[mf][nt][2], d3 = acc[mf][nt][3];
            float s1 = odd ? d0 : d2;
            float s2 = odd ? d1 : d3;
            float r1 = __shfl_xor_sync(0xffffffffu, s1, 1);
            float r2 = __shfl_xor_sync(0xffffffffu, s2, 1);
            float fi = odd ? r1 : d0;
            float ff = odd ? r2 : d1;
            float fo = odd ? d2 : r1;
            float fg = odd ? d3 : r2;
            int j = blockIdx.y * 64 + wn * 16 + nt * 2 + cpair;
            size_t ix = (size_t)j * B + bglob;
            float T = g_T[(size_t)t * H * B + ix];
            float cp = (t > 0) ? g_c[ix] : 0.f;
            float cn = sigmoidf_(ff) * cp + sigmoidf_(fi) * T * tanhf(fg);
            g_c[ix] = cn;
            g_H1t[(size_t)t * H * B + ix] = sigmoidf_(fo) * tanhf(cn);
        }
    }
}

// ============================================================
// k_out: output heads from transposed h1
// ============================================================
__global__ void k_out(const float* __restrict__ Wc, const float* __restrict__ bc,
                      const float* __restrict__ Wm, const float* __restrict__ bm,
                      float* __restrict__ out)
{
    __shared__ float sh[256][32];
    __shared__ float sl[32][25];
    int t = blockIdx.x;
    int b0 = blockIdx.y * 32;
    int tid = threadIdx.x;

    for (int e = tid; e < 256 * 32; e += 256) {
        int jj = e >> 5, b = e & 31;
        sh[jj][b] = g_H1t[((size_t)t * H + jj) * B + b0 + b];
    }
    __syncthreads();

    for (int o = tid; o < 32 * 25; o += 256) {
        int r = o / 25, jx = o % 25;
        float s;
        if (jx < 3) {
            s = bc[jx];
            #pragma unroll 8
            for (int k = 0; k < H; k++) s += sh[k][r] * Wc[k * 3 + jx];
        } else {
            int jj = jx - 3;
            s = bm[jj];
            #pragma unroll 8
            for (int k = 0; k < H; k++) s += sh[k][r] * Wm[k * 22 + jj];
        }
        sl[r][jx] = s;
    }
    __syncthreads();

    float* out_cat = out;
    float* out_val = out + (size_t)SB * B * 3;
    for (int o = tid; o < 32 * 25; o += 256) {
        int r = o / 25, jx = o % 25;
        int b = b0 + r;
        if (jx < 3) {
            float l0 = sl[r][0], l1 = sl[r][1], l2 = sl[r][2];
            float mx = fmaxf(l0, fmaxf(l1, l2));
            float e0 = expf(l0 - mx), e1 = expf(l1 - mx), e2 = expf(l2 - mx);
            float inv = 1.f / (e0 + e1 + e2);
            float v = (jx == 0 ? e0 : (jx == 1 ? e1 : e2)) * inv;
            out_cat[(size_t)t * B * 3 + (size_t)b * 3 + jx] = v;
        } else {
            out_val[(size_t)t * B * 22 + (size_t)b * 22 + (jx - 3)] = sl[r][jx];
        }
    }
}

// ============================================================
// launch
// ============================================================
extern "C" void kernel_launch(void* const* d_in, const int* in_sizes, int n_in,
                              void* d_out, int out_size)
{
    const float* val_seq = (const float*)d_in[1];
    const float* delta   = (const float*)d_in[2];
    const float* W_d     = (const float*)d_in[3];
    const float* b_d     = (const float*)d_in[4];
    const float* W_xt    = (const float*)d_in[5];
    const float* W_dt    = (const float*)d_in[6];
    const float* b_t     = (const float*)d_in[7];
    const float* W_x_s   = (const float*)d_in[8];
    const float* b_s     = (const float*)d_in[10];
    const float* W_x_p   = (const float*)d_in[11];
    const float* W_h_p   = (const float*)d_in[12];
    const float* W_s_p   = (const float*)d_in[13];
    const float* b_p     = (const float*)d_in[14];
    const float* Wc      = (const float*)d_in[15];
    const float* bcv     = (const float*)d_in[16];
    const float* Wm      = (const float*)d_in[17];
    const float* bm      = (const float*)d_in[18];
    float* out = (float*)d_out;

    cudaFuncSetAttribute(k_step, cudaFuncAttributeMaxDynamicSharedMemorySize, 2 * STAGE);

    k_packw<<<(KTOT * G4 + 255) / 256, 256>>>(W_x_p, W_h_p, W_s_p, b_p);
    k_pre<<<dim3(SB, B / 64), 256>>>(val_seq, delta, W_d, b_d, W_xt, W_dt, b_t, W_x_s, b_s);

    for (int t = 0; t < SB; t++)
        k_step<<<dim3(B / MT, G4 / NT), 512, 2 * STAGE>>>(t);

    k_out<<<dim3(SB, B / 32), 256>>>(Wc, bcv, Wm, bm, out);
}

// round 6
// speedup vs baseline: 3.2286x; 1.0329x over previous
#include <cuda_runtime.h>
#include <cuda_bf16.h>
#include <math.h>
#include <stdint.h>

#define S    256
#define SB   255
#define B    4096
#define H    256
#define E    32
#define MM   20
#define G4   1024
#define KTOT 544
#define KSTAT 288

// ---------------- scratch (static device globals; allocation-free) ----------------
// total ~3.38 GB (must stay < ~4GB: aarch64 adrp reloc range)
__device__ __align__(256) float g_T [(size_t)SB*H*B];               // [t][j][b]
__device__ __align__(256) float g_c [(size_t)H*B];                  // [j][b]
__device__ __align__(256) float g_blob[(size_t)2*B*G4];             // static pre, frag layout, ping-pong (33.5MB)
__device__ __align__(256) __nv_bfloat16 g_Aphi[(size_t)SB*KSTAT*B]; // [t][k][b]
__device__ __align__(256) __nv_bfloat16 g_Aplo[(size_t)SB*KSTAT*B];
__device__ __align__(256) __nv_bfloat16 g_Hhi [(size_t)SB*H*B];     // [t][j][b]
__device__ __align__(256) __nv_bfloat16 g_Hlo [(size_t)SB*H*B];
__device__ __align__(256) __nv_bfloat16 g_Wbhi[(size_t)KTOT*G4];    // [k][n'], n'=j*4+gate
__device__ __align__(256) __nv_bfloat16 g_Wblo[(size_t)KTOT*G4];

__device__ __forceinline__ float sigmoidf_(float x) { return 1.f / (1.f + expf(-x)); }

__device__ __forceinline__ uint32_t smem_u32(const void* p) {
    uint32_t a;
    asm("{ .reg .u64 t; cvta.to.shared.u64 t, %1; cvt.u32.u64 %0, t; }" : "=r"(a) : "l"(p));
    return a;
}
__device__ __forceinline__ void ldsm4t(uint32_t* r, uint32_t addr) {
    asm volatile("ldmatrix.sync.aligned.m8n8.x4.trans.shared.b16 {%0,%1,%2,%3}, [%4];"
        : "=r"(r[0]), "=r"(r[1]), "=r"(r[2]), "=r"(r[3]) : "r"(addr));
}
__device__ __forceinline__ void mma_bf16(float* d, const uint32_t* a, const uint32_t* b) {
    asm volatile("mma.sync.aligned.m16n8k16.row.col.f32.bf16.bf16.f32 "
        "{%0,%1,%2,%3}, {%4,%5,%6,%7}, {%8,%9}, {%0,%1,%2,%3};"
        : "+f"(d[0]), "+f"(d[1]), "+f"(d[2]), "+f"(d[3])
        : "r"(a[0]), "r"(a[1]), "r"(a[2]), "r"(a[3]), "r"(b[0]), "r"(b[1]));
}
__device__ __forceinline__ void cp16(uint32_t sa, const void* g) {
    asm volatile("cp.async.cg.shared.global [%0], [%1], 16;" :: "r"(sa), "l"(g));
}
#define CP_COMMIT() asm volatile("cp.async.commit_group;" ::: "memory")
#define CP_WAIT1()  asm volatile("cp.async.wait_group 1;" ::: "memory")
#define CP_WAIT0()  asm volatile("cp.async.wait_group 0;" ::: "memory")

// smem tile geometry: rows = k (32), cols = 128, row stride 272B (conflict-free ldmatrix)
#define ROWB  272
#define MATB  (32 * ROWB)      // 8704
#define OFF_AHI 0
#define OFF_ALO MATB
#define OFF_BHI (2 * MATB)
#define OFF_BLO (3 * MATB)
#define STAGE   (4 * MATB)     // 34816
#define NSTG    3
#define SMEM_TOTAL (NSTG * STAGE)  // 104448

// ============================================================
// k_packw: weights [k][n'] bf16 hi/lo; n'=j*4+g (src col g*256+j)
// rows: 0-19 W_x_p | 20-275 W_s_p | 276 bias | 277-287 zero | 288-543 W_h_p
// ============================================================
__global__ void k_packw(const float* __restrict__ W_x_p, const float* __restrict__ W_h_p,
                        const float* __restrict__ W_s_p, const float* __restrict__ b_p)
{
    int idx = blockIdx.x * blockDim.x + threadIdx.x;
    if (idx >= KTOT * G4) return;
    int k  = idx >> 10;
    int np = idx & 1023;
    int j = np >> 2, g = np & 3;
    int col = g * H + j;
    float v;
    if (k < MM)            v = W_x_p[(size_t)k * G4 + col];
    else if (k < MM + H)   v = W_s_p[(size_t)(k - MM) * G4 + col];
    else if (k == 276)     v = b_p[col];
    else if (k < KSTAT)    v = 0.f;
    else                   v = W_h_p[(size_t)(k - KSTAT) * G4 + col];
    __nv_bfloat16 hv = __float2bfloat16(v);
    g_Wbhi[idx] = hv;
    g_Wblo[idx] = __float2bfloat16(v - __bfloat162float(hv));
}

// ============================================================
// k_pre: T[t][j][b] fp32; static A rows as bf16 hi/lo in [t][k][b]
// ============================================================
__global__ void k_pre(const float* __restrict__ val_seq, const float* __restrict__ delta,
                      const float* __restrict__ W_d,  const float* __restrict__ b_d,
                      const float* __restrict__ W_xt, const float* __restrict__ W_dt,
                      const float* __restrict__ b_t,
                      const float* __restrict__ W_x_s, const float* __restrict__ b_s)
{
    __shared__ float sx[64][20];
    __shared__ float sde[64][32];
    __shared__ float sT[256][16];
    __shared__ float sH[256][16];
    int t = blockIdx.x;
    int b0 = blockIdx.y * 64;
    int tid = threadIdx.x;

    for (int e = tid; e < 64 * 20; e += 256) {
        int b = e / 20, k = e % 20;
        sx[b][k] = val_seq[((size_t)t * B + b0 + b) * MM + k];
    }
    for (int e = tid; e < 64 * 32; e += 256) {
        int b = e >> 5, ee = e & 31;
        float dd = delta[(size_t)t * B + b0 + b];
        sde[b][ee] = tanhf(dd * W_d[ee] + b_d[ee]);
    }
    __syncthreads();

    int j = tid;
    float wxt[20], wdt[32], wi[20], wo[20], wg[20];
    #pragma unroll
    for (int k = 0; k < 20; k++) wxt[k] = W_xt[k * H + j];
    #pragma unroll
    for (int e = 0; e < 32; e++) wdt[e] = W_dt[e * H + j];
    #pragma unroll
    for (int k = 0; k < 20; k++) {
        wi[k] = W_x_s[k * G4 + j];
        wo[k] = W_x_s[k * G4 + 2 * H + j];
        wg[k] = W_x_s[k * G4 + 3 * H + j];
    }
    float bt = b_t[j], bi = b_s[j], bo = b_s[2 * H + j], bg = b_s[3 * H + j];

    for (int bc = 0; bc < 4; bc++) {
        #pragma unroll 1
        for (int bl = 0; bl < 16; bl++) {
            int b = bc * 16 + bl;
            float tx = bt, td = 0.f, ai = bi, ao = bo, ag = bg;
            #pragma unroll
            for (int k = 0; k < 20; k++) {
                float xv = sx[b][k];
                tx += xv * wxt[k]; ai += xv * wi[k]; ao += xv * wo[k]; ag += xv * wg[k];
            }
            #pragma unroll
            for (int e = 0; e < 32; e++) td += sde[b][e] * wdt[e];
            float T = sigmoidf_(tx + sigmoidf_(td));
            float cns = sigmoidf_(ai) * T * tanhf(ag);
            sT[j][bl] = T;
            sH[j][bl] = sigmoidf_(ao) * tanhf(cns);
        }
        __syncthreads();
        size_t bb = (size_t)b0 + bc * 16;
        for (int e = tid; e < 256 * 16; e += 256) {
            int jj = e >> 4, bl = e & 15;
            g_T[((size_t)t * H + jj) * B + bb + bl] = sT[jj][bl];
            float v = sH[jj][bl];
            __nv_bfloat16 hv = __float2bfloat16(v);
            size_t ix = ((size_t)t * KSTAT + MM + jj) * B + bb + bl;
            g_Aphi[ix] = hv;
            g_Aplo[ix] = __float2bfloat16(v - __bfloat162float(hv));
        }
        for (int e = tid; e < 32 * 16; e += 256) {
            int k = e >> 4, bl = e & 15;
            int row = (k < MM) ? k : (256 + k);   // 276..287 for k=20..31
            float v = (k < MM) ? sx[bc * 16 + bl][k] : (k == MM ? 1.f : 0.f);
            __nv_bfloat16 hv = __float2bfloat16(v);
            size_t ix = ((size_t)t * KSTAT + row) * B + bb + bl;
            g_Aphi[ix] = hv;
            g_Aplo[ix] = __float2bfloat16(v - __bfloat162float(hv));
        }
        __syncthreads();
    }
}

// ============================================================
// k_step(t): 512 CTAs. cta<256: dynamic GEMM (K=256, h_prev) for step t,
// acc init from blob slot t&1, fused cell epilogue. cta>=256: static GEMM
// (K=288) for step t+1, writes blob slot (t+1)&1. t=-1: static-only (slot 0).
// ============================================================
__global__ void __launch_bounds__(256, 2) k_step(int t)
{
    extern __shared__ __align__(16) char sm[];
    int cta = blockIdx.x;
    bool dyn = (cta < 256);
    int tgt, clin, nch;
    const __nv_bfloat16 *Ahi, *Alo;
    int brow0;
    if (dyn) {
        if (t < 0) return;
        tgt = t; clin = cta;
        nch = (t == 0) ? 0 : 8;
        Ahi = g_Hhi + ((size_t)t - 1) * H * B;   // deref'd only when t>0
        Alo = g_Hlo + ((size_t)t - 1) * H * B;
        brow0 = KSTAT;
    } else {
        tgt = t + 1;
        if (tgt >= SB) return;
        clin = cta - 256;
        nch = 9;
        Ahi = g_Aphi + (size_t)tgt * KSTAT * B;
        Alo = g_Aplo + (size_t)tgt * KSTAT * B;
        brow0 = 0;
    }
    int bt = clin >> 3, ntb = clin & 7;
    int m0 = bt * 128, n0 = ntb * 128;
    int tid = threadIdx.x, lane = tid & 31, wid = tid >> 5;
    int wm = wid & 3, wn = wid >> 2;
    uint32_t smb = smem_u32(sm);

    float acc[2][8][4];
    float* afl = &acc[0][0][0];

    auto issue = [&](int c) {
        int k0 = c * 32;
        #pragma unroll
        for (int i = 0; i < 8; i++) {
            int g = tid + i * 256;
            int mat = g >> 9, r = (g >> 4) & 31, col = g & 15;
            const __nv_bfloat16* src;
            if (mat == 0)      src = Ahi + (size_t)(k0 + r) * B + m0 + col * 8;
            else if (mat == 1) src = Alo + (size_t)(k0 + r) * B + m0 + col * 8;
            else if (mat == 2) src = g_Wbhi + (size_t)(brow0 + k0 + r) * G4 + n0 + col * 8;
            else               src = g_Wblo + (size_t)(brow0 + k0 + r) * G4 + n0 + col * 8;
            uint32_t sa = smb + (uint32_t)((c % NSTG) * STAGE + mat * MATB + r * ROWB + col * 16);
            cp16(sa, src);
        }
        CP_COMMIT();
    };

    if (nch > 0) { issue(0); issue(1); }

    // accumulator init: dynamic reads blob slot tgt&1 (frag layout), static zeros
    size_t blob_ix = ((((size_t)(tgt & 1)) * 256 + clin) * 256 + tid) * 64;
    if (dyn) {
        const uint4* bp = (const uint4*)(g_blob + blob_ix);
        #pragma unroll
        for (int i = 0; i < 16; i++) ((uint4*)afl)[i] = bp[i];
    } else {
        #pragma unroll
        for (int i = 0; i < 64; i++) afl[i] = 0.f;
    }

    uint32_t aoff = (uint32_t)((((lane >> 4) * 8 + (lane & 7)) * ROWB) + (((lane >> 3) & 1) * 8 + wm * 32) * 2);
    uint32_t boff = (uint32_t)((((lane & 7) + ((lane >> 3) & 1) * 8) * ROWB) + ((lane >> 4) * 8 + wn * 64) * 2);

    for (int c = 0; c < nch; c++) {
        if (c == nch - 1) CP_WAIT0(); else CP_WAIT1();
        __syncthreads();
        if (c + 2 < nch) issue(c + 2);
        uint32_t sb = smb + (uint32_t)((c % NSTG) * STAGE);
        #pragma unroll
        for (int kf = 0; kf < 2; kf++) {
            uint32_t ah[2][4], al[2][4];
            #pragma unroll
            for (int mf = 0; mf < 2; mf++) {
                uint32_t ao = sb + aoff + (uint32_t)(kf * 16 * ROWB + mf * 32);
                ldsm4t(ah[mf], ao + OFF_AHI);
                ldsm4t(al[mf], ao + OFF_ALO);
            }
            #pragma unroll
            for (int nfp = 0; nfp < 4; nfp++) {
                uint32_t bo = sb + boff + (uint32_t)(kf * 16 * ROWB + nfp * 32);
                uint32_t bh[4], bl[4];
                ldsm4t(bh, bo + OFF_BHI);
                ldsm4t(bl, bo + OFF_BLO);
                #pragma unroll
                for (int mf = 0; mf < 2; mf++) {
                    mma_bf16(acc[mf][2 * nfp],     ah[mf], bh);
                    mma_bf16(acc[mf][2 * nfp],     ah[mf], bl);
                    mma_bf16(acc[mf][2 * nfp],     al[mf], bh);
                    mma_bf16(acc[mf][2 * nfp + 1], ah[mf], bh + 2);
                    mma_bf16(acc[mf][2 * nfp + 1], ah[mf], bl + 2);
                    mma_bf16(acc[mf][2 * nfp + 1], al[mf], bh + 2);
                }
            }
        }
    }

    if (!dyn) {
        uint4* bp = (uint4*)(g_blob + blob_ix);
        #pragma unroll
        for (int i = 0; i < 16; i++) bp[i] = ((const uint4*)afl)[i];
        return;
    }

    // ---- fused cell epilogue (dynamic) ----
    int odd = lane & 1;
    int cpair = (lane >> 1) & 1;
    int r_lane = lane >> 2;
    size_t tbase = (size_t)t * H * B;
    #pragma unroll
    for (int mf = 0; mf < 2; mf++) {
        int bglob = m0 + wm * 32 + mf * 16 + r_lane + (odd ? 8 : 0);
        #pragma unroll
        for (int nt = 0; nt < 8; nt++) {
            float d0 = acc[mf][nt][0], d1 = acc[mf][nt][1];
            float d2 = acc[mf][nt][2], d3 = acc[mf][nt][3];
            float s1 = odd ? d0 : d2;
            float s2 = odd ? d1 : d3;
            float r1 = __shfl_xor_sync(0xffffffffu, s1, 1);
            float r2 = __shfl_xor_sync(0xffffffffu, s2, 1);
            float fi = odd ? r1 : d0;
            float ff = odd ? r2 : d1;
            float fo = odd ? d2 : r1;
            float fg = odd ? d3 : r2;
            int j = ntb * 32 + wn * 16 + nt * 2 + cpair;
            size_t ix = (size_t)j * B + bglob;
            float T = g_T[tbase + ix];
            float cp = (t > 0) ? g_c[ix] : 0.f;
            float cn = sigmoidf_(ff) * cp + sigmoidf_(fi) * T * tanhf(fg);
            g_c[ix] = cn;
            float h = sigmoidf_(fo) * tanhf(cn);
            __nv_bfloat16 hh = __float2bfloat16(h);
            g_Hhi[tbase + ix] = hh;
            g_Hlo[tbase + ix] = __float2bfloat16(h - __bfloat162float(hh));
        }
    }
}

// ============================================================
// k_out: output heads from h1 = hi + lo
// ============================================================
__global__ void k_out(const float* __restrict__ Wc, const float* __restrict__ bc,
                      const float* __restrict__ Wm, const float* __restrict__ bm,
                      float* __restrict__ out)
{
    __shared__ float sh[256][32];
    __shared__ float sl[32][25];
    int t = blockIdx.x;
    int b0 = blockIdx.y * 32;
    int tid = threadIdx.x;

    for (int e = tid; e < 256 * 32; e += 256) {
        int jj = e >> 5, b = e & 31;
        size_t ix = ((size_t)t * H + jj) * B + b0 + b;
        sh[jj][b] = __bfloat162float(g_Hhi[ix]) + __bfloat162float(g_Hlo[ix]);
    }
    __syncthreads();

    for (int o = tid; o < 32 * 25; o += 256) {
        int r = o / 25, jx = o % 25;
        float s;
        if (jx < 3) {
            s = bc[jx];
            #pragma unroll 8
            for (int k = 0; k < H; k++) s += sh[k][r] * Wc[k * 3 + jx];
        } else {
            int jj = jx - 3;
            s = bm[jj];
            #pragma unroll 8
            for (int k = 0; k < H; k++) s += sh[k][r] * Wm[k * 22 + jj];
        }
        sl[r][jx] = s;
    }
    __syncthreads();

    float* out_cat = out;
    float* out_val = out + (size_t)SB * B * 3;
    for (int o = tid; o < 32 * 25; o += 256) {
        int r = o / 25, jx = o % 25;
        int b = b0 + r;
        if (jx < 3) {
            float l0 = sl[r][0], l1 = sl[r][1], l2 = sl[r][2];
            float mx = fmaxf(l0, fmaxf(l1, l2));
            float e0 = expf(l0 - mx), e1 = expf(l1 - mx), e2 = expf(l2 - mx);
            float inv = 1.f / (e0 + e1 + e2);
            float v = (jx == 0 ? e0 : (jx == 1 ? e1 : e2)) * inv;
            out_cat[(size_t)t * B * 3 + (size_t)b * 3 + jx] = v;
        } else {
            out_val[(size_t)t * B * 22 + (size_t)b * 22 + (jx - 3)] = sl[r][jx];
        }
    }
}

// ============================================================
// launch
// ============================================================
extern "C" void kernel_launch(void* const* d_in, const int* in_sizes, int n_in,
                              void* d_out, int out_size)
{
    const float* val_seq = (const float*)d_in[1];
    const float* delta   = (const float*)d_in[2];
    const float* W_d     = (const float*)d_in[3];
    const float* b_d     = (const float*)d_in[4];
    const float* W_xt    = (const float*)d_in[5];
    const float* W_dt    = (const float*)d_in[6];
    const float* b_t     = (const float*)d_in[7];
    const float* W_x_s   = (const float*)d_in[8];
    const float* b_s     = (const float*)d_in[10];
    const float* W_x_p   = (const float*)d_in[11];
    const float* W_h_p   = (const float*)d_in[12];
    const float* W_s_p   = (const float*)d_in[13];
    const float* b_p     = (const float*)d_in[14];
    const float* Wc      = (const float*)d_in[15];
    const float* bcv     = (const float*)d_in[16];
    const float* Wm      = (const float*)d_in[17];
    const float* bm      = (const float*)d_in[18];
    float* out = (float*)d_out;

    cudaFuncSetAttribute(k_step, cudaFuncAttributeMaxDynamicSharedMemorySize, SMEM_TOTAL);

    k_packw<<<(KTOT * G4 + 255) / 256, 256>>>(W_x_p, W_h_p, W_s_p, b_p);
    k_pre<<<dim3(SB, B / 64), 256>>>(val_seq, delta, W_d, b_d, W_xt, W_dt, b_t, W_x_s, b_s);

    k_step<<<512, 256, SMEM_TOTAL>>>(-1);           // static-only: blob slot 0
    for (int t = 0; t < SB; t++)
        k_step<<<512, 256, SMEM_TOTAL>>>(t);        // dynamic t + static t+1

    k_out<<<dim3(SB, B / 32), 256>>>(Wc, bcv, Wm, bm, out);
}

// round 7
// speedup vs baseline: 3.4334x; 1.0634x over previous
#include <cuda_runtime.h>
#include <cuda_bf16.h>
#include <math.h>
#include <stdint.h>

#define S    256
#define SB   255
#define B    4096
#define H    256
#define E    32
#define MM   20
#define G4   1024
#define KTOT 544
#define KSTAT 288
#define NCTA 256

// ---------------- scratch (static device globals; < 4GB total: aarch64 adrp range) ----------------
__device__ __align__(256) float g_T [(size_t)SB*H*B];               // [t][j][b]
__device__ __align__(256) float g_c [(size_t)H*B];                  // [j][b]
__device__ __align__(256) __nv_bfloat16 g_Aphi[(size_t)SB*KSTAT*B]; // [t][k][b]
__device__ __align__(256) __nv_bfloat16 g_Aplo[(size_t)SB*KSTAT*B];
__device__ __align__(256) __nv_bfloat16 g_Hhi [(size_t)SB*H*B];     // [t][j][b]
__device__ __align__(256) __nv_bfloat16 g_Hlo [(size_t)SB*H*B];
__device__ __align__(256) __nv_bfloat16 g_Wbhi[(size_t)KTOT*G4];    // [k][n'], n'=j*4+gate
__device__ __align__(256) __nv_bfloat16 g_Wblo[(size_t)KTOT*G4];
__device__ int g_bar_cnt;
__device__ volatile int g_bar_gen;

__device__ __forceinline__ float sigmoidf_(float x) { return 1.f / (1.f + expf(-x)); }

__device__ __forceinline__ uint32_t smem_u32(const void* p) {
    uint32_t a;
    asm("{ .reg .u64 t; cvta.to.shared.u64 t, %1; cvt.u32.u64 %0, t; }" : "=r"(a) : "l"(p));
    return a;
}
__device__ __forceinline__ void ldsm4t(uint32_t* r, uint32_t addr) {
    asm volatile("ldmatrix.sync.aligned.m8n8.x4.trans.shared.b16 {%0,%1,%2,%3}, [%4];"
        : "=r"(r[0]), "=r"(r[1]), "=r"(r[2]), "=r"(r[3]) : "r"(addr));
}
__device__ __forceinline__ void mma_bf16(float* d, const uint32_t* a, const uint32_t* b) {
    asm volatile("mma.sync.aligned.m16n8k16.row.col.f32.bf16.bf16.f32 "
        "{%0,%1,%2,%3}, {%4,%5,%6,%7}, {%8,%9}, {%0,%1,%2,%3};"
        : "+f"(d[0]), "+f"(d[1]), "+f"(d[2]), "+f"(d[3])
        : "r"(a[0]), "r"(a[1]), "r"(a[2]), "r"(a[3]), "r"(b[0]), "r"(b[1]));
}
__device__ __forceinline__ void cp16(uint32_t sa, const void* g) {
    asm volatile("cp.async.cg.shared.global [%0], [%1], 16;" :: "r"(sa), "l"(g));
}
#define CP_COMMIT() asm volatile("cp.async.commit_group;" ::: "memory")
#define CP_WAIT1()  asm volatile("cp.async.wait_group 1;" ::: "memory")
#define CP_WAIT0()  asm volatile("cp.async.wait_group 0;" ::: "memory")

// smem tile geometry: rows = k (32), cols = 128, row stride 272B (conflict-free ldmatrix)
#define ROWB  272
#define MATB  (32 * ROWB)      // 8704
#define OFF_AHI 0
#define OFF_ALO MATB
#define OFF_BHI (2 * MATB)
#define OFF_BLO (3 * MATB)
#define STAGE   (4 * MATB)     // 34816
#define NSTG    3
#define SMEM_TOTAL (NSTG * STAGE)  // 104448

// ============================================================
// k_packw: weights [k][n'] bf16 hi/lo; also resets the global barrier
// ============================================================
__global__ void k_packw(const float* __restrict__ W_x_p, const float* __restrict__ W_h_p,
                        const float* __restrict__ W_s_p, const float* __restrict__ b_p)
{
    if (blockIdx.x == 0 && threadIdx.x == 0) { g_bar_cnt = 0; g_bar_gen = 0; }
    int idx = blockIdx.x * blockDim.x + threadIdx.x;
    if (idx >= KTOT * G4) return;
    int k  = idx >> 10;
    int np = idx & 1023;
    int j = np >> 2, g = np & 3;
    int col = g * H + j;
    float v;
    if (k < MM)            v = W_x_p[(size_t)k * G4 + col];
    else if (k < MM + H)   v = W_s_p[(size_t)(k - MM) * G4 + col];
    else if (k == 276)     v = b_p[col];
    else if (k < KSTAT)    v = 0.f;
    else                   v = W_h_p[(size_t)(k - KSTAT) * G4 + col];
    __nv_bfloat16 hv = __float2bfloat16(v);
    g_Wbhi[idx] = hv;
    g_Wblo[idx] = __float2bfloat16(v - __bfloat162float(hv));
}

// ============================================================
// k_pre: T[t][j][b] fp32; static A rows as bf16 hi/lo in [t][k][b]
// ============================================================
__global__ void k_pre(const float* __restrict__ val_seq, const float* __restrict__ delta,
                      const float* __restrict__ W_d,  const float* __restrict__ b_d,
                      const float* __restrict__ W_xt, const float* __restrict__ W_dt,
                      const float* __restrict__ b_t,
                      const float* __restrict__ W_x_s, const float* __restrict__ b_s)
{
    __shared__ float sx[64][20];
    __shared__ float sde[64][32];
    __shared__ float sT[256][16];
    __shared__ float sH[256][16];
    int t = blockIdx.x;
    int b0 = blockIdx.y * 64;
    int tid = threadIdx.x;

    for (int e = tid; e < 64 * 20; e += 256) {
        int b = e / 20, k = e % 20;
        sx[b][k] = val_seq[((size_t)t * B + b0 + b) * MM + k];
    }
    for (int e = tid; e < 64 * 32; e += 256) {
        int b = e >> 5, ee = e & 31;
        float dd = delta[(size_t)t * B + b0 + b];
        sde[b][ee] = tanhf(dd * W_d[ee] + b_d[ee]);
    }
    __syncthreads();

    int j = tid;
    float wxt[20], wdt[32], wi[20], wo[20], wg[20];
    #pragma unroll
    for (int k = 0; k < 20; k++) wxt[k] = W_xt[k * H + j];
    #pragma unroll
    for (int e = 0; e < 32; e++) wdt[e] = W_dt[e * H + j];
    #pragma unroll
    for (int k = 0; k < 20; k++) {
        wi[k] = W_x_s[k * G4 + j];
        wo[k] = W_x_s[k * G4 + 2 * H + j];
        wg[k] = W_x_s[k * G4 + 3 * H + j];
    }
    float bt = b_t[j], bi = b_s[j], bo = b_s[2 * H + j], bg = b_s[3 * H + j];

    for (int bc = 0; bc < 4; bc++) {
        #pragma unroll 1
        for (int bl = 0; bl < 16; bl++) {
            int b = bc * 16 + bl;
            float tx = bt, td = 0.f, ai = bi, ao = bo, ag = bg;
            #pragma unroll
            for (int k = 0; k < 20; k++) {
                float xv = sx[b][k];
                tx += xv * wxt[k]; ai += xv * wi[k]; ao += xv * wo[k]; ag += xv * wg[k];
            }
            #pragma unroll
            for (int e = 0; e < 32; e++) td += sde[b][e] * wdt[e];
            float T = sigmoidf_(tx + sigmoidf_(td));
            float cns = sigmoidf_(ai) * T * tanhf(ag);
            sT[j][bl] = T;
            sH[j][bl] = sigmoidf_(ao) * tanhf(cns);
        }
        __syncthreads();
        size_t bb = (size_t)b0 + bc * 16;
        for (int e = tid; e < 256 * 16; e += 256) {
            int jj = e >> 4, bl = e & 15;
            g_T[((size_t)t * H + jj) * B + bb + bl] = sT[jj][bl];
            float v = sH[jj][bl];
            __nv_bfloat16 hv = __float2bfloat16(v);
            size_t ix = ((size_t)t * KSTAT + MM + jj) * B + bb + bl;
            g_Aphi[ix] = hv;
            g_Aplo[ix] = __float2bfloat16(v - __bfloat162float(hv));
        }
        for (int e = tid; e < 32 * 16; e += 256) {
            int k = e >> 4, bl = e & 15;
            int row = (k < MM) ? k : (256 + k);   // 276..287 for k=20..31
            float v = (k < MM) ? sx[bc * 16 + bl][k] : (k == MM ? 1.f : 0.f);
            __nv_bfloat16 hv = __float2bfloat16(v);
            size_t ix = ((size_t)t * KSTAT + row) * B + bb + bl;
            g_Aphi[ix] = hv;
            g_Aplo[ix] = __float2bfloat16(v - __bfloat162float(hv));
        }
        __syncthreads();
    }
}

// ============================================================
// k_seq: ONE persistent kernel for the whole recurrence.
// 256 CTAs (2/SM resident, <=296 capacity). Each CTA owns tile (bt,ntb).
// Per step: dyn GEMM (K=256, accumulates onto register-carried static pre)
//   -> fused cell epilogue -> global barrier arrive
//   -> static GEMM for t+1 into acc -> barrier spin.
// ============================================================
__global__ void __launch_bounds__(256, 2) k_seq()
{
    extern __shared__ __align__(16) char sm[];
    int clin = blockIdx.x;
    int bt = clin >> 3, ntb = clin & 7;
    int m0 = bt * 128, n0 = ntb * 128;
    int tid = threadIdx.x, lane = tid & 31, wid = tid >> 5;
    int wm = wid & 3, wn = wid >> 2;
    uint32_t smb = smem_u32(sm);

    float acc[2][8][4];
    float* afl = &acc[0][0][0];

    uint32_t aoff = (uint32_t)((((lane >> 4) * 8 + (lane & 7)) * ROWB) + (((lane >> 3) & 1) * 8 + wm * 32) * 2);
    uint32_t boff = (uint32_t)((((lane & 7) + ((lane >> 3) & 1) * 8) * ROWB) + ((lane >> 4) * 8 + wn * 64) * 2);

    auto run_gemm = [&](const __nv_bfloat16* __restrict__ Ahi,
                        const __nv_bfloat16* __restrict__ Alo,
                        int brow0, int nch) {
        auto issue = [&](int c) {
            int k0 = c * 32;
            #pragma unroll
            for (int i = 0; i < 8; i++) {
                int g = tid + i * 256;
                int mat = g >> 9, r = (g >> 4) & 31, col = g & 15;
                const __nv_bfloat16* src;
                if (mat == 0)      src = Ahi + (size_t)(k0 + r) * B + m0 + col * 8;
                else if (mat == 1) src = Alo + (size_t)(k0 + r) * B + m0 + col * 8;
                else if (mat == 2) src = g_Wbhi + (size_t)(brow0 + k0 + r) * G4 + n0 + col * 8;
                else               src = g_Wblo + (size_t)(brow0 + k0 + r) * G4 + n0 + col * 8;
                cp16(smb + (uint32_t)((c % NSTG) * STAGE + mat * MATB + r * ROWB + col * 16), src);
            }
            CP_COMMIT();
        };
        issue(0); issue(1);
        for (int c = 0; c < nch; c++) {
            if (c == nch - 1) CP_WAIT0(); else CP_WAIT1();
            __syncthreads();
            if (c + 2 < nch) issue(c + 2);
            uint32_t sb = smb + (uint32_t)((c % NSTG) * STAGE);
            #pragma unroll
            for (int kf = 0; kf < 2; kf++) {
                uint32_t ko = (uint32_t)(kf * 16 * ROWB);
                uint32_t ah[2][4], bh[4][4];
                #pragma unroll
                for (int mf = 0; mf < 2; mf++)
                    ldsm4t(ah[mf], sb + aoff + ko + (uint32_t)(mf * 32) + OFF_AHI);
                #pragma unroll
                for (int nf = 0; nf < 4; nf++)
                    ldsm4t(bh[nf], sb + boff + ko + (uint32_t)(nf * 32) + OFF_BHI);
                // pass 1: Ahi x Bhi (16 independent MMAs)
                #pragma unroll
                for (int mf = 0; mf < 2; mf++)
                    #pragma unroll
                    for (int nf = 0; nf < 4; nf++) {
                        mma_bf16(acc[mf][2 * nf],     ah[mf], bh[nf]);
                        mma_bf16(acc[mf][2 * nf + 1], ah[mf], bh[nf] + 2);
                    }
                // pass 2: Ahi x Blo
                uint32_t bl[4][4];
                #pragma unroll
                for (int nf = 0; nf < 4; nf++)
                    ldsm4t(bl[nf], sb + boff + ko + (uint32_t)(nf * 32) + OFF_BLO);
                #pragma unroll
                for (int mf = 0; mf < 2; mf++)
                    #pragma unroll
                    for (int nf = 0; nf < 4; nf++) {
                        mma_bf16(acc[mf][2 * nf],     ah[mf], bl[nf]);
                        mma_bf16(acc[mf][2 * nf + 1], ah[mf], bl[nf] + 2);
                    }
                // pass 3: Alo x Bhi
                uint32_t al[2][4];
                #pragma unroll
                for (int mf = 0; mf < 2; mf++)
                    ldsm4t(al[mf], sb + aoff + ko + (uint32_t)(mf * 32) + OFF_ALO);
                #pragma unroll
                for (int mf = 0; mf < 2; mf++)
                    #pragma unroll
                    for (int nf = 0; nf < 4; nf++) {
                        mma_bf16(acc[mf][2 * nf],     al[mf], bh[nf]);
                        mma_bf16(acc[mf][2 * nf + 1], al[mf], bh[nf] + 2);
                    }
            }
        }
    };

    // prologue: static preactivation for t=0 (own tile; no barrier needed)
    #pragma unroll
    for (int i = 0; i < 64; i++) afl[i] = 0.f;
    run_gemm(g_Aphi, g_Aplo, 0, 9);

    int odd = lane & 1;
    int cpair = (lane >> 1) & 1;
    int r_lane = lane >> 2;

    for (int t = 0; t < SB; t++) {
        // dynamic GEMM: accumulate h_prev contribution onto register-carried static pre
        if (t > 0)
            run_gemm(g_Hhi + ((size_t)t - 1) * H * B, g_Hlo + ((size_t)t - 1) * H * B, KSTAT, 8);

        // fused cell epilogue
        size_t tbase = (size_t)t * H * B;
        #pragma unroll
        for (int mf = 0; mf < 2; mf++) {
            int bglob = m0 + wm * 32 + mf * 16 + r_lane + (odd ? 8 : 0);
            #pragma unroll
            for (int nt = 0; nt < 8; nt++) {
                float d0 = acc[mf][nt][0], d1 = acc[mf][nt][1];
                float d2 = acc[mf][nt][2], d3 = acc[mf][nt][3];
                float s1 = odd ? d0 : d2;
                float s2 = odd ? d1 : d3;
                float r1 = __shfl_xor_sync(0xffffffffu, s1, 1);
                float r2 = __shfl_xor_sync(0xffffffffu, s2, 1);
                float fi = odd ? r1 : d0;
                float ff = odd ? r2 : d1;
                float fo = odd ? d2 : r1;
                float fg = odd ? d3 : r2;
                int j = ntb * 32 + wn * 16 + nt * 2 + cpair;
                size_t ix = (size_t)j * B + bglob;
                float T = g_T[tbase + ix];
                float cp = (t > 0) ? g_c[ix] : 0.f;
                float cn = sigmoidf_(ff) * cp + sigmoidf_(fi) * T * tanhf(fg);
                g_c[ix] = cn;
                float h = sigmoidf_(fo) * tanhf(cn);
                __nv_bfloat16 hh = __float2bfloat16(h);
                g_Hhi[tbase + ix] = hh;
                g_Hlo[tbase + ix] = __float2bfloat16(h - __bfloat162float(hh));
            }
        }

        if (t + 1 >= SB) break;

        // publish h[t] and arrive at barrier t
        __threadfence();
        __syncthreads();
        if (tid == 0) {
            int v = atomicAdd(&g_bar_cnt, 1);
            if (v == NCTA - 1) {
                atomicExch(&g_bar_cnt, 0);
                __threadfence();
                g_bar_gen = t + 1;
            }
        }

        // overlap: static preactivation for t+1 (own tile, independent of barrier)
        #pragma unroll
        for (int i = 0; i < 64; i++) afl[i] = 0.f;
        run_gemm(g_Aphi + (size_t)(t + 1) * KSTAT * B, g_Aplo + (size_t)(t + 1) * KSTAT * B, 0, 9);

        // wait for all CTAs to have published h[t]
        if (tid == 0) {
            while (g_bar_gen <= t) __nanosleep(32);
        }
        __syncthreads();
    }
}

// ============================================================
// k_out: output heads from h1 = hi + lo
// ============================================================
__global__ void k_out(const float* __restrict__ Wc, const float* __restrict__ bc,
                      const float* __restrict__ Wm, const float* __restrict__ bm,
                      float* __restrict__ out)
{
    __shared__ float sh[256][32];
    __shared__ float sl[32][25];
    int t = blockIdx.x;
    int b0 = blockIdx.y * 32;
    int tid = threadIdx.x;

    for (int e = tid; e < 256 * 32; e += 256) {
        int jj = e >> 5, b = e & 31;
        size_t ix = ((size_t)t * H + jj) * B + b0 + b;
        sh[jj][b] = __bfloat162float(g_Hhi[ix]) + __bfloat162float(g_Hlo[ix]);
    }
    __syncthreads();

    for (int o = tid; o < 32 * 25; o += 256) {
        int r = o / 25, jx = o % 25;
        float s;
        if (jx < 3) {
            s = bc[jx];
            #pragma unroll 8
            for (int k = 0; k < H; k++) s += sh[k][r] * Wc[k * 3 + jx];
        } else {
            int jj = jx - 3;
            s = bm[jj];
            #pragma unroll 8
            for (int k = 0; k < H; k++) s += sh[k][r] * Wm[k * 22 + jj];
        }
        sl[r][jx] = s;
    }
    __syncthreads();

    float* out_cat = out;
    float* out_val = out + (size_t)SB * B * 3;
    for (int o = tid; o < 32 * 25; o += 256) {
        int r = o / 25, jx = o % 25;
        int b = b0 + r;
        if (jx < 3) {
            float l0 = sl[r][0], l1 = sl[r][1], l2 = sl[r][2];
            float mx = fmaxf(l0, fmaxf(l1, l2));
            float e0 = expf(l0 - mx), e1 = expf(l1 - mx), e2 = expf(l2 - mx);
            float inv = 1.f / (e0 + e1 + e2);
            float v = (jx == 0 ? e0 : (jx == 1 ? e1 : e2)) * inv;
            out_cat[(size_t)t * B * 3 + (size_t)b * 3 + jx] = v;
        } else {
            out_val[(size_t)t * B * 22 + (size_t)b * 22 + (jx - 3)] = sl[r][jx];
        }
    }
}

// ============================================================
// launch
// ============================================================
extern "C" void kernel_launch(void* const* d_in, const int* in_sizes, int n_in,
                              void* d_out, int out_size)
{
    const float* val_seq = (const float*)d_in[1];
    const float* delta   = (const float*)d_in[2];
    const float* W_d     = (const float*)d_in[3];
    const float* b_d     = (const float*)d_in[4];
    const float* W_xt    = (const float*)d_in[5];
    const float* W_dt    = (const float*)d_in[6];
    const float* b_t     = (const float*)d_in[7];
    const float* W_x_s   = (const float*)d_in[8];
    const float* b_s     = (const float*)d_in[10];
    const float* W_x_p   = (const float*)d_in[11];
    const float* W_h_p   = (const float*)d_in[12];
    const float* W_s_p   = (const float*)d_in[13];
    const float* b_p     = (const float*)d_in[14];
    const float* Wc      = (const float*)d_in[15];
    const float* bcv     = (const float*)d_in[16];
    const float* Wm      = (const float*)d_in[17];
    const float* bm      = (const float*)d_in[18];
    float* out = (float*)d_out;

    cudaFuncSetAttribute(k_seq, cudaFuncAttributeMaxDynamicSharedMemorySize, SMEM_TOTAL);

    k_packw<<<(KTOT * G4 + 255) / 256, 256>>>(W_x_p, W_h_p, W_s_p, b_p);
    k_pre<<<dim3(SB, B / 64), 256>>>(val_seq, delta, W_d, b_d, W_xt, W_dt, b_t, W_x_s, b_s);

    k_seq<<<NCTA, 256, SMEM_TOTAL>>>();

    k_out<<<dim3(SB, B / 32), 256>>>(Wc, bcv, Wm, bm, out);
}

// round 8
// speedup vs baseline: 3.5315x; 1.0286x over previous
#include <cuda_runtime.h>
#include <cuda_bf16.h>
#include <math.h>
#include <stdint.h>

#define S    256
#define SB   255
#define B    4096
#define H    256
#define E    32
#define MM   20
#define G4   1024
#define KTOT 544
#define KSTAT 288
#define NCTA 256
#define NGRP 32
#define GRP  8

// ---------------- scratch (static device globals; < 4GB total: aarch64 adrp range) ----------------
__device__ __align__(256) float g_T [(size_t)SB*H*B];               // [t][j][b]
__device__ __align__(256) float g_c [(size_t)H*B];                  // [j][b]
__device__ __align__(256) __nv_bfloat16 g_Aphi[(size_t)SB*KSTAT*B]; // [t][k][b]
__device__ __align__(256) __nv_bfloat16 g_Aplo[(size_t)SB*KSTAT*B];
__device__ __align__(256) __nv_bfloat16 g_Hhi [(size_t)SB*H*B];     // [t][j][b]
__device__ __align__(256) __nv_bfloat16 g_Hlo [(size_t)SB*H*B];
__device__ __align__(256) __nv_bfloat16 g_Wbhi[(size_t)KTOT*G4];    // [k][n'], n'=j*4+gate
__device__ __align__(256) __nv_bfloat16 g_Wblo[(size_t)KTOT*G4];
// per-bt-group barriers, 128B stride to avoid line sharing
__device__ __align__(256) int g_cnt[NGRP * 32];
__device__ __align__(256) volatile int g_gen[NGRP * 32];

__device__ __forceinline__ float sigmoidf_(float x) { return 1.f / (1.f + expf(-x)); }

__device__ __forceinline__ uint32_t smem_u32(const void* p) {
    uint32_t a;
    asm("{ .reg .u64 t; cvta.to.shared.u64 t, %1; cvt.u32.u64 %0, t; }" : "=r"(a) : "l"(p));
    return a;
}
__device__ __forceinline__ void ldsm4t(uint32_t* r, uint32_t addr) {
    asm volatile("ldmatrix.sync.aligned.m8n8.x4.trans.shared.b16 {%0,%1,%2,%3}, [%4];"
        : "=r"(r[0]), "=r"(r[1]), "=r"(r[2]), "=r"(r[3]) : "r"(addr));
}
__device__ __forceinline__ void mma_bf16(float* d, const uint32_t* a, const uint32_t* b) {
    asm volatile("mma.sync.aligned.m16n8k16.row.col.f32.bf16.bf16.f32 "
        "{%0,%1,%2,%3}, {%4,%5,%6,%7}, {%8,%9}, {%0,%1,%2,%3};"
        : "+f"(d[0]), "+f"(d[1]), "+f"(d[2]), "+f"(d[3])
        : "r"(a[0]), "r"(a[1]), "r"(a[2]), "r"(a[3]), "r"(b[0]), "r"(b[1]));
}
__device__ __forceinline__ void cp16(uint32_t sa, const void* g) {
    asm volatile("cp.async.cg.shared.global [%0], [%1], 16;" :: "r"(sa), "l"(g));
}
#define CP_COMMIT() asm volatile("cp.async.commit_group;" ::: "memory")
#define CP_WAIT1()  asm volatile("cp.async.wait_group 1;" ::: "memory")
#define CP_WAIT0()  asm volatile("cp.async.wait_group 0;" ::: "memory")

// smem tile geometry: rows = k (32), cols = 128, row stride 272B (conflict-free ldmatrix)
#define ROWB  272
#define MATB  (32 * ROWB)      // 8704
#define OFF_AHI 0
#define OFF_ALO MATB
#define OFF_BHI (2 * MATB)
#define OFF_BLO (3 * MATB)
#define STAGE   (4 * MATB)     // 34816
#define NSTG    3
#define SMEM_TOTAL (NSTG * STAGE)  // 104448

// ============================================================
// k_packw: weights [k][n'] bf16 hi/lo; also resets the group barriers
// ============================================================
__global__ void k_packw(const float* __restrict__ W_x_p, const float* __restrict__ W_h_p,
                        const float* __restrict__ W_s_p, const float* __restrict__ b_p)
{
    int idx = blockIdx.x * blockDim.x + threadIdx.x;
    if (idx < NGRP * 32) { g_cnt[idx] = 0; g_gen[idx] = 0; }
    if (idx >= KTOT * G4) return;
    int k  = idx >> 10;
    int np = idx & 1023;
    int j = np >> 2, g = np & 3;
    int col = g * H + j;
    float v;
    if (k < MM)            v = W_x_p[(size_t)k * G4 + col];
    else if (k < MM + H)   v = W_s_p[(size_t)(k - MM) * G4 + col];
    else if (k == 276)     v = b_p[col];
    else if (k < KSTAT)    v = 0.f;
    else                   v = W_h_p[(size_t)(k - KSTAT) * G4 + col];
    __nv_bfloat16 hv = __float2bfloat16(v);
    g_Wbhi[idx] = hv;
    g_Wblo[idx] = __float2bfloat16(v - __bfloat162float(hv));
}

// ============================================================
// k_pre: T[t][j][b] fp32; static A rows as bf16 hi/lo in [t][k][b]
// ============================================================
__global__ void k_pre(const float* __restrict__ val_seq, const float* __restrict__ delta,
                      const float* __restrict__ W_d,  const float* __restrict__ b_d,
                      const float* __restrict__ W_xt, const float* __restrict__ W_dt,
                      const float* __restrict__ b_t,
                      const float* __restrict__ W_x_s, const float* __restrict__ b_s)
{
    __shared__ float sx[64][20];
    __shared__ float sde[64][32];
    __shared__ float sT[256][16];
    __shared__ float sH[256][16];
    int t = blockIdx.x;
    int b0 = blockIdx.y * 64;
    int tid = threadIdx.x;

    for (int e = tid; e < 64 * 20; e += 256) {
        int b = e / 20, k = e % 20;
        sx[b][k] = val_seq[((size_t)t * B + b0 + b) * MM + k];
    }
    for (int e = tid; e < 64 * 32; e += 256) {
        int b = e >> 5, ee = e & 31;
        float dd = delta[(size_t)t * B + b0 + b];
        sde[b][ee] = tanhf(dd * W_d[ee] + b_d[ee]);
    }
    __syncthreads();

    int j = tid;
    float wxt[20], wdt[32], wi[20], wo[20], wg[20];
    #pragma unroll
    for (int k = 0; k < 20; k++) wxt[k] = W_xt[k * H + j];
    #pragma unroll
    for (int e = 0; e < 32; e++) wdt[e] = W_dt[e * H + j];
    #pragma unroll
    for (int k = 0; k < 20; k++) {
        wi[k] = W_x_s[k * G4 + j];
        wo[k] = W_x_s[k * G4 + 2 * H + j];
        wg[k] = W_x_s[k * G4 + 3 * H + j];
    }
    float bt = b_t[j], bi = b_s[j], bo = b_s[2 * H + j], bg = b_s[3 * H + j];

    for (int bc = 0; bc < 4; bc++) {
        #pragma unroll 1
        for (int bl = 0; bl < 16; bl++) {
            int b = bc * 16 + bl;
            float tx = bt, td = 0.f, ai = bi, ao = bo, ag = bg;
            #pragma unroll
            for (int k = 0; k < 20; k++) {
                float xv = sx[b][k];
                tx += xv * wxt[k]; ai += xv * wi[k]; ao += xv * wo[k]; ag += xv * wg[k];
            }
            #pragma unroll
            for (int e = 0; e < 32; e++) td += sde[b][e] * wdt[e];
            float T = sigmoidf_(tx + sigmoidf_(td));
            float cns = sigmoidf_(ai) * T * tanhf(ag);
            sT[j][bl] = T;
            sH[j][bl] = sigmoidf_(ao) * tanhf(cns);
        }
        __syncthreads();
        size_t bb = (size_t)b0 + bc * 16;
        for (int e = tid; e < 256 * 16; e += 256) {
            int jj = e >> 4, bl = e & 15;
            g_T[((size_t)t * H + jj) * B + bb + bl] = sT[jj][bl];
            float v = sH[jj][bl];
            __nv_bfloat16 hv = __float2bfloat16(v);
            size_t ix = ((size_t)t * KSTAT + MM + jj) * B + bb + bl;
            g_Aphi[ix] = hv;
            g_Aplo[ix] = __float2bfloat16(v - __bfloat162float(hv));
        }
        for (int e = tid; e < 32 * 16; e += 256) {
            int k = e >> 4, bl = e & 15;
            int row = (k < MM) ? k : (256 + k);   // 276..287 for k=20..31
            float v = (k < MM) ? sx[bc * 16 + bl][k] : (k == MM ? 1.f : 0.f);
            __nv_bfloat16 hv = __float2bfloat16(v);
            size_t ix = ((size_t)t * KSTAT + row) * B + bb + bl;
            g_Aphi[ix] = hv;
            g_Aplo[ix] = __float2bfloat16(v - __bfloat162float(hv));
        }
        __syncthreads();
    }
}

// ============================================================
// k_seq: ONE persistent kernel for the whole recurrence.
// 256 CTAs (2/SM). CTA (bt,ntb) owns tile rows b in [bt*128,+128),
// cols j in [ntb*32,+32). h[t][:,b-range] is produced/consumed entirely
// within the 8-CTA bt-group -> per-group barrier, groups fully decoupled.
// Per step: dyn GEMM (K=256, acc carries static pre) -> cell epilogue
//   -> group arrive -> static GEMM for t+1 -> group spin.
// ============================================================
__global__ void __launch_bounds__(256, 2) k_seq()
{
    extern __shared__ __align__(16) char sm[];
    int clin = blockIdx.x;
    int bt = clin >> 3, ntb = clin & 7;
    int m0 = bt * 128, n0 = ntb * 128;
    int gslot = bt * 32;
    int tid = threadIdx.x, lane = tid & 31, wid = tid >> 5;
    int wm = wid & 3, wn = wid >> 2;
    uint32_t smb = smem_u32(sm);

    float acc[2][8][4];
    float* afl = &acc[0][0][0];

    uint32_t aoff = (uint32_t)((((lane >> 4) * 8 + (lane & 7)) * ROWB) + (((lane >> 3) & 1) * 8 + wm * 32) * 2);
    uint32_t boff = (uint32_t)((((lane & 7) + ((lane >> 3) & 1) * 8) * ROWB) + ((lane >> 4) * 8 + wn * 64) * 2);

    auto run_gemm = [&](const __nv_bfloat16* __restrict__ Ahi,
                        const __nv_bfloat16* __restrict__ Alo,
                        int brow0, int nch) {
        auto issue = [&](int c) {
            int k0 = c * 32;
            #pragma unroll
            for (int i = 0; i < 8; i++) {
                int g = tid + i * 256;
                int mat = g >> 9, r = (g >> 4) & 31, col = g & 15;
                const __nv_bfloat16* src;
                if (mat == 0)      src = Ahi + (size_t)(k0 + r) * B + m0 + col * 8;
                else if (mat == 1) src = Alo + (size_t)(k0 + r) * B + m0 + col * 8;
                else if (mat == 2) src = g_Wbhi + (size_t)(brow0 + k0 + r) * G4 + n0 + col * 8;
                else               src = g_Wblo + (size_t)(brow0 + k0 + r) * G4 + n0 + col * 8;
                cp16(smb + (uint32_t)((c % NSTG) * STAGE + mat * MATB + r * ROWB + col * 16), src);
            }
            CP_COMMIT();
        };
        issue(0); issue(1);
        for (int c = 0; c < nch; c++) {
            if (c == nch - 1) CP_WAIT0(); else CP_WAIT1();
            __syncthreads();
            if (c + 2 < nch) issue(c + 2);
            uint32_t sb = smb + (uint32_t)((c % NSTG) * STAGE);
            #pragma unroll
            for (int kf = 0; kf < 2; kf++) {
                uint32_t ko = (uint32_t)(kf * 16 * ROWB);
                uint32_t ah[2][4], bh[4][4];
                #pragma unroll
                for (int mf = 0; mf < 2; mf++)
                    ldsm4t(ah[mf], sb + aoff + ko + (uint32_t)(mf * 32) + OFF_AHI);
                #pragma unroll
                for (int nf = 0; nf < 4; nf++)
                    ldsm4t(bh[nf], sb + boff + ko + (uint32_t)(nf * 32) + OFF_BHI);
                // pass 1: Ahi x Bhi (16 independent MMAs)
                #pragma unroll
                for (int mf = 0; mf < 2; mf++)
                    #pragma unroll
                    for (int nf = 0; nf < 4; nf++) {
                        mma_bf16(acc[mf][2 * nf],     ah[mf], bh[nf]);
                        mma_bf16(acc[mf][2 * nf + 1], ah[mf], bh[nf] + 2);
                    }
                // pass 2: Ahi x Blo
                uint32_t bl[4][4];
                #pragma unroll
                for (int nf = 0; nf < 4; nf++)
                    ldsm4t(bl[nf], sb + boff + ko + (uint32_t)(nf * 32) + OFF_BLO);
                #pragma unroll
                for (int mf = 0; mf < 2; mf++)
                    #pragma unroll
                    for (int nf = 0; nf < 4; nf++) {
                        mma_bf16(acc[mf][2 * nf],     ah[mf], bl[nf]);
                        mma_bf16(acc[mf][2 * nf + 1], ah[mf], bl[nf] + 2);
                    }
                // pass 3: Alo x Bhi
                uint32_t al[2][4];
                #pragma unroll
                for (int mf = 0; mf < 2; mf++)
                    ldsm4t(al[mf], sb + aoff + ko + (uint32_t)(mf * 32) + OFF_ALO);
                #pragma unroll
                for (int mf = 0; mf < 2; mf++)
                    #pragma unroll
                    for (int nf = 0; nf < 4; nf++) {
                        mma_bf16(acc[mf][2 * nf],     al[mf], bh[nf]);
                        mma_bf16(acc[mf][2 * nf + 1], al[mf], bh[nf] + 2);
                    }
            }
        }
    };

    // prologue: static preactivation for t=0 (own tile; no barrier needed)
    #pragma unroll
    for (int i = 0; i < 64; i++) afl[i] = 0.f;
    run_gemm(g_Aphi, g_Aplo, 0, 9);

    int odd = lane & 1;
    int cpair = (lane >> 1) & 1;
    int r_lane = lane >> 2;

    for (int t = 0; t < SB; t++) {
        // dynamic GEMM: accumulate h_prev contribution onto register-carried static pre
        if (t > 0)
            run_gemm(g_Hhi + ((size_t)t - 1) * H * B, g_Hlo + ((size_t)t - 1) * H * B, KSTAT, 8);

        // fused cell epilogue
        size_t tbase = (size_t)t * H * B;
        #pragma unroll
        for (int mf = 0; mf < 2; mf++) {
            int bglob = m0 + wm * 32 + mf * 16 + r_lane + (odd ? 8 : 0);
            #pragma unroll
            for (int nt = 0; nt < 8; nt++) {
                float d0 = acc[mf][nt][0], d1 = acc[mf][nt][1];
                float d2 = acc[mf][nt][2], d3 = acc[mf][nt][3];
                float s1 = odd ? d0 : d2;
                float s2 = odd ? d1 : d3;
                float r1 = __shfl_xor_sync(0xffffffffu, s1, 1);
                float r2 = __shfl_xor_sync(0xffffffffu, s2, 1);
                float fi = odd ? r1 : d0;
                float ff = odd ? r2 : d1;
                float fo = odd ? d2 : r1;
                float fg = odd ? d3 : r2;
                int j = ntb * 32 + wn * 16 + nt * 2 + cpair;
                size_t ix = (size_t)j * B + bglob;
                float T = g_T[tbase + ix];
                float cp = (t > 0) ? g_c[ix] : 0.f;
                float cn = sigmoidf_(ff) * cp + sigmoidf_(fi) * T * tanhf(fg);
                g_c[ix] = cn;
                float h = sigmoidf_(fo) * tanhf(cn);
                __nv_bfloat16 hh = __float2bfloat16(h);
                g_Hhi[tbase + ix] = hh;
                g_Hlo[tbase + ix] = __float2bfloat16(h - __bfloat162float(hh));
            }
        }

        if (t + 1 >= SB) break;

        // publish h[t] and arrive at this bt-group's barrier for step t
        __threadfence();
        __syncthreads();
        if (tid == 0) {
            int v = atomicAdd(&g_cnt[gslot], 1);
            if (v == GRP - 1) {
                atomicExch(&g_cnt[gslot], 0);
                __threadfence();
                g_gen[gslot] = t + 1;
            }
        }

        // overlap: static preactivation for t+1 (own tile, independent of barrier)
        #pragma unroll
        for (int i = 0; i < 64; i++) afl[i] = 0.f;
        run_gemm(g_Aphi + (size_t)(t + 1) * KSTAT * B, g_Aplo + (size_t)(t + 1) * KSTAT * B, 0, 9);

        // wait for the 8 CTAs of this bt-group to have published h[t]
        if (tid == 0) {
            while (g_gen[gslot] <= t) __nanosleep(32);
        }
        __syncthreads();
    }
}

// ============================================================
// k_out: output heads from h1 = hi + lo
// ============================================================
__global__ void k_out(const float* __restrict__ Wc, const float* __restrict__ bc,
                      const float* __restrict__ Wm, const float* __restrict__ bm,
                      float* __restrict__ out)
{
    __shared__ float sh[256][32];
    __shared__ float sl[32][25];
    int t = blockIdx.x;
    int b0 = blockIdx.y * 32;
    int tid = threadIdx.x;

    for (int e = tid; e < 256 * 32; e += 256) {
        int jj = e >> 5, b = e & 31;
        size_t ix = ((size_t)t * H + jj) * B + b0 + b;
        sh[jj][b] = __bfloat162float(g_Hhi[ix]) + __bfloat162float(g_Hlo[ix]);
    }
    __syncthreads();

    for (int o = tid; o < 32 * 25; o += 256) {
        int r = o / 25, jx = o % 25;
        float s;
        if (jx < 3) {
            s = bc[jx];
            #pragma unroll 8
            for (int k = 0; k < H; k++) s += sh[k][r] * Wc[k * 3 + jx];
        } else {
            int jj = jx - 3;
            s = bm[jj];
            #pragma unroll 8
            for (int k = 0; k < H; k++) s += sh[k][r] * Wm[k * 22 + jj];
        }
        sl[r][jx] = s;
    }
    __syncthreads();

    float* out_cat = out;
    float* out_val = out + (size_t)SB * B * 3;
    for (int o = tid; o < 32 * 25; o += 256) {
        int r = o / 25, jx = o % 25;
        int b = b0 + r;
        if (jx < 3) {
            float l0 = sl[r][0], l1 = sl[r][1], l2 = sl[r][2];
            float mx = fmaxf(l0, fmaxf(l1, l2));
            float e0 = expf(l0 - mx), e1 = expf(l1 - mx), e2 = expf(l2 - mx);
            float inv = 1.f / (e0 + e1 + e2);
            float v = (jx == 0 ? e0 : (jx == 1 ? e1 : e2)) * inv;
            out_cat[(size_t)t * B * 3 + (size_t)b * 3 + jx] = v;
        } else {
            out_val[(size_t)t * B * 22 + (size_t)b * 22 + (jx - 3)] = sl[r][jx];
        }
    }
}

// ============================================================
// launch
// ============================================================
extern "C" void kernel_launch(void* const* d_in, const int* in_sizes, int n_in,
                              void* d_out, int out_size)
{
    const float* val_seq = (const float*)d_in[1];
    const float* delta   = (const float*)d_in[2];
    const float* W_d     = (const float*)d_in[3];
    const float* b_d     = (const float*)d_in[4];
    const float* W_xt    = (const float*)d_in[5];
    const float* W_dt    = (const float*)d_in[6];
    const float* b_t     = (const float*)d_in[7];
    const float* W_x_s   = (const float*)d_in[8];
    const float* b_s     = (const float*)d_in[10];
    const float* W_x_p   = (const float*)d_in[11];
    const float* W_h_p   = (const float*)d_in[12];
    const float* W_s_p   = (const float*)d_in[13];
    const float* b_p     = (const float*)d_in[14];
    const float* Wc      = (const float*)d_in[15];
    const float* bcv     = (const float*)d_in[16];
    const float* Wm      = (const float*)d_in[17];
    const float* bm      = (const float*)d_in[18];
    float* out = (float*)d_out;

    cudaFuncSetAttribute(k_seq, cudaFuncAttributeMaxDynamicSharedMemorySize, SMEM_TOTAL);

    k_packw<<<(KTOT * G4 + 255) / 256, 256>>>(W_x_p, W_h_p, W_s_p, b_p);
    k_pre<<<dim3(SB, B / 64), 256>>>(val_seq, delta, W_d, b_d, W_xt, W_dt, b_t, W_x_s, b_s);

    k_seq<<<NCTA, 256, SMEM_TOTAL>>>();

    k_out<<<dim3(SB, B / 32), 256>>>(Wc, bcv, Wm, bm, out);
}

// round 9
// speedup vs baseline: 4.2370x; 1.1998x over previous
#include <cuda_runtime.h>
#include <cuda_fp16.h>
#include <math.h>
#include <stdint.h>

#define S    256
#define SB   255
#define B    4096
#define H    256
#define E    32
#define MM   20
#define G4   1024
#define KSP  320        // static K padded to 5*64 (rows 277..319 zero)
#define WROWS 576       // 320 static + 256 dyn
#define NCTA 256
#define NGRP 32
#define GRP  8

// ---------------- scratch (static device globals; < 4GB aarch64 adrp limit) ----------------
__device__ __align__(256) __half g_T [(size_t)SB*H*B];            // [t][j][b] plain
__device__ __align__(256) float  g_c [(size_t)H*B];               // [j][b]
__device__ __align__(256) __half g_Ah[(size_t)SB*32*KSP*128];     // [t][bt][k][128 swz]
__device__ __align__(256) __half g_Hh[(size_t)SB*32*H*128];       // [t][bt][j][128 swz]
__device__ __align__(256) __half g_Wh[(size_t)8*WROWS*128];       // [ntb][k][128 swz]
__device__ __align__(256) __half g_Wl[(size_t)8*WROWS*128];
__device__ __align__(256) int g_cnt[NGRP * 32];
__device__ __align__(256) volatile int g_gen[NGRP * 32];

__device__ __forceinline__ float sigmoidf_(float x) { return 1.f / (1.f + expf(-x)); }

__device__ __forceinline__ uint32_t smem_u32(const void* p) {
    uint32_t a;
    asm("{ .reg .u64 t; cvta.to.shared.u64 t, %1; cvt.u32.u64 %0, t; }" : "=r"(a) : "l"(p));
    return a;
}
__device__ __forceinline__ void ldsm4t(uint32_t* r, uint32_t addr) {
    asm volatile("ldmatrix.sync.aligned.m8n8.x4.trans.shared.b16 {%0,%1,%2,%3}, [%4];"
        : "=r"(r[0]), "=r"(r[1]), "=r"(r[2]), "=r"(r[3]) : "r"(addr));
}
__device__ __forceinline__ void mma_f16(float* d, const uint32_t* a, const uint32_t* b) {
    asm volatile("mma.sync.aligned.m16n8k16.row.col.f32.f16.f16.f32 "
        "{%0,%1,%2,%3}, {%4,%5,%6,%7}, {%8,%9}, {%0,%1,%2,%3};"
        : "+f"(d[0]), "+f"(d[1]), "+f"(d[2]), "+f"(d[3])
        : "r"(a[0]), "r"(a[1]), "r"(a[2]), "r"(a[3]), "r"(b[0]), "r"(b[1]));
}
__device__ __forceinline__ void bulkcp(uint32_t dst, const void* src, uint32_t n, uint32_t mbar) {
    asm volatile("cp.async.bulk.shared::cta.global.mbarrier::complete_tx::bytes [%0], [%1], %2, [%3];"
        :: "r"(dst), "l"(src), "r"(n), "r"(mbar) : "memory");
}
#define MBARRIER_INIT(a, c) \
    asm volatile("mbarrier.init.shared.b64 [%0], %1;" :: "r"((uint32_t)(a)), "r"((uint32_t)(c)) : "memory")
#define MBARRIER_WAIT_PARITY(a, ph) do { \
    uint32_t _m = (uint32_t)(a), _p = (uint32_t)(ph), _d; \
    asm volatile("{\n\t.reg .pred p;\n\t" \
        "mbarrier.try_wait.parity.acquire.cta.shared::cta.b64 p, [%1], %2;\n\t" \
        "selp.b32 %0, 1, 0, p;\n\t}" : "=r"(_d) : "r"(_m), "r"(_p) : "memory"); \
    if (!_d) { \
        asm volatile("{\n\t.reg .pred P1;\n\t" \
            "WL_%=:\n\t" \
            "mbarrier.try_wait.parity.acquire.cta.shared::cta.b64 P1, [%0], %1, 0x989680;\n\t" \
            "@P1 bra.uni WD_%=;\n\t" \
            "bra.uni WL_%=;\n\t" \
            "WD_%=:\n\t}" :: "r"(_m), "r"(_p) : "memory"); \
    } \
} while (0)

// smem: per stage 3 contiguous 16KB mats (A, Bh, Bl)
#define OFF_A  0
#define OFF_BH 16384
#define OFF_BL 32768
#define STAGE  49152
#define SMEM_TOTAL (2 * STAGE)   // 98304

// ============================================================
// k_packw: weights -> [ntb][k][128 swz] fp16 hi/lo; resets group barriers.
// k rows: 0-19 W_x_p | 20-275 W_s_p | 276 bias | 277-319 zero | 320-575 W_h_p
// ============================================================
__global__ void k_packw(const float* __restrict__ W_x_p, const float* __restrict__ W_h_p,
                        const float* __restrict__ W_s_p, const float* __restrict__ b_p)
{
    int idx = blockIdx.x * blockDim.x + threadIdx.x;
    if (idx < NGRP * 32) { g_cnt[idx] = 0; g_gen[idx] = 0; }
    if (idx >= 8 * WROWS * 128) return;
    int tile = idx / (WROWS * 128);
    int rem  = idx % (WROWS * 128);
    int k    = rem >> 7;
    int col  = rem & 127;               // logical column within tile
    int np = tile * 128 + col;
    int j = np >> 2, g = np & 3;
    int scol = g * H + j;
    float v;
    if (k < MM)            v = W_x_p[(size_t)k * G4 + scol];
    else if (k < MM + H)   v = W_s_p[(size_t)(k - MM) * G4 + scol];
    else if (k == 276)     v = b_p[scol];
    else if (k < KSP)      v = 0.f;
    else                   v = W_h_p[(size_t)(k - KSP) * G4 + scol];
    int u = col >> 3, e = col & 7;
    size_t dst = ((size_t)tile * WROWS + k) * 128 + (((u ^ (k & 7)) << 3) + e);
    __half hv = __float2half(v);
    g_Wh[dst] = hv;
    g_Wl[dst] = __float2half(v - __half2float(hv));
}

// ============================================================
// k_pre: T[t][j][b] fp16; static A (x rows, hs1 rows, bias) into swizzled tiled g_Ah
// grid (SB, B/64), block 256
// ============================================================
__global__ void k_pre(const float* __restrict__ val_seq, const float* __restrict__ delta,
                      const float* __restrict__ W_d,  const float* __restrict__ b_d,
                      const float* __restrict__ W_xt, const float* __restrict__ W_dt,
                      const float* __restrict__ b_t,
                      const float* __restrict__ W_x_s, const float* __restrict__ b_s)
{
    __shared__ float sx[64][20];
    __shared__ float sde[64][32];
    __shared__ float sT[256][16];
    __shared__ float sH[256][16];
    int t = blockIdx.x;
    int b0 = blockIdx.y * 64;
    int bt = b0 >> 7;
    int tid = threadIdx.x;
    size_t abase = ((size_t)t * 32 + bt) * KSP * 128;
    int blb0 = b0 & 127;   // b_local base within bt tile

    for (int e = tid; e < 64 * 20; e += 256) {
        int b = e / 20, k = e % 20;
        sx[b][k] = val_seq[((size_t)t * B + b0 + b) * MM + k];
    }
    for (int e = tid; e < 64 * 32; e += 256) {
        int b = e >> 5, ee = e & 31;
        float dd = delta[(size_t)t * B + b0 + b];
        sde[b][ee] = tanhf(dd * W_d[ee] + b_d[ee]);
    }
    __syncthreads();

    int j = tid;
    float wxt[20], wdt[32], wi[20], wo[20], wg[20];
    #pragma unroll
    for (int k = 0; k < 20; k++) wxt[k] = W_xt[k * H + j];
    #pragma unroll
    for (int e = 0; e < 32; e++) wdt[e] = W_dt[e * H + j];
    #pragma unroll
    for (int k = 0; k < 20; k++) {
        wi[k] = W_x_s[k * G4 + j];
        wo[k] = W_x_s[k * G4 + 2 * H + j];
        wg[k] = W_x_s[k * G4 + 3 * H + j];
    }
    float bt_ = b_t[j], bi = b_s[j], bo = b_s[2 * H + j], bg = b_s[3 * H + j];

    for (int bc = 0; bc < 4; bc++) {
        #pragma unroll 1
        for (int bl = 0; bl < 16; bl++) {
            int b = bc * 16 + bl;
            float tx = bt_, td = 0.f, ai = bi, ao = bo, ag = bg;
            #pragma unroll
            for (int k = 0; k < 20; k++) {
                float xv = sx[b][k];
                tx += xv * wxt[k]; ai += xv * wi[k]; ao += xv * wo[k]; ag += xv * wg[k];
            }
            #pragma unroll
            for (int e = 0; e < 32; e++) td += sde[b][e] * wdt[e];
            float T = sigmoidf_(tx + sigmoidf_(td));
            float cns = sigmoidf_(ai) * T * tanhf(ag);
            sT[j][bl] = T;
            sH[j][bl] = sigmoidf_(ao) * tanhf(cns);
        }
        __syncthreads();
        int blbase = blb0 + bc * 16;
        for (int e = tid; e < 256 * 16; e += 256) {
            int jj = e >> 4, bl = e & 15;
            g_T[((size_t)t * H + jj) * B + b0 + bc * 16 + bl] = __float2half(sT[jj][bl]);
            int k = 20 + jj;
            int b_local = blbase + bl;
            int u = b_local >> 3, ee = b_local & 7;
            g_Ah[abase + (size_t)k * 128 + (((u ^ (k & 7)) << 3) + ee)] = __float2half(sH[jj][bl]);
        }
        for (int e = tid; e < 20 * 16; e += 256) {
            int k = e >> 4, bl = e & 15;
            int b_local = blbase + bl;
            int u = b_local >> 3, ee = b_local & 7;
            g_Ah[abase + (size_t)k * 128 + (((u ^ (k & 7)) << 3) + ee)] = __float2half(sx[bc * 16 + bl][k]);
        }
        __syncthreads();
    }
    // bias row 276 = 1.0
    if (tid < 64) {
        int b_local = blb0 + tid;
        int u = b_local >> 3, ee = b_local & 7;
        g_Ah[abase + (size_t)276 * 128 + (((u ^ 4) << 3) + ee)] = __float2half(1.f);
    }
}

// ============================================================
// k_seq: persistent recurrence. 256 CTAs (2/SM). Bulk-copy pipelined chunks,
// fp16 2-pass MMA, register-carried static acc, per-bt group barriers.
// ============================================================
__global__ void __launch_bounds__(256, 2) k_seq()
{
    extern __shared__ __align__(16) char sm[];
    __shared__ __align__(8) unsigned long long mbar[2];
    int clin = blockIdx.x;
    int bt = clin >> 3, ntb = clin & 7;
    int gslot = bt * 32;
    int tid = threadIdx.x, lane = tid & 31, wid = tid >> 5;
    int wm = wid & 3, wn = wid >> 2;
    uint32_t smb = smem_u32(sm);
    uint32_t mb[2] = { smem_u32(&mbar[0]), smem_u32(&mbar[1]) };
    if (tid == 0) { MBARRIER_INIT(mb[0], 1); MBARRIER_INIT(mb[1], 1); }
    __syncthreads();
    uint32_t ph[2] = {0, 0};

    const __half* WhT = g_Wh + (size_t)ntb * WROWS * 128;
    const __half* WlT = g_Wl + (size_t)ntb * WROWS * 128;

    // lane addressing (16B units, swizzle u^(k&7))
    int kra = (lane >> 4) * 8 + (lane & 7);
    int ua0 = ((lane >> 3) & 1) + wm * 4;
    int swa = kra & 7;
    int krb = (lane & 7) + ((lane >> 3) & 1) * 8;
    int ub0 = (lane >> 4) + wn * 8;
    int swb = krb & 7;
    uint32_t aoff0 = (uint32_t)(kra * 256);
    uint32_t boff0 = (uint32_t)(krb * 256);

    float acc[2][8][4];
    float* afl = &acc[0][0][0];

    auto issue = [&](int stg, const __half* aSrc, int wrow) {
        if (tid == 0) {
            asm volatile("mbarrier.arrive.expect_tx.shared.b64 _, [%0], %1;"
                         :: "r"(mb[stg]), "r"(49152u) : "memory");
            uint32_t d = smb + (uint32_t)stg * STAGE;
            bulkcp(d + OFF_A,  aSrc,                     16384, mb[stg]);
            bulkcp(d + OFF_BH, WhT + (size_t)wrow * 128, 16384, mb[stg]);
            bulkcp(d + OFF_BL, WlT + (size_t)wrow * 128, 16384, mb[stg]);
        }
    };
    auto wait_stage = [&](int stg) {
        MBARRIER_WAIT_PARITY(mb[stg], ph[stg]);
        ph[stg] ^= 1;
    };
    auto compute_chunk = [&](int stg) {
        uint32_t sb = smb + (uint32_t)stg * STAGE;
        #pragma unroll
        for (int kf = 0; kf < 4; kf++) {
            uint32_t kofs = (uint32_t)(kf * 4096);
            uint32_t ah[2][4], bh[4][4];
            #pragma unroll
            for (int mf = 0; mf < 2; mf++)
                ldsm4t(ah[mf], sb + OFF_A + aoff0 + kofs + (uint32_t)(((ua0 + mf * 2) ^ swa) << 4));
            #pragma unroll
            for (int nf = 0; nf < 4; nf++)
                ldsm4t(bh[nf], sb + OFF_BH + boff0 + kofs + (uint32_t)(((ub0 + nf * 2) ^ swb) << 4));
            #pragma unroll
            for (int mf = 0; mf < 2; mf++)
                #pragma unroll
                for (int nf = 0; nf < 4; nf++) {
                    mma_f16(acc[mf][2 * nf],     ah[mf], bh[nf]);
                    mma_f16(acc[mf][2 * nf + 1], ah[mf], bh[nf] + 2);
                }
            uint32_t bl[4][4];
            #pragma unroll
            for (int nf = 0; nf < 4; nf++)
                ldsm4t(bl[nf], sb + OFF_BL + boff0 + kofs + (uint32_t)(((ub0 + nf * 2) ^ swb) << 4));
            #pragma unroll
            for (int mf = 0; mf < 2; mf++)
                #pragma unroll
                for (int nf = 0; nf < 4; nf++) {
                    mma_f16(acc[mf][2 * nf],     ah[mf], bl[nf]);
                    mma_f16(acc[mf][2 * nf + 1], ah[mf], bl[nf] + 2);
                }
        }
    };

    int odd = lane & 1, cpair = (lane >> 1) & 1, r_lane = lane >> 2;
    auto epilogue = [&](int t) {
        #pragma unroll
        for (int mf = 0; mf < 2; mf++) {
            int b_local = wm * 32 + mf * 16 + r_lane + (odd ? 8 : 0);
            int bglob = bt * 128 + b_local;
            #pragma unroll
            for (int nt = 0; nt < 8; nt++) {
                float d0 = acc[mf][nt][0], d1 = acc[mf][nt][1];
                float d2 = acc[mf][nt][2], d3 = acc[mf][nt][3];
                float s1 = odd ? d0 : d2;
                float s2 = odd ? d1 : d3;
                float r1 = __shfl_xor_sync(0xffffffffu, s1, 1);
                float r2 = __shfl_xor_sync(0xffffffffu, s2, 1);
                float fi = odd ? r1 : d0;
                float ff = odd ? r2 : d1;
                float fo = odd ? d2 : r1;
                float fg = odd ? d3 : r2;
                int j = ntb * 32 + wn * 16 + nt * 2 + cpair;
                size_t cix = (size_t)j * B + bglob;
                float T = __half2float(g_T[(size_t)t * H * B + cix]);
                float cp = (t > 0) ? g_c[cix] : 0.f;
                float cn = sigmoidf_(ff) * cp + sigmoidf_(fi) * T * tanhf(fg);
                g_c[cix] = cn;
                float h = sigmoidf_(fo) * tanhf(cn);
                g_Hh[(((size_t)t * 32 + bt) * H + j) * 128 +
                     ((((b_local >> 3) ^ (j & 7)) << 3) + (b_local & 7))] = __float2half(h);
            }
        }
    };
    auto arrive = [&](int t) {
        __threadfence();
        __syncthreads();
        if (tid == 0) {
            int v = atomicAdd(&g_cnt[gslot], 1);
            if (v == GRP - 1) {
                atomicExch(&g_cnt[gslot], 0);
                __threadfence();
                g_gen[gslot] = t + 1;
            }
        }
    };

    int gb = 0;
    #pragma unroll
    for (int i = 0; i < 64; i++) afl[i] = 0.f;

    // prologue: static(0), 5 chunks
    {
        const __half* A0 = g_Ah + ((size_t)bt) * KSP * 128;   // t=0
        issue(gb & 1, A0, 0);
        issue((gb + 1) & 1, A0 + (size_t)64 * 128, 64);
        for (int c = 0; c < 5; c++) {
            int stg = (gb + c) & 1;
            wait_stage(stg);
            compute_chunk(stg);
            __syncthreads();
            if (c + 2 < 5) issue(stg, A0 + (size_t)(c + 2) * 64 * 128, (c + 2) * 64);
        }
        gb += 5;
    }

    for (int t = 0; t < SB; t++) {
        int dynN = (t > 0) ? 4 : 0;
        int statN = (t + 1 < SB) ? 5 : 0;
        int n = dynN + statN;
        const __half* Ad = g_Hh + ((size_t)(t - 1) * 32 + bt) * H * 128;     // valid if t>0
        const __half* As = g_Ah + ((size_t)(t + 1) * 32 + bt) * KSP * 128;   // valid if t+1<SB
        auto srci = [&](int c, int stg) {
            if (c < dynN) issue(stg, Ad + (size_t)c * 64 * 128, KSP + c * 64);
            else { int s2 = c - dynN; issue(stg, As + (size_t)s2 * 64 * 128, s2 * 64); }
        };
        if (n > 0) srci(0, gb & 1);
        if (n > 1) srci(1, (gb + 1) & 1);

        if (dynN == 0) {   // t == 0: acc already holds static(0)
            epilogue(0);
            arrive(0);
            #pragma unroll
            for (int i = 0; i < 64; i++) afl[i] = 0.f;
        }
        for (int c = 0; c < n; c++) {
            int stg = (gb + c) & 1;
            wait_stage(stg);
            compute_chunk(stg);
            if (c == dynN - 1 && dynN > 0) {
                epilogue(t);
                arrive(t);
                #pragma unroll
                for (int i = 0; i < 64; i++) afl[i] = 0.f;
            }
            __syncthreads();
            if (c + 2 < n) srci(c + 2, stg);
        }
        gb += n;

        if (t + 1 < SB) {
            if (tid == 0) { while (g_gen[gslot] <= t) __nanosleep(32); }
            __syncthreads();
        }
    }
}

// ============================================================
// k_out: output heads; reads swizzled tiled g_Hh
// ============================================================
__global__ void k_out(const float* __restrict__ Wc, const float* __restrict__ bc,
                      const float* __restrict__ Wm, const float* __restrict__ bm,
                      float* __restrict__ out)
{
    __shared__ float sh[256][32];
    __shared__ float sl[32][25];
    int t = blockIdx.x;
    int b0 = blockIdx.y * 32;
    int bt = b0 >> 7;
    int tid = threadIdx.x;

    for (int e = tid; e < 256 * 32; e += 256) {
        int jj = e >> 5, bb = e & 31;
        int b_local = (b0 & 127) + bb;
        int u = b_local >> 3, ee = b_local & 7;
        sh[jj][bb] = __half2float(
            g_Hh[(((size_t)t * 32 + bt) * H + jj) * 128 + (((u ^ (jj & 7)) << 3) + ee)]);
    }
    __syncthreads();

    for (int o = tid; o < 32 * 25; o += 256) {
        int r = o / 25, jx = o % 25;
        float s;
        if (jx < 3) {
            s = bc[jx];
            #pragma unroll 8
            for (int k = 0; k < H; k++) s += sh[k][r] * Wc[k * 3 + jx];
        } else {
            int jj = jx - 3;
            s = bm[jj];
            #pragma unroll 8
            for (int k = 0; k < H; k++) s += sh[k][r] * Wm[k * 22 + jj];
        }
        sl[r][jx] = s;
    }
    __syncthreads();

    float* out_cat = out;
    float* out_val = out + (size_t)SB * B * 3;
    for (int o = tid; o < 32 * 25; o += 256) {
        int r = o / 25, jx = o % 25;
        int b = b0 + r;
        if (jx < 3) {
            float l0 = sl[r][0], l1 = sl[r][1], l2 = sl[r][2];
            float mx = fmaxf(l0, fmaxf(l1, l2));
            float e0 = expf(l0 - mx), e1 = expf(l1 - mx), e2 = expf(l2 - mx);
            float inv = 1.f / (e0 + e1 + e2);
            float v = (jx == 0 ? e0 : (jx == 1 ? e1 : e2)) * inv;
            out_cat[(size_t)t * B * 3 + (size_t)b * 3 + jx] = v;
        } else {
            out_val[(size_t)t * B * 22 + (size_t)b * 22 + (jx - 3)] = sl[r][jx];
        }
    }
}

// ============================================================
// launch
// ============================================================
extern "C" void kernel_launch(void* const* d_in, const int* in_sizes, int n_in,
                              void* d_out, int out_size)
{
    const float* val_seq = (const float*)d_in[1];
    const float* delta   = (const float*)d_in[2];
    const float* W_d     = (const float*)d_in[3];
    const float* b_d     = (const float*)d_in[4];
    const float* W_xt    = (const float*)d_in[5];
    const float* W_dt    = (const float*)d_in[6];
    const float* b_t     = (const float*)d_in[7];
    const float* W_x_s   = (const float*)d_in[8];
    const float* b_s     = (const float*)d_in[10];
    const float* W_x_p   = (const float*)d_in[11];
    const float* W_h_p   = (const float*)d_in[12];
    const float* W_s_p   = (const float*)d_in[13];
    const float* b_p     = (const float*)d_in[14];
    const float* Wc      = (const float*)d_in[15];
    const float* bcv     = (const float*)d_in[16];
    const float* Wm      = (const float*)d_in[17];
    const float* bm      = (const float*)d_in[18];
    float* out = (float*)d_out;

    cudaFuncSetAttribute(k_seq, cudaFuncAttributeMaxDynamicSharedMemorySize, SMEM_TOTAL);

    k_packw<<<(8 * WROWS * 128 + 255) / 256, 256>>>(W_x_p, W_h_p, W_s_p, b_p);
    k_pre<<<dim3(SB, B / 64), 256>>>(val_seq, delta, W_d, b_d, W_xt, W_dt, b_t, W_x_s, b_s);

    k_seq<<<NCTA, 256, SMEM_TOTAL>>>();

    k_out<<<dim3(SB, B / 32), 256>>>(Wc, bcv, Wm, bm, out);
}

// round 10
// speedup vs baseline: 4.5105x; 1.0645x over previous
#include <cuda_runtime.h>
#include <cuda_fp16.h>
#include <math.h>
#include <stdint.h>

#define S    256
#define SB   255
#define B    4096
#define H    256
#define MM   20
#define G4   1024
#define KSP  320        // static K padded to 5*64 (rows 277..319 zero)
#define WROWS 576       // 320 static + 256 dyn
#define NCTA 256
#define NGRP 32
#define GRP  8

// ---------------- scratch (static device globals; total ~3.88GB, < ~4GB aarch64 adrp limit) ----------------
__device__ __align__(256) __half g_Tf  [(size_t)SB*256*256*16];   // [t][tile][tid][slot] frag layout
__device__ __align__(256) __half g_blob[(size_t)SB*256*256*64];   // static pre, frag layout fp16
__device__ __align__(256) __half g_Ah[(size_t)SB*32*KSP*128];     // [t][bt][k][128 swz]
__device__ __align__(256) __half g_Hh[(size_t)SB*32*H*128];       // [t][bt][j][128 swz]
__device__ __align__(256) __half g_Wh[(size_t)8*WROWS*128];       // [ntb][k][128 swz]
__device__ __align__(256) __half g_Wl[(size_t)8*WROWS*128];
__device__ __align__(256) int g_cnt[NGRP * 32];
__device__ __align__(256) volatile int g_gen[NGRP * 32];

__device__ __forceinline__ float sigmoidf_(float x) { return 1.f / (1.f + expf(-x)); }

__device__ __forceinline__ uint32_t smem_u32(const void* p) {
    uint32_t a;
    asm("{ .reg .u64 t; cvta.to.shared.u64 t, %1; cvt.u32.u64 %0, t; }" : "=r"(a) : "l"(p));
    return a;
}
__device__ __forceinline__ void ldsm4t(uint32_t* r, uint32_t addr) {
    asm volatile("ldmatrix.sync.aligned.m8n8.x4.trans.shared.b16 {%0,%1,%2,%3}, [%4];"
        : "=r"(r[0]), "=r"(r[1]), "=r"(r[2]), "=r"(r[3]) : "r"(addr));
}
__device__ __forceinline__ void mma_f16(float* d, const uint32_t* a, const uint32_t* b) {
    asm volatile("mma.sync.aligned.m16n8k16.row.col.f32.f16.f16.f32 "
        "{%0,%1,%2,%3}, {%4,%5,%6,%7}, {%8,%9}, {%0,%1,%2,%3};"
        : "+f"(d[0]), "+f"(d[1]), "+f"(d[2]), "+f"(d[3])
        : "r"(a[0]), "r"(a[1]), "r"(a[2]), "r"(a[3]), "r"(b[0]), "r"(b[1]));
}
__device__ __forceinline__ void bulkcp(uint32_t dst, const void* src, uint32_t n, uint32_t mbar) {
    asm volatile("cp.async.bulk.shared::cta.global.mbarrier::complete_tx::bytes [%0], [%1], %2, [%3];"
        :: "r"(dst), "l"(src), "r"(n), "r"(mbar) : "memory");
}
#define MBARRIER_INIT(a, c) \
    asm volatile("mbarrier.init.shared.b64 [%0], %1;" :: "r"((uint32_t)(a)), "r"((uint32_t)(c)) : "memory")
#define MBARRIER_EXPECT_TX(a, n) \
    asm volatile("mbarrier.arrive.expect_tx.shared.b64 _, [%0], %1;" :: "r"((uint32_t)(a)), "r"((uint32_t)(n)) : "memory")
#define MBARRIER_WAIT_PARITY(a, ph) do { \
    uint32_t _m = (uint32_t)(a), _p = (uint32_t)(ph), _d; \
    asm volatile("{\n\t.reg .pred p;\n\t" \
        "mbarrier.try_wait.parity.acquire.cta.shared::cta.b64 p, [%1], %2;\n\t" \
        "selp.b32 %0, 1, 0, p;\n\t}" : "=r"(_d) : "r"(_m), "r"(_p) : "memory"); \
    if (!_d) { \
        asm volatile("{\n\t.reg .pred P1;\n\t" \
            "WL_%=:\n\t" \
            "mbarrier.try_wait.parity.acquire.cta.shared::cta.b64 P1, [%0], %1, 0x989680;\n\t" \
            "@P1 bra.uni WD_%=;\n\t" \
            "bra.uni WL_%=;\n\t" \
            "WD_%=:\n\t}" :: "r"(_m), "r"(_p) : "memory"); \
    } \
} while (0)

#define OFF_A  0
#define OFF_BH 16384
#define OFF_BL 32768
#define STAGE  49152
#define SMEM_TOTAL (2 * STAGE)   // 98304

// ============================================================
// k_packw: weights -> [ntb][k][128 swz] fp16 hi/lo; resets group barriers.
// ============================================================
__global__ void k_packw(const float* __restrict__ W_x_p, const float* __restrict__ W_h_p,
                        const float* __restrict__ W_s_p, const float* __restrict__ b_p)
{
    int idx = blockIdx.x * blockDim.x + threadIdx.x;
    if (idx < NGRP * 32) { g_cnt[idx] = 0; g_gen[idx] = 0; }
    if (idx >= 8 * WROWS * 128) return;
    int tile = idx / (WROWS * 128);
    int rem  = idx % (WROWS * 128);
    int k    = rem >> 7;
    int col  = rem & 127;
    int np = tile * 128 + col;
    int j = np >> 2, g = np & 3;
    int scol = g * H + j;
    float v;
    if (k < MM)            v = W_x_p[(size_t)k * G4 + scol];
    else if (k < MM + H)   v = W_s_p[(size_t)(k - MM) * G4 + scol];
    else if (k == 276)     v = b_p[scol];
    else if (k < KSP)      v = 0.f;
    else                   v = W_h_p[(size_t)(k - KSP) * G4 + scol];
    int u = col >> 3, e = col & 7;
    size_t dst = ((size_t)tile * WROWS + k) * 128 + (((u ^ (k & 7)) << 3) + e);
    __half hv = __float2half(v);
    g_Wh[dst] = hv;
    g_Wl[dst] = __float2half(v - __half2float(hv));
}

// ============================================================
// k_pre: T into frag layout g_Tf; static A rows into swizzled tiled g_Ah
// grid (SB, B/64), block 256
// ============================================================
__global__ void k_pre(const float* __restrict__ val_seq, const float* __restrict__ delta,
                      const float* __restrict__ W_d,  const float* __restrict__ b_d,
                      const float* __restrict__ W_xt, const float* __restrict__ W_dt,
                      const float* __restrict__ b_t,
                      const float* __restrict__ W_x_s, const float* __restrict__ b_s)
{
    __shared__ float sx[64][20];
    __shared__ float sde[64][32];
    __shared__ float sT[256][16];
    __shared__ float sH[256][16];
    int t = blockIdx.x;
    int b0 = blockIdx.y * 64;
    int bt = b0 >> 7;
    int tid = threadIdx.x;
    size_t abase = ((size_t)t * 32 + bt) * KSP * 128;

    for (int e = tid; e < 64 * 20; e += 256) {
        int b = e / 20, k = e % 20;
        sx[b][k] = val_seq[((size_t)t * B + b0 + b) * MM + k];
    }
    for (int e = tid; e < 64 * 32; e += 256) {
        int b = e >> 5, ee = e & 31;
        float dd = delta[(size_t)t * B + b0 + b];
        sde[b][ee] = tanhf(dd * W_d[ee] + b_d[ee]);
    }
    __syncthreads();

    int j = tid;
    float wxt[20], wdt[32], wi[20], wo[20], wg[20];
    #pragma unroll
    for (int k = 0; k < 20; k++) wxt[k] = W_xt[k * H + j];
    #pragma unroll
    for (int e = 0; e < 32; e++) wdt[e] = W_dt[e * H + j];
    #pragma unroll
    for (int k = 0; k < 20; k++) {
        wi[k] = W_x_s[k * G4 + j];
        wo[k] = W_x_s[k * G4 + 2 * H + j];
        wg[k] = W_x_s[k * G4 + 3 * H + j];
    }
    float bt_ = b_t[j], bi = b_s[j], bo = b_s[2 * H + j], bg = b_s[3 * H + j];

    for (int bc = 0; bc < 4; bc++) {
        #pragma unroll 1
        for (int bl = 0; bl < 16; bl++) {
            int b = bc * 16 + bl;
            float tx = bt_, td = 0.f, ai = bi, ao = bo, ag = bg;
            #pragma unroll
            for (int k = 0; k < 20; k++) {
                float xv = sx[b][k];
                tx += xv * wxt[k]; ai += xv * wi[k]; ao += xv * wo[k]; ag += xv * wg[k];
            }
            #pragma unroll
            for (int e = 0; e < 32; e++) td += sde[b][e] * wdt[e];
            float T = sigmoidf_(tx + sigmoidf_(td));
            float cns = sigmoidf_(ai) * T * tanhf(ag);
            sT[j][bl] = T;
            sH[j][bl] = sigmoidf_(ao) * tanhf(cns);
        }
        __syncthreads();
        for (int e = tid; e < 256 * 16; e += 256) {
            int jj = e >> 4, bl = e & 15;
            int b_local = (b0 & 127) + bc * 16 + bl;
            // frag-layout T write: (jj, b_local) -> (tile, tidt, slot)
            {
                int tile = bt * 8 + (jj >> 5);
                int wn = (jj >> 4) & 1, j_in = jj & 15, nt = j_in >> 1, cpair = j_in & 1;
                int wm = b_local >> 5, r = b_local & 31;
                int mf = r >> 4, oddb = (r >> 3) & 1, r_lane = r & 7;
                int tidt = ((wn << 2) | wm) * 32 + (oddb | (cpair << 1) | (r_lane << 2));
                int slot = mf * 8 + nt;
                g_Tf[(((size_t)t * 256 + tile) * 256 + tidt) * 16 + slot] = __float2half(sT[jj][bl]);
            }
            int k = 20 + jj;
            int u = b_local >> 3, ee = b_local & 7;
            g_Ah[abase + (size_t)k * 128 + (((u ^ (k & 7)) << 3) + ee)] = __float2half(sH[jj][bl]);
        }
        for (int e = tid; e < 20 * 16; e += 256) {
            int k = e >> 4, bl = e & 15;
            int b_local = (b0 & 127) + bc * 16 + bl;
            int u = b_local >> 3, ee = b_local & 7;
            g_Ah[abase + (size_t)k * 128 + (((u ^ (k & 7)) << 3) + ee)] = __float2half(sx[bc * 16 + bl][k]);
        }
        __syncthreads();
    }
    // bias row 276 = 1.0
    if (tid < 64) {
        int b_local = (b0 & 127) + tid;
        int u = b_local >> 3, ee = b_local & 7;
        g_Ah[abase + (size_t)276 * 128 + (((u ^ 4) << 3) + ee)] = __float2half(1.f);
    }
}

// ============================================================
// k_static: massively parallel static-pre GEMM for ALL steps.
// grid (256 tiles, SB), 256 threads, 2-stage bulk pipeline, 5 chunks, 2-pass fp16.
// Writes g_blob in frag layout (fp16).
// ============================================================
__global__ void __launch_bounds__(256, 2) k_static()
{
    extern __shared__ __align__(16) char sm[];
    __shared__ __align__(8) unsigned long long mbar[2];
    int tile = blockIdx.x, t = blockIdx.y;
    int bt = tile >> 3, ntb = tile & 7;
    int tid = threadIdx.x, lane = tid & 31, wid = tid >> 5;
    int wm = wid & 3, wn = wid >> 2;
    uint32_t smb = smem_u32(sm);
    uint32_t mb[2] = { smem_u32(&mbar[0]), smem_u32(&mbar[1]) };
    if (tid == 0) { MBARRIER_INIT(mb[0], 1); MBARRIER_INIT(mb[1], 1); }
    __syncthreads();
    uint32_t ph[2] = {0, 0};

    const __half* A0  = g_Ah + ((size_t)t * 32 + bt) * KSP * 128;
    const __half* WhT = g_Wh + (size_t)ntb * WROWS * 128;
    const __half* WlT = g_Wl + (size_t)ntb * WROWS * 128;

    int kra = (lane >> 4) * 8 + (lane & 7);
    int ua0 = ((lane >> 3) & 1) + wm * 4;
    int swa = kra & 7;
    int krb = (lane & 7) + ((lane >> 3) & 1) * 8;
    int ub0 = (lane >> 4) + wn * 8;
    int swb = krb & 7;
    uint32_t aoff0 = (uint32_t)(kra * 256);
    uint32_t boff0 = (uint32_t)(krb * 256);

    float acc[2][8][4];
    float* afl = &acc[0][0][0];
    #pragma unroll
    for (int i = 0; i < 64; i++) afl[i] = 0.f;

    auto issue = [&](int stg, int c) {
        if (tid == 0) {
            MBARRIER_EXPECT_TX(mb[stg], 49152u);
            uint32_t d = smb + (uint32_t)stg * STAGE;
            bulkcp(d + OFF_A,  A0  + (size_t)c * 64 * 128, 16384, mb[stg]);
            bulkcp(d + OFF_BH, WhT + (size_t)c * 64 * 128, 16384, mb[stg]);
            bulkcp(d + OFF_BL, WlT + (size_t)c * 64 * 128, 16384, mb[stg]);
        }
    };
    issue(0, 0); issue(1, 1);

    for (int c = 0; c < 5; c++) {
        int stg = c & 1;
        MBARRIER_WAIT_PARITY(mb[stg], ph[stg]); ph[stg] ^= 1;
        uint32_t sb = smb + (uint32_t)stg * STAGE;
        #pragma unroll
        for (int kf = 0; kf < 4; kf++) {
            uint32_t kofs = (uint32_t)(kf * 4096);
            uint32_t ah[2][4], bh[4][4];
            #pragma unroll
            for (int mf = 0; mf < 2; mf++)
                ldsm4t(ah[mf], sb + OFF_A + aoff0 + kofs + (uint32_t)(((ua0 + mf * 2) ^ swa) << 4));
            #pragma unroll
            for (int nf = 0; nf < 4; nf++)
                ldsm4t(bh[nf], sb + OFF_BH + boff0 + kofs + (uint32_t)(((ub0 + nf * 2) ^ swb) << 4));
            #pragma unroll
            for (int mf = 0; mf < 2; mf++)
                #pragma unroll
                for (int nf = 0; nf < 4; nf++) {
                    mma_f16(acc[mf][2 * nf],     ah[mf], bh[nf]);
                    mma_f16(acc[mf][2 * nf + 1], ah[mf], bh[nf] + 2);
                }
            uint32_t bl[4][4];
            #pragma unroll
            for (int nf = 0; nf < 4; nf++)
                ldsm4t(bl[nf], sb + OFF_BL + boff0 + kofs + (uint32_t)(((ub0 + nf * 2) ^ swb) << 4));
            #pragma unroll
            for (int mf = 0; mf < 2; mf++)
                #pragma unroll
                for (int nf = 0; nf < 4; nf++) {
                    mma_f16(acc[mf][2 * nf],     ah[mf], bl[nf]);
                    mma_f16(acc[mf][2 * nf + 1], ah[mf], bl[nf] + 2);
                }
        }
        __syncthreads();
        if (c + 2 < 5) issue(stg, c + 2);
    }

    // write blob (fp16, frag layout, 128B/thread)
    __half hb[64];
    #pragma unroll
    for (int i = 0; i < 64; i++) hb[i] = __float2half(afl[i]);
    uint4* bp = (uint4*)(g_blob + (((size_t)t * 256 + tile) * 256 + tid) * 64);
    #pragma unroll
    for (int i = 0; i < 8; i++) bp[i] = ((const uint4*)hb)[i];
}

// ============================================================
// k_seq: persistent recurrence, dyn-only (4 chunks/step).
// 256 CTAs (2/SM). acc init from blob; T from frag g_Tf; c in registers.
// B copies + blob/T loads issued pre-spin; A(h[t-1]) copies post-spin.
// ============================================================
__global__ void __launch_bounds__(256, 2) k_seq()
{
    extern __shared__ __align__(16) char sm[];
    __shared__ __align__(8) unsigned long long mbar[2];
    int clin = blockIdx.x;
    int bt = clin >> 3, ntb = clin & 7;
    int gslot = bt * 32;
    int tid = threadIdx.x, lane = tid & 31, wid = tid >> 5;
    int wm = wid & 3, wn = wid >> 2;
    uint32_t smb = smem_u32(sm);
    uint32_t mb[2] = { smem_u32(&mbar[0]), smem_u32(&mbar[1]) };
    if (tid == 0) { MBARRIER_INIT(mb[0], 1); MBARRIER_INIT(mb[1], 1); }
    __syncthreads();
    uint32_t ph[2] = {0, 0};

    const __half* WhT = g_Wh + (size_t)ntb * WROWS * 128 + (size_t)KSP * 128;  // dyn rows
    const __half* WlT = g_Wl + (size_t)ntb * WROWS * 128 + (size_t)KSP * 128;

    int kra = (lane >> 4) * 8 + (lane & 7);
    int ua0 = ((lane >> 3) & 1) + wm * 4;
    int swa = kra & 7;
    int krb = (lane & 7) + ((lane >> 3) & 1) * 8;
    int ub0 = (lane >> 4) + wn * 8;
    int swb = krb & 7;
    uint32_t aoff0 = (uint32_t)(kra * 256);
    uint32_t boff0 = (uint32_t)(krb * 256);

    float acc[2][8][4];
    float* afl = &acc[0][0][0];
    float c_reg[16];
    #pragma unroll
    for (int i = 0; i < 16; i++) c_reg[i] = 0.f;

    int odd = lane & 1, cpair = (lane >> 1) & 1, r_lane = lane >> 2;

    auto compute_chunk = [&](int stg) {
        uint32_t sb = smb + (uint32_t)stg * STAGE;
        #pragma unroll
        for (int kf = 0; kf < 4; kf++) {
            uint32_t kofs = (uint32_t)(kf * 4096);
            uint32_t ah[2][4], bh[4][4];
            #pragma unroll
            for (int mf = 0; mf < 2; mf++)
                ldsm4t(ah[mf], sb + OFF_A + aoff0 + kofs + (uint32_t)(((ua0 + mf * 2) ^ swa) << 4));
            #pragma unroll
            for (int nf = 0; nf < 4; nf++)
                ldsm4t(bh[nf], sb + OFF_BH + boff0 + kofs + (uint32_t)(((ub0 + nf * 2) ^ swb) << 4));
            #pragma unroll
            for (int mf = 0; mf < 2; mf++)
                #pragma unroll
                for (int nf = 0; nf < 4; nf++) {
                    mma_f16(acc[mf][2 * nf],     ah[mf], bh[nf]);
                    mma_f16(acc[mf][2 * nf + 1], ah[mf], bh[nf] + 2);
                }
            uint32_t bl[4][4];
            #pragma unroll
            for (int nf = 0; nf < 4; nf++)
                ldsm4t(bl[nf], sb + OFF_BL + boff0 + kofs + (uint32_t)(((ub0 + nf * 2) ^ swb) << 4));
            #pragma unroll
            for (int mf = 0; mf < 2; mf++)
                #pragma unroll
                for (int nf = 0; nf < 4; nf++) {
                    mma_f16(acc[mf][2 * nf],     ah[mf], bl[nf]);
                    mma_f16(acc[mf][2 * nf + 1], ah[mf], bl[nf] + 2);
                }
        }
    };

    auto epilogue = [&](int t, const __half* tv) {
        #pragma unroll
        for (int mf = 0; mf < 2; mf++) {
            int b_local = wm * 32 + mf * 16 + r_lane + (odd ? 8 : 0);
            #pragma unroll
            for (int nt = 0; nt < 8; nt++) {
                float d0 = acc[mf][nt][0], d1 = acc[mf][nt][1];
                float d2 = acc[mf][nt][2], d3 = acc[mf][nt][3];
                float s1 = odd ? d0 : d2;
                float s2 = odd ? d1 : d3;
                float r1 = __shfl_xor_sync(0xffffffffu, s1, 1);
                float r2 = __shfl_xor_sync(0xffffffffu, s2, 1);
                float fi = odd ? r1 : d0;
                float ff = odd ? r2 : d1;
                float fo = odd ? d2 : r1;
                float fg = odd ? d3 : r2;
                int slot = mf * 8 + nt;
                float T = __half2float(tv[slot]);
                float cp = c_reg[slot];
                float cn = sigmoidf_(ff) * cp + sigmoidf_(fi) * T * tanhf(fg);
                c_reg[slot] = cn;
                float h = sigmoidf_(fo) * tanhf(cn);
                int j = ntb * 32 + wn * 16 + nt * 2 + cpair;
                g_Hh[(((size_t)t * 32 + bt) * H + j) * 128 +
                     ((((b_local >> 3) ^ (j & 7)) << 3) + (b_local & 7))] = __float2half(h);
            }
        }
    };
    auto arrive = [&](int t) {
        __threadfence();
        __syncthreads();
        if (tid == 0) {
            int v = atomicAdd(&g_cnt[gslot], 1);
            if (v == GRP - 1) {
                atomicExch(&g_cnt[gslot], 0);
                __threadfence();
                g_gen[gslot] = t + 1;
            }
        }
    };

    // ---- t = 0: acc = blob[0], no dyn GEMM ----
    {
        uint4 braw[8], traw[2];
        const uint4* bp = (const uint4*)(g_blob + ((size_t)clin * 256 + tid) * 64);
        #pragma unroll
        for (int i = 0; i < 8; i++) braw[i] = bp[i];
        const uint4* tp = (const uint4*)(g_Tf + ((size_t)clin * 256 + tid) * 16);
        traw[0] = tp[0]; traw[1] = tp[1];
        const __half* bh = (const __half*)braw;
        #pragma unroll
        for (int i = 0; i < 64; i++) afl[i] = __half2float(bh[i]);
        epilogue(0, (const __half*)traw);
        arrive(0);
    }

    for (int t = 1; t < SB; t++) {
        const __half* Ad = g_Hh + ((size_t)(t - 1) * 32 + bt) * H * 128;
        // pre-spin: B copies for chunks 0,1 (h-independent)
        if (tid == 0) {
            MBARRIER_EXPECT_TX(mb[0], 49152u);
            bulkcp(smb + OFF_BH, WhT, 16384, mb[0]);
            bulkcp(smb + OFF_BL, WlT, 16384, mb[0]);
            MBARRIER_EXPECT_TX(mb[1], 49152u);
            bulkcp(smb + STAGE + OFF_BH, WhT + (size_t)64 * 128, 16384, mb[1]);
            bulkcp(smb + STAGE + OFF_BL, WlT + (size_t)64 * 128, 16384, mb[1]);
        }
        // pre-spin: blob + T loads
        uint4 braw[8], traw[2];
        const uint4* bp = (const uint4*)(g_blob + (((size_t)t * 256 + clin) * 256 + tid) * 64);
        #pragma unroll
        for (int i = 0; i < 8; i++) braw[i] = bp[i];
        const uint4* tp = (const uint4*)(g_Tf + (((size_t)t * 256 + clin) * 256 + tid) * 16);
        traw[0] = tp[0]; traw[1] = tp[1];

        // wait for group to publish h[t-1]
        if (tid == 0) { while (g_gen[gslot] < t) __nanosleep(32); }
        __syncthreads();

        // post-spin: A copies for chunks 0,1
        if (tid == 0) {
            bulkcp(smb + OFF_A,         Ad,                     16384, mb[0]);
            bulkcp(smb + STAGE + OFF_A, Ad + (size_t)64 * 128,  16384, mb[1]);
        }

        // acc init from blob
        const __half* bh = (const __half*)braw;
        #pragma unroll
        for (int i = 0; i < 64; i++) afl[i] = __half2float(bh[i]);

        for (int c = 0; c < 4; c++) {
            int stg = c & 1;
            MBARRIER_WAIT_PARITY(mb[stg], ph[stg]); ph[stg] ^= 1;
            compute_chunk(stg);
            __syncthreads();
            if (c + 2 < 4 && tid == 0) {
                MBARRIER_EXPECT_TX(mb[stg], 49152u);
                uint32_t d = smb + (uint32_t)stg * STAGE;
                bulkcp(d + OFF_A,  Ad  + (size_t)(c + 2) * 64 * 128, 16384, mb[stg]);
                bulkcp(d + OFF_BH, WhT + (size_t)(c + 2) * 64 * 128, 16384, mb[stg]);
                bulkcp(d + OFF_BL, WlT + (size_t)(c + 2) * 64 * 128, 16384, mb[stg]);
            }
        }

        epilogue(t, (const __half*)traw);
        if (t + 1 < SB) arrive(t);
    }
}

// ============================================================
// k_out: output heads; reads swizzled tiled g_Hh
// ============================================================
__global__ void k_out(const float* __restrict__ Wc, const float* __restrict__ bc,
                      const float* __restrict__ Wm, const float* __restrict__ bm,
                      float* __restrict__ out)
{
    __shared__ float sh[256][32];
    __shared__ float sl[32][25];
    int t = blockIdx.x;
    int b0 = blockIdx.y * 32;
    int bt = b0 >> 7;
    int tid = threadIdx.x;

    for (int e = tid; e < 256 * 32; e += 256) {
        int jj = e >> 5, bb = e & 31;
        int b_local = (b0 & 127) + bb;
        int u = b_local >> 3, ee = b_local & 7;
        sh[jj][bb] = __half2float(
            g_Hh[(((size_t)t * 32 + bt) * H + jj) * 128 + (((u ^ (jj & 7)) << 3) + ee)]);
    }
    __syncthreads();

    for (int o = tid; o < 32 * 25; o += 256) {
        int r = o / 25, jx = o % 25;
        float s;
        if (jx < 3) {
            s = bc[jx];
            #pragma unroll 8
            for (int k = 0; k < H; k++) s += sh[k][r] * Wc[k * 3 + jx];
        } else {
            int jj = jx - 3;
            s = bm[jj];
            #pragma unroll 8
            for (int k = 0; k < H; k++) s += sh[k][r] * Wm[k * 22 + jj];
        }
        sl[r][jx] = s;
    }
    __syncthreads();

    float* out_cat = out;
    float* out_val = out + (size_t)SB * B * 3;
    for (int o = tid; o < 32 * 25; o += 256) {
        int r = o / 25, jx = o % 25;
        int b = b0 + r;
        if (jx < 3) {
            float l0 = sl[r][0], l1 = sl[r][1], l2 = sl[r][2];
            float mx = fmaxf(l0, fmaxf(l1, l2));
            float e0 = expf(l0 - mx), e1 = expf(l1 - mx), e2 = expf(l2 - mx);
            float inv = 1.f / (e0 + e1 + e2);
            float v = (jx == 0 ? e0 : (jx == 1 ? e1 : e2)) * inv;
            out_cat[(size_t)t * B * 3 + (size_t)b * 3 + jx] = v;
        } else {
            out_val[(size_t)t * B * 22 + (size_t)b * 22 + (jx - 3)] = sl[r][jx];
        }
    }
}

// ============================================================
// launch
// ============================================================
extern "C" void kernel_launch(void* const* d_in, const int* in_sizes, int n_in,
                              void* d_out, int out_size)
{
    const float* val_seq = (const float*)d_in[1];
    const float* delta   = (const float*)d_in[2];
    const float* W_d     = (const float*)d_in[3];
    const float* b_d     = (const float*)d_in[4];
    const float* W_xt    = (const float*)d_in[5];
    const float* W_dt    = (const float*)d_in[6];
    const float* b_t     = (const float*)d_in[7];
    const float* W_x_s   = (const float*)d_in[8];
    const float* b_s     = (const float*)d_in[10];
    const float* W_x_p   = (const float*)d_in[11];
    const float* W_h_p   = (const float*)d_in[12];
    const float* W_s_p   = (const float*)d_in[13];
    const float* b_p     = (const float*)d_in[14];
    const float* Wc      = (const float*)d_in[15];
    const float* bcv     = (const float*)d_in[16];
    const float* Wm      = (const float*)d_in[17];
    const float* bm      = (const float*)d_in[18];
    float* out = (float*)d_out;

    cudaFuncSetAttribute(k_static, cudaFuncAttributeMaxDynamicSharedMemorySize, SMEM_TOTAL);
    cudaFuncSetAttribute(k_seq,    cudaFuncAttributeMaxDynamicSharedMemorySize, SMEM_TOTAL);

    k_packw<<<(8 * WROWS * 128 + 255) / 256, 256>>>(W_x_p, W_h_p, W_s_p, b_p);
    k_pre<<<dim3(SB, B / 64), 256>>>(val_seq, delta, W_d, b_d, W_xt, W_dt, b_t, W_x_s, b_s);
    k_static<<<dim3(256, SB), 256, SMEM_TOTAL>>>();
    k_seq<<<NCTA, 256, SMEM_TOTAL>>>();
    k_out<<<dim3(SB, B / 32), 256>>>(Wc, bcv, Wm, bm, out);
}

// round 13
// speedup vs baseline: 5.0504x; 1.1197x over previous
#include <cuda_runtime.h>
#include <cuda_fp16.h>
#include <math.h>
#include <stdint.h>

#define S    256
#define SB   255
#define B    4096
#define H    256
#define MM   20
#define G4   1024
#define KSP  320        // static K padded to 5*64 (rows 277..319 zero)
#define WROWS 576       // 320 static + 256 dyn
#define NCTA 256
#define NGRP 32
#define GRP  8

// ---------------- scratch (static device globals; total ~3.88GB, < ~4GB aarch64 adrp limit) ----------------
__device__ __align__(256) __half g_Tf  [(size_t)SB*256*256*16];   // [t][tile][tid][slot] frag layout
__device__ __align__(256) __half g_blob[(size_t)SB*256*256*64];   // static pre, frag layout fp16
__device__ __align__(256) __half g_Ah[(size_t)SB*32*KSP*128];     // [t][bt][k][128 swz]
__device__ __align__(256) __half g_Hh[(size_t)SB*32*H*128];       // [t][bt][j][128 swz]
__device__ __align__(256) __half g_Wh[(size_t)8*WROWS*128];       // [ntb][k][128 swz]
__device__ __align__(256) __half g_Wl[(size_t)8*WROWS*128];
__device__ __align__(256) int g_cnt[NGRP * 32];
__device__ __align__(256) volatile int g_gen[NGRP * 32];

// ---- fast-but-accurate transcendentals (MUFU EX2 + RCP; ~1e-6 rel err) ----
__device__ __forceinline__ float fexp2_(float x) {
    float r; asm("ex2.approx.ftz.f32 %0, %1;" : "=f"(r) : "f"(x)); return r;
}
__device__ __forceinline__ float frcp_(float x) {
    float r; asm("rcp.approx.ftz.f32 %0, %1;" : "=f"(r) : "f"(x)); return r;
}
#define LOG2E 1.4426950408889634f
__device__ __forceinline__ float sigmoidf_(float x) {
    return frcp_(1.f + fexp2_(-x * LOG2E));
}
__device__ __forceinline__ float tanhf_(float x) {
    return 1.f - 2.f * frcp_(1.f + fexp2_(2.f * x * LOG2E));
}

__device__ __forceinline__ uint32_t smem_u32(const void* p) {
    uint32_t a;
    asm("{ .reg .u64 t; cvta.to.shared.u64 t, %1; cvt.u32.u64 %0, t; }" : "=r"(a) : "l"(p));
    return a;
}
__device__ __forceinline__ void ldsm4t(uint32_t* r, uint32_t addr) {
    asm volatile("ldmatrix.sync.aligned.m8n8.x4.trans.shared.b16 {%0,%1,%2,%3}, [%4];"
        : "=r"(r[0]), "=r"(r[1]), "=r"(r[2]), "=r"(r[3]) : "r"(addr));
}
__device__ __forceinline__ void mma_f16(float* d, const uint32_t* a, const uint32_t* b) {
    asm volatile("mma.sync.aligned.m16n8k16.row.col.f32.f16.f16.f32 "
        "{%0,%1,%2,%3}, {%4,%5,%6,%7}, {%8,%9}, {%0,%1,%2,%3};"
        : "+f"(d[0]), "+f"(d[1]), "+f"(d[2]), "+f"(d[3])
        : "r"(a[0]), "r"(a[1]), "r"(a[2]), "r"(a[3]), "r"(b[0]), "r"(b[1]));
}
__device__ __forceinline__ void bulkcp(uint32_t dst, const void* src, uint32_t n, uint32_t mbar) {
    asm volatile("cp.async.bulk.shared::cta.global.mbarrier::complete_tx::bytes [%0], [%1], %2, [%3];"
        :: "r"(dst), "l"(src), "r"(n), "r"(mbar) : "memory");
}
#define MBARRIER_INIT(a, c) \
    asm volatile("mbarrier.init.shared.b64 [%0], %1;" :: "r"((uint32_t)(a)), "r"((uint32_t)(c)) : "memory")
#define MBARRIER_EXPECT_TX(a, n) \
    asm volatile("mbarrier.arrive.expect_tx.shared.b64 _, [%0], %1;" :: "r"((uint32_t)(a)), "r"((uint32_t)(n)) : "memory")
#define MBARRIER_WAIT_PARITY(a, ph) do { \
    uint32_t _m = (uint32_t)(a), _p = (uint32_t)(ph), _d; \
    asm volatile("{\n\t.reg .pred p;\n\t" \
        "mbarrier.try_wait.parity.acquire.cta.shared::cta.b64 p, [%1], %2;\n\t" \
        "selp.b32 %0, 1, 0, p;\n\t}" : "=r"(_d) : "r"(_m), "r"(_p) : "memory"); \
    if (!_d) { \
        asm volatile("{\n\t.reg .pred P1;\n\t" \
            "WL_%=:\n\t" \
            "mbarrier.try_wait.parity.acquire.cta.shared::cta.b64 P1, [%0], %1, 0x989680;\n\t" \
            "@P1 bra.uni WD_%=;\n\t" \
            "bra.uni WL_%=;\n\t" \
            "WD_%=:\n\t}" :: "r"(_m), "r"(_p) : "memory"); \
    } \
} while (0)

// stage layout (both kernels): A 16K + Bh 16K + Bl 16K
#define OFF_A  0
#define OFF_BH 16384
#define OFF_BL 32768
#define STAGE  49152
#define SMEM_TOTAL (2 * STAGE)   // 98304

// ============================================================
// k_packw: weights -> [ntb][k][128 swz] fp16 hi/lo; resets group barriers.
// ============================================================
__global__ void k_packw(const float* __restrict__ W_x_p, const float* __restrict__ W_h_p,
                        const float* __restrict__ W_s_p, const float* __restrict__ b_p)
{
    int idx = blockIdx.x * blockDim.x + threadIdx.x;
    if (idx < NGRP * 32) { g_cnt[idx] = 0; g_gen[idx] = 0; }
    if (idx >= 8 * WROWS * 128) return;
    int tile = idx / (WROWS * 128);
    int rem  = idx % (WROWS * 128);
    int k    = rem >> 7;
    int col  = rem & 127;
    int np = tile * 128 + col;
    int j = np >> 2, g = np & 3;
    int scol = g * H + j;
    float v;
    if (k < MM)            v = W_x_p[(size_t)k * G4 + scol];
    else if (k < MM + H)   v = W_s_p[(size_t)(k - MM) * G4 + scol];
    else if (k == 276)     v = b_p[scol];
    else if (k < KSP)      v = 0.f;
    else                   v = W_h_p[(size_t)(k - KSP) * G4 + scol];
    int u = col >> 3, e = col & 7;
    size_t dst = ((size_t)tile * WROWS + k) * 128 + (((u ^ (k & 7)) << 3) + e);
    __half hv = __float2half(v);
    g_Wh[dst] = hv;
    g_Wl[dst] = __float2half(v - __half2float(hv));
}

// ============================================================
// k_pre: T into frag layout g_Tf; static A rows into swizzled tiled g_Ah
// grid (SB, B/64), block 256
// ============================================================
__global__ void k_pre(const float* __restrict__ val_seq, const float* __restrict__ delta,
                      const float* __restrict__ W_d,  const float* __restrict__ b_d,
                      const float* __restrict__ W_xt, const float* __restrict__ W_dt,
                      const float* __restrict__ b_t,
                      const float* __restrict__ W_x_s, const float* __restrict__ b_s)
{
    __shared__ float sx[64][20];
    __shared__ float sde[64][32];
    __shared__ float sT[256][16];
    __shared__ float sH[256][16];
    int t = blockIdx.x;
    int b0 = blockIdx.y * 64;
    int bt = b0 >> 7;
    int tid = threadIdx.x;
    size_t abase = ((size_t)t * 32 + bt) * KSP * 128;

    for (int e = tid; e < 64 * 20; e += 256) {
        int b = e / 20, k = e % 20;
        sx[b][k] = val_seq[((size_t)t * B + b0 + b) * MM + k];
    }
    for (int e = tid; e < 64 * 32; e += 256) {
        int b = e >> 5, ee = e & 31;
        float dd = delta[(size_t)t * B + b0 + b];
        sde[b][ee] = tanhf_(dd * W_d[ee] + b_d[ee]);
    }
    __syncthreads();

    int j = tid;
    float wxt[20], wdt[32], wi[20], wo[20], wg[20];
    #pragma unroll
    for (int k = 0; k < 20; k++) wxt[k] = W_xt[k * H + j];
    #pragma unroll
    for (int e = 0; e < 32; e++) wdt[e] = W_dt[e * H + j];
    #pragma unroll
    for (int k = 0; k < 20; k++) {
        wi[k] = W_x_s[k * G4 + j];
        wo[k] = W_x_s[k * G4 + 2 * H + j];
        wg[k] = W_x_s[k * G4 + 3 * H + j];
    }
    float bt_ = b_t[j], bi = b_s[j], bo = b_s[2 * H + j], bg = b_s[3 * H + j];

    for (int bc = 0; bc < 4; bc++) {
        #pragma unroll 1
        for (int bl = 0; bl < 16; bl++) {
            int b = bc * 16 + bl;
            float tx = bt_, td = 0.f, ai = bi, ao = bo, ag = bg;
            #pragma unroll
            for (int k = 0; k < 20; k++) {
                float xv = sx[b][k];
                tx += xv * wxt[k]; ai += xv * wi[k]; ao += xv * wo[k]; ag += xv * wg[k];
            }
            #pragma unroll
            for (int e = 0; e < 32; e++) td += sde[b][e] * wdt[e];
            float T = sigmoidf_(tx + sigmoidf_(td));
            float cns = sigmoidf_(ai) * T * tanhf_(ag);
            sT[j][bl] = T;
            sH[j][bl] = sigmoidf_(ao) * tanhf_(cns);
        }
        __syncthreads();
        for (int e = tid; e < 256 * 16; e += 256) {
            int jj = e >> 4, bl = e & 15;
            int b_local = (b0 & 127) + bc * 16 + bl;
            {
                int tile = bt * 8 + (jj >> 5);
                int wn = (jj >> 4) & 1, j_in = jj & 15, nt = j_in >> 1, cpair = j_in & 1;
                int wm = b_local >> 5, r = b_local & 31;
                int mf = r >> 4, oddb = (r >> 3) & 1, r_lane = r & 7;
                int tidt = ((wn << 2) | wm) * 32 + (oddb | (cpair << 1) | (r_lane << 2));
                int slot = mf * 8 + nt;
                g_Tf[(((size_t)t * 256 + tile) * 256 + tidt) * 16 + slot] = __float2half(sT[jj][bl]);
            }
            int k = 20 + jj;
            int u = b_local >> 3, ee = b_local & 7;
            g_Ah[abase + (size_t)k * 128 + (((u ^ (k & 7)) << 3) + ee)] = __float2half(sH[jj][bl]);
        }
        for (int e = tid; e < 20 * 16; e += 256) {
            int k = e >> 4, bl = e & 15;
            int b_local = (b0 & 127) + bc * 16 + bl;
            int u = b_local >> 3, ee = b_local & 7;
            g_Ah[abase + (size_t)k * 128 + (((u ^ (k & 7)) << 3) + ee)] = __float2half(sx[bc * 16 + bl][k]);
        }
        __syncthreads();
    }
    if (tid < 64) {
        int b_local = (b0 & 127) + tid;
        int u = b_local >> 3, ee = b_local & 7;
        g_Ah[abase + (size_t)276 * 128 + (((u ^ 4) << 3) + ee)] = __float2half(1.f);
    }
}

// ============================================================
// k_static: parallel static-pre GEMM for ALL steps (2-pass fp16, off critical path).
// ============================================================
__global__ void __launch_bounds__(256, 2) k_static()
{
    extern __shared__ __align__(16) char sm[];
    __shared__ __align__(8) unsigned long long mbar[2];
    int tile = blockIdx.x, t = blockIdx.y;
    int bt = tile >> 3, ntb = tile & 7;
    int tid = threadIdx.x, lane = tid & 31, wid = tid >> 5;
    int wm = wid & 3, wn = wid >> 2;
    uint32_t smb = smem_u32(sm);
    uint32_t mb[2] = { smem_u32(&mbar[0]), smem_u32(&mbar[1]) };
    if (tid == 0) { MBARRIER_INIT(mb[0], 1); MBARRIER_INIT(mb[1], 1); }
    __syncthreads();
    uint32_t ph[2] = {0, 0};

    const __half* A0  = g_Ah + ((size_t)t * 32 + bt) * KSP * 128;
    const __half* WhT = g_Wh + (size_t)ntb * WROWS * 128;
    const __half* WlT = g_Wl + (size_t)ntb * WROWS * 128;

    int kra = (lane >> 4) * 8 + (lane & 7);
    int ua0 = ((lane >> 3) & 1) + wm * 4;
    int swa = kra & 7;
    int krb = (lane & 7) + ((lane >> 3) & 1) * 8;
    int ub0 = (lane >> 4) + wn * 8;
    int swb = krb & 7;
    uint32_t aoff0 = (uint32_t)(kra * 256);
    uint32_t boff0 = (uint32_t)(krb * 256);

    float acc[2][8][4];
    float* afl = &acc[0][0][0];
    #pragma unroll
    for (int i = 0; i < 64; i++) afl[i] = 0.f;

    auto issue = [&](int stg, int c) {
        if (tid == 0) {
            MBARRIER_EXPECT_TX(mb[stg], 49152u);
            uint32_t d = smb + (uint32_t)stg * STAGE;
            bulkcp(d + OFF_A,  A0  + (size_t)c * 64 * 128, 16384, mb[stg]);
            bulkcp(d + OFF_BH, WhT + (size_t)c * 64 * 128, 16384, mb[stg]);
            bulkcp(d + OFF_BL, WlT + (size_t)c * 64 * 128, 16384, mb[stg]);
        }
    };
    issue(0, 0); issue(1, 1);

    for (int c = 0; c < 5; c++) {
        int stg = c & 1;
        MBARRIER_WAIT_PARITY(mb[stg], ph[stg]); ph[stg] ^= 1;
        uint32_t sb = smb + (uint32_t)stg * STAGE;
        #pragma unroll
        for (int kf = 0; kf < 4; kf++) {
            uint32_t kofs = (uint32_t)(kf * 4096);
            uint32_t ah[2][4], bh[4][4];
            #pragma unroll
            for (int mf = 0; mf < 2; mf++)
                ldsm4t(ah[mf], sb + OFF_A + aoff0 + kofs + (uint32_t)(((ua0 + mf * 2) ^ swa) << 4));
            #pragma unroll
            for (int nf = 0; nf < 4; nf++)
                ldsm4t(bh[nf], sb + OFF_BH + boff0 + kofs + (uint32_t)(((ub0 + nf * 2) ^ swb) << 4));
            #pragma unroll
            for (int mf = 0; mf < 2; mf++)
                #pragma unroll
                for (int nf = 0; nf < 4; nf++) {
                    mma_f16(acc[mf][2 * nf],     ah[mf], bh[nf]);
                    mma_f16(acc[mf][2 * nf + 1], ah[mf], bh[nf] + 2);
                }
            uint32_t bl[4][4];
            #pragma unroll
            for (int nf = 0; nf < 4; nf++)
                ldsm4t(bl[nf], sb + OFF_BL + boff0 + kofs + (uint32_t)(((ub0 + nf * 2) ^ swb) << 4));
            #pragma unroll
            for (int mf = 0; mf < 2; mf++)
                #pragma unroll
                for (int nf = 0; nf < 4; nf++) {
                    mma_f16(acc[mf][2 * nf],     ah[mf], bl[nf]);
                    mma_f16(acc[mf][2 * nf + 1], ah[mf], bl[nf] + 2);
                }
        }
        __syncthreads();
        if (c + 2 < 5) issue(stg, c + 2);
    }

    __half hb[64];
    #pragma unroll
    for (int i = 0; i < 64; i++) hb[i] = __float2half(afl[i]);
    uint4* bp = (uint4*)(g_blob + (((size_t)t * 256 + tile) * 256 + tid) * 64);
    #pragma unroll
    for (int i = 0; i < 8; i++) bp[i] = ((const uint4*)hb)[i];
}

// ============================================================
// k_seq: persistent recurrence, 2-pass fp16 dyn GEMM (4 chunks/step).
// 256 CTAs (2/SM). acc init from blob; T frag; c in registers.
// Epilogue h staged in smem -> proxy fence -> one 8KB bulk S2G by tid0.
// ============================================================
__global__ void __launch_bounds__(256, 2) k_seq()
{
    extern __shared__ __align__(16) char sm[];
    __shared__ __align__(8) unsigned long long mbar[2];
    __shared__ __align__(16) __half hstage[32 * 128];   // 8KB h staging
    int clin = blockIdx.x;
    int bt = clin >> 3, ntb = clin & 7;
    int gslot = bt * 32;
    int tid = threadIdx.x, lane = tid & 31, wid = tid >> 5;
    int wm = wid & 3, wn = wid >> 2;
    uint32_t smb = smem_u32(sm);
    uint32_t hsb = smem_u32(hstage);
    uint32_t mb[2] = { smem_u32(&mbar[0]), smem_u32(&mbar[1]) };
    if (tid == 0) { MBARRIER_INIT(mb[0], 1); MBARRIER_INIT(mb[1], 1); }
    __syncthreads();
    uint32_t ph[2] = {0, 0};

    const __half* WhT = g_Wh + (size_t)ntb * WROWS * 128 + (size_t)KSP * 128;  // dyn rows
    const __half* WlT = g_Wl + (size_t)ntb * WROWS * 128 + (size_t)KSP * 128;

    int kra = (lane >> 4) * 8 + (lane & 7);
    int ua0 = ((lane >> 3) & 1) + wm * 4;
    int swa = kra & 7;
    int krb = (lane & 7) + ((lane >> 3) & 1) * 8;
    int ub0 = (lane >> 4) + wn * 8;
    int swb = krb & 7;
    uint32_t aoff0 = (uint32_t)(kra * 256);
    uint32_t boff0 = (uint32_t)(krb * 256);

    float acc[2][8][4];
    float* afl = &acc[0][0][0];
    float c_reg[16];
    #pragma unroll
    for (int i = 0; i < 16; i++) c_reg[i] = 0.f;

    int odd = lane & 1, cpair = (lane >> 1) & 1, r_lane = lane >> 2;

    auto compute_chunk = [&](int stg) {
        uint32_t sb = smb + (uint32_t)stg * STAGE;
        #pragma unroll
        for (int kf = 0; kf < 4; kf++) {
            uint32_t kofs = (uint32_t)(kf * 4096);
            uint32_t ah[2][4], bh[4][4];
            #pragma unroll
            for (int mf = 0; mf < 2; mf++)
                ldsm4t(ah[mf], sb + OFF_A + aoff0 + kofs + (uint32_t)(((ua0 + mf * 2) ^ swa) << 4));
            #pragma unroll
            for (int nf = 0; nf < 4; nf++)
                ldsm4t(bh[nf], sb + OFF_BH + boff0 + kofs + (uint32_t)(((ub0 + nf * 2) ^ swb) << 4));
            #pragma unroll
            for (int mf = 0; mf < 2; mf++)
                #pragma unroll
                for (int nf = 0; nf < 4; nf++) {
                    mma_f16(acc[mf][2 * nf],     ah[mf], bh[nf]);
                    mma_f16(acc[mf][2 * nf + 1], ah[mf], bh[nf] + 2);
                }
            uint32_t bl[4][4];
            #pragma unroll
            for (int nf = 0; nf < 4; nf++)
                ldsm4t(bl[nf], sb + OFF_BL + boff0 + kofs + (uint32_t)(((ub0 + nf * 2) ^ swb) << 4));
            #pragma unroll
            for (int mf = 0; mf < 2; mf++)
                #pragma unroll
                for (int nf = 0; nf < 4; nf++) {
                    mma_f16(acc[mf][2 * nf],     ah[mf], bl[nf]);
                    mma_f16(acc[mf][2 * nf + 1], ah[mf], bl[nf] + 2);
                }
        }
    };

    // epilogue: gates -> c/h; h staged to smem; PROXY FENCE; one bulk S2G by tid0
    auto epilogue = [&](int t, const __half* tv) {
        #pragma unroll
        for (int mf = 0; mf < 2; mf++) {
            int b_local = wm * 32 + mf * 16 + r_lane + (odd ? 8 : 0);
            #pragma unroll
            for (int nt = 0; nt < 8; nt++) {
                float d0 = acc[mf][nt][0], d1 = acc[mf][nt][1];
                float d2 = acc[mf][nt][2], d3 = acc[mf][nt][3];
                float s1 = odd ? d0 : d2;
                float s2 = odd ? d1 : d3;
                float r1 = __shfl_xor_sync(0xffffffffu, s1, 1);
                float r2 = __shfl_xor_sync(0xffffffffu, s2, 1);
                float fi = odd ? r1 : d0;
                float ff = odd ? r2 : d1;
                float fo = odd ? d2 : r1;
                float fg = odd ? d3 : r2;
                int slot = mf * 8 + nt;
                float T = __half2float(tv[slot]);
                float cn = sigmoidf_(ff) * c_reg[slot] + sigmoidf_(fi) * T * tanhf_(fg);
                c_reg[slot] = cn;
                float h = sigmoidf_(fo) * tanhf_(cn);
                int j_local = wn * 16 + nt * 2 + cpair;
                hstage[j_local * 128 + (((b_local >> 3) ^ (j_local & 7)) << 3) + (b_local & 7)]
                    = __float2half(h);
            }
        }
        __syncthreads();
        if (tid == 0) {
            // generic->async proxy fence: TMA must see the STS writes above
            asm volatile("fence.proxy.async.shared::cta;" ::: "memory");
            const __half* gdst = g_Hh + (((size_t)t * 32 + bt) * H + ntb * 32) * 128;
            asm volatile("cp.async.bulk.global.shared::cta.bulk_group [%0], [%1], %2;"
                :: "l"(gdst), "r"(hsb), "r"(8192u) : "memory");
            asm volatile("cp.async.bulk.commit_group;" ::: "memory");
            asm volatile("cp.async.bulk.wait_group 0;" ::: "memory");
        }
    };
    auto arrive = [&](int t) {
        if (tid == 0) {
            asm volatile("membar.gl;" ::: "memory");
            int v = atomicAdd(&g_cnt[gslot], 1);
            if (v == GRP - 1) {
                atomicExch(&g_cnt[gslot], 0);
                __threadfence();
                g_gen[gslot] = t + 1;
            }
        }
    };

    // ---- t = 0: acc = blob[0], no dyn GEMM ----
    {
        uint4 braw[8], traw[2];
        const uint4* bp = (const uint4*)(g_blob + ((size_t)clin * 256 + tid) * 64);
        #pragma unroll
        for (int i = 0; i < 8; i++) braw[i] = bp[i];
        const uint4* tp = (const uint4*)(g_Tf + ((size_t)clin * 256 + tid) * 16);
        traw[0] = tp[0]; traw[1] = tp[1];
        const __half* bh = (const __half*)braw;
        #pragma unroll
        for (int i = 0; i < 64; i++) afl[i] = __half2float(bh[i]);
        epilogue(0, (const __half*)traw);
        arrive(0);
    }

    for (int t = 1; t < SB; t++) {
        const __half* Ad = g_Hh + ((size_t)(t - 1) * 32 + bt) * H * 128;
        // pre-spin: B copies for chunks 0,1 (h-independent); expect covers B now + A later
        if (tid == 0) {
            MBARRIER_EXPECT_TX(mb[0], 49152u);
            bulkcp(smb + OFF_BH, WhT,                      16384, mb[0]);
            bulkcp(smb + OFF_BL, WlT,                      16384, mb[0]);
            MBARRIER_EXPECT_TX(mb[1], 49152u);
            bulkcp(smb + STAGE + OFF_BH, WhT + (size_t)64 * 128, 16384, mb[1]);
            bulkcp(smb + STAGE + OFF_BL, WlT + (size_t)64 * 128, 16384, mb[1]);
        }
        // pre-spin: blob + T loads
        uint4 braw[8], traw[2];
        const uint4* bp = (const uint4*)(g_blob + (((size_t)t * 256 + clin) * 256 + tid) * 64);
        #pragma unroll
        for (int i = 0; i < 8; i++) braw[i] = bp[i];
        const uint4* tp = (const uint4*)(g_Tf + (((size_t)t * 256 + clin) * 256 + tid) * 16);
        traw[0] = tp[0]; traw[1] = tp[1];

        // wait for group to publish h[t-1]
        if (tid == 0) { while (g_gen[gslot] < t) __nanosleep(32); }
        __syncthreads();

        // post-spin: A copies for chunks 0,1
        if (tid == 0) {
            bulkcp(smb + OFF_A,         Ad,                    16384, mb[0]);
            bulkcp(smb + STAGE + OFF_A, Ad + (size_t)64 * 128, 16384, mb[1]);
        }

        const __half* bh = (const __half*)braw;
        #pragma unroll
        for (int i = 0; i < 64; i++) afl[i] = __half2float(bh[i]);

        for (int c = 0; c < 4; c++) {
            int stg = c & 1;
            MBARRIER_WAIT_PARITY(mb[stg], ph[stg]); ph[stg] ^= 1;
            compute_chunk(stg);
            __syncthreads();
            if (c + 2 < 4 && tid == 0) {
                MBARRIER_EXPECT_TX(mb[stg], 49152u);
                uint32_t d = smb + (uint32_t)stg * STAGE;
                bulkcp(d + OFF_A,  Ad  + (size_t)(c + 2) * 64 * 128, 16384, mb[stg]);
                bulkcp(d + OFF_BH, WhT + (size_t)(c + 2) * 64 * 128, 16384, mb[stg]);
                bulkcp(d + OFF_BL, WlT + (size_t)(c + 2) * 64 * 128, 16384, mb[stg]);
            }
        }

        epilogue(t, (const __half*)traw);
        if (t + 1 < SB) arrive(t);
    }
}

// ============================================================
// k_out: output heads; reads swizzled tiled g_Hh
// ============================================================
__global__ void k_out(const float* __restrict__ Wc, const float* __restrict__ bc,
                      const float* __restrict__ Wm, const float* __restrict__ bm,
                      float* __restrict__ out)
{
    __shared__ float sh[256][32];
    __shared__ float sl[32][25];
    int t = blockIdx.x;
    int b0 = blockIdx.y * 32;
    int bt = b0 >> 7;
    int tid = threadIdx.x;

    for (int e = tid; e < 256 * 32; e += 256) {
        int jj = e >> 5, bb = e & 31;
        int b_local = (b0 & 127) + bb;
        int u = b_local >> 3, ee = b_local & 7;
        sh[jj][bb] = __half2float(
            g_Hh[(((size_t)t * 32 + bt) * H + jj) * 128 + (((u ^ (jj & 7)) << 3) + ee)]);
    }
    __syncthreads();

    for (int o = tid; o < 32 * 25; o += 256) {
        int r = o / 25, jx = o % 25;
        float s;
        if (jx < 3) {
            s = bc[jx];
            #pragma unroll 8
            for (int k = 0; k < H; k++) s += sh[k][r] * Wc[k * 3 + jx];
        } else {
            int jj = jx - 3;
            s = bm[jj];
            #pragma unroll 8
            for (int k = 0; k < H; k++) s += sh[k][r] * Wm[k * 22 + jj];
        }
        sl[r][jx] = s;
    }
    __syncthreads();

    float* out_cat = out;
    float* out_val = out + (size_t)SB * B * 3;
    for (int o = tid; o < 32 * 25; o += 256) {
        int r = o / 25, jx = o % 25;
        int b = b0 + r;
        if (jx < 3) {
            float l0 = sl[r][0], l1 = sl[r][1], l2 = sl[r][2];
            float mx = fmaxf(l0, fmaxf(l1, l2));
            float e0 = fexp2_((l0 - mx) * LOG2E);
            float e1 = fexp2_((l1 - mx) * LOG2E);
            float e2 = fexp2_((l2 - mx) * LOG2E);
            float inv = frcp_(e0 + e1 + e2);
            float v = (jx == 0 ? e0 : (jx == 1 ? e1 : e2)) * inv;
            out_cat[(size_t)t * B * 3 + (size_t)b * 3 + jx] = v;
        } else {
            out_val[(size_t)t * B * 22 + (size_t)b * 22 + (jx - 3)] = sl[r][jx];
        }
    }
}

// ============================================================
// launch
// ============================================================
extern "C" void kernel_launch(void* const* d_in, const int* in_sizes, int n_in,
                              void* d_out, int out_size)
{
    const float* val_seq = (const float*)d_in[1];
    const float* delta   = (const float*)d_in[2];
    const float* W_d     = (const float*)d_in[3];
    const float* b_d     = (const float*)d_in[4];
    const float* W_xt    = (const float*)d_in[5];
    const float* W_dt    = (const float*)d_in[6];
    const float* b_t     = (const float*)d_in[7];
    const float* W_x_s   = (const float*)d_in[8];
    const float* b_s     = (const float*)d_in[10];
    const float* W_x_p   = (const float*)d_in[11];
    const float* W_h_p   = (const float*)d_in[12];
    const float* W_s_p   = (const float*)d_in[13];
    const float* b_p     = (const float*)d_in[14];
    const float* Wc      = (const float*)d_in[15];
    const float* bcv     = (const float*)d_in[16];
    const float* Wm      = (const float*)d_in[17];
    const float* bm      = (const float*)d_in[18];
    float* out = (float*)d_out;

    cudaFuncSetAttribute(k_static, cudaFuncAttributeMaxDynamicSharedMemorySize, SMEM_TOTAL);
    cudaFuncSetAttribute(k_seq,    cudaFuncAttributeMaxDynamicSharedMemorySize, SMEM_TOTAL);

    k_packw<<<(8 * WROWS * 128 + 255) / 256, 256>>>(W_x_p, W_h_p, W_s_p, b_p);
    k_pre<<<dim3(SB, B / 64), 256>>>(val_seq, delta, W_d, b_d, W_xt, W_dt, b_t, W_x_s, b_s);
    k_static<<<dim3(256, SB), 256, SMEM_TOTAL>>>();
    k_seq<<<NCTA, 256, SMEM_TOTAL>>>();
    k_out<<<dim3(SB, B / 32), 256>>>(Wc, bcv, Wm, bm, out);
}

// round 14
// speedup vs baseline: 5.5617x; 1.1012x over previous
#include <cuda_runtime.h>
#include <cuda_fp16.h>
#include <math.h>
#include <stdint.h>

#define S    256
#define SB   255
#define B    4096
#define H    256
#define MM   20
#define G4   1024
#define KSP  320        // static K padded to 5*64 (rows 277..319 zero)
#define WROWS 576       // 320 static + 256 dyn
#define NCTA 256
#define NGRP 32
#define GRP  8

// ---------------- scratch (static device globals; total ~3.88GB, < ~4GB aarch64 adrp limit) ----------------
__device__ __align__(256) __half g_Tf  [(size_t)SB*256*256*16];   // [t][tile][tid][slot] frag layout
__device__ __align__(256) __half g_blob[(size_t)SB*256*256*64];   // static pre, frag layout fp16
__device__ __align__(256) __half g_Ah[(size_t)SB*32*KSP*128];     // [t][bt][k][128 swz]
__device__ __align__(256) __half g_Hh[(size_t)SB*32*H*128];       // [t][bt][j][128 swz]
__device__ __align__(256) __half g_Wh[(size_t)8*WROWS*128];       // [ntb][k][128 swz]
__device__ __align__(256) __half g_Wl[(size_t)8*WROWS*128];
__device__ __align__(256) int g_cnt[NGRP * 32];
__device__ __align__(256) volatile int g_gen[NGRP * 32];

// ---- fast-but-accurate transcendentals (MUFU EX2 + RCP; ~1e-6 rel err) ----
__device__ __forceinline__ float fexp2_(float x) {
    float r; asm("ex2.approx.ftz.f32 %0, %1;" : "=f"(r) : "f"(x)); return r;
}
__device__ __forceinline__ float frcp_(float x) {
    float r; asm("rcp.approx.ftz.f32 %0, %1;" : "=f"(r) : "f"(x)); return r;
}
#define LOG2E 1.4426950408889634f
__device__ __forceinline__ float sigmoidf_(float x) {
    return frcp_(1.f + fexp2_(-x * LOG2E));
}
__device__ __forceinline__ float tanhf_(float x) {
    return 1.f - 2.f * frcp_(1.f + fexp2_(2.f * x * LOG2E));
}

__device__ __forceinline__ uint32_t smem_u32(const void* p) {
    uint32_t a;
    asm("{ .reg .u64 t; cvta.to.shared.u64 t, %1; cvt.u32.u64 %0, t; }" : "=r"(a) : "l"(p));
    return a;
}
__device__ __forceinline__ void ldsm4t(uint32_t* r, uint32_t addr) {
    asm volatile("ldmatrix.sync.aligned.m8n8.x4.trans.shared.b16 {%0,%1,%2,%3}, [%4];"
        : "=r"(r[0]), "=r"(r[1]), "=r"(r[2]), "=r"(r[3]) : "r"(addr));
}
__device__ __forceinline__ void mma_f16(float* d, const uint32_t* a, const uint32_t* b) {
    asm volatile("mma.sync.aligned.m16n8k16.row.col.f32.f16.f16.f32 "
        "{%0,%1,%2,%3}, {%4,%5,%6,%7}, {%8,%9}, {%0,%1,%2,%3};"
        : "+f"(d[0]), "+f"(d[1]), "+f"(d[2]), "+f"(d[3])
        : "r"(a[0]), "r"(a[1]), "r"(a[2]), "r"(a[3]), "r"(b[0]), "r"(b[1]));
}
__device__ __forceinline__ void bulkcp(uint32_t dst, const void* src, uint32_t n, uint32_t mbar) {
    asm volatile("cp.async.bulk.shared::cta.global.mbarrier::complete_tx::bytes [%0], [%1], %2, [%3];"
        :: "r"(dst), "l"(src), "r"(n), "r"(mbar) : "memory");
}
#define MBARRIER_INIT(a, c) \
    asm volatile("mbarrier.init.shared.b64 [%0], %1;" :: "r"((uint32_t)(a)), "r"((uint32_t)(c)) : "memory")
#define MBARRIER_EXPECT_TX(a, n) \
    asm volatile("mbarrier.arrive.expect_tx.shared.b64 _, [%0], %1;" :: "r"((uint32_t)(a)), "r"((uint32_t)(n)) : "memory")
#define MBARRIER_WAIT_PARITY(a, ph) do { \
    uint32_t _m = (uint32_t)(a), _p = (uint32_t)(ph), _d; \
    asm volatile("{\n\t.reg .pred p;\n\t" \
        "mbarrier.try_wait.parity.acquire.cta.shared::cta.b64 p, [%1], %2;\n\t" \
        "selp.b32 %0, 1, 0, p;\n\t}" : "=r"(_d) : "r"(_m), "r"(_p) : "memory"); \
    if (!_d) { \
        asm volatile("{\n\t.reg .pred P1;\n\t" \
            "WL_%=:\n\t" \
            "mbarrier.try_wait.parity.acquire.cta.shared::cta.b64 P1, [%0], %1, 0x989680;\n\t" \
            "@P1 bra.uni WD_%=;\n\t" \
            "bra.uni WL_%=;\n\t" \
            "WD_%=:\n\t}" :: "r"(_m), "r"(_p) : "memory"); \
    } \
} while (0)

// k_static stage: A 16K + Bh 16K + Bl 16K
#define OFF_A  0
#define OFF_BH 16384
#define OFF_BL 32768
#define STA_STAGE 49152
#define STA_SMEM (2 * STA_STAGE)    // 98304
// k_seq stage: A 16K + Bh 16K (single-pass dyn), 3-stage ring
#define SEQ_STAGE 32768
#define SEQ_NSTG  3
#define SEQ_SMEM  (SEQ_NSTG * SEQ_STAGE)  // 98304

// ============================================================
// k_packw: weights -> [ntb][k][128 swz] fp16 hi/lo; resets group barriers.
// ============================================================
__global__ void k_packw(const float* __restrict__ W_x_p, const float* __restrict__ W_h_p,
                        const float* __restrict__ W_s_p, const float* __restrict__ b_p)
{
    int idx = blockIdx.x * blockDim.x + threadIdx.x;
    if (idx < NGRP * 32) { g_cnt[idx] = 0; g_gen[idx] = 0; }
    if (idx >= 8 * WROWS * 128) return;
    int tile = idx / (WROWS * 128);
    int rem  = idx % (WROWS * 128);
    int k    = rem >> 7;
    int col  = rem & 127;
    int np = tile * 128 + col;
    int j = np >> 2, g = np & 3;
    int scol = g * H + j;
    float v;
    if (k < MM)            v = W_x_p[(size_t)k * G4 + scol];
    else if (k < MM + H)   v = W_s_p[(size_t)(k - MM) * G4 + scol];
    else if (k == 276)     v = b_p[scol];
    else if (k < KSP)      v = 0.f;
    else                   v = W_h_p[(size_t)(k - KSP) * G4 + scol];
    int u = col >> 3, e = col & 7;
    size_t dst = ((size_t)tile * WROWS + k) * 128 + (((u ^ (k & 7)) << 3) + e);
    __half hv = __float2half(v);
    g_Wh[dst] = hv;
    g_Wl[dst] = __float2half(v - __half2float(hv));
}

// ============================================================
// k_pre: T into frag layout g_Tf; static A rows into swizzled tiled g_Ah
// grid (SB, B/64), block 256
// ============================================================
__global__ void k_pre(const float* __restrict__ val_seq, const float* __restrict__ delta,
                      const float* __restrict__ W_d,  const float* __restrict__ b_d,
                      const float* __restrict__ W_xt, const float* __restrict__ W_dt,
                      const float* __restrict__ b_t,
                      const float* __restrict__ W_x_s, const float* __restrict__ b_s)
{
    __shared__ float sx[64][20];
    __shared__ float sde[64][32];
    __shared__ float sT[256][16];
    __shared__ float sH[256][16];
    int t = blockIdx.x;
    int b0 = blockIdx.y * 64;
    int bt = b0 >> 7;
    int tid = threadIdx.x;
    size_t abase = ((size_t)t * 32 + bt) * KSP * 128;

    for (int e = tid; e < 64 * 20; e += 256) {
        int b = e / 20, k = e % 20;
        sx[b][k] = val_seq[((size_t)t * B + b0 + b) * MM + k];
    }
    for (int e = tid; e < 64 * 32; e += 256) {
        int b = e >> 5, ee = e & 31;
        float dd = delta[(size_t)t * B + b0 + b];
        sde[b][ee] = tanhf_(dd * W_d[ee] + b_d[ee]);
    }
    __syncthreads();

    int j = tid;
    float wxt[20], wdt[32], wi[20], wo[20], wg[20];
    #pragma unroll
    for (int k = 0; k < 20; k++) wxt[k] = W_xt[k * H + j];
    #pragma unroll
    for (int e = 0; e < 32; e++) wdt[e] = W_dt[e * H + j];
    #pragma unroll
    for (int k = 0; k < 20; k++) {
        wi[k] = W_x_s[k * G4 + j];
        wo[k] = W_x_s[k * G4 + 2 * H + j];
        wg[k] = W_x_s[k * G4 + 3 * H + j];
    }
    float bt_ = b_t[j], bi = b_s[j], bo = b_s[2 * H + j], bg = b_s[3 * H + j];

    for (int bc = 0; bc < 4; bc++) {
        #pragma unroll 1
        for (int bl = 0; bl < 16; bl++) {
            int b = bc * 16 + bl;
            float tx = bt_, td = 0.f, ai = bi, ao = bo, ag = bg;
            #pragma unroll
            for (int k = 0; k < 20; k++) {
                float xv = sx[b][k];
                tx += xv * wxt[k]; ai += xv * wi[k]; ao += xv * wo[k]; ag += xv * wg[k];
            }
            #pragma unroll
            for (int e = 0; e < 32; e++) td += sde[b][e] * wdt[e];
            float T = sigmoidf_(tx + sigmoidf_(td));
            float cns = sigmoidf_(ai) * T * tanhf_(ag);
            sT[j][bl] = T;
            sH[j][bl] = sigmoidf_(ao) * tanhf_(cns);
        }
        __syncthreads();
        for (int e = tid; e < 256 * 16; e += 256) {
            int jj = e >> 4, bl = e & 15;
            int b_local = (b0 & 127) + bc * 16 + bl;
            {
                int tile = bt * 8 + (jj >> 5);
                int wn = (jj >> 4) & 1, j_in = jj & 15, nt = j_in >> 1, cpair = j_in & 1;
                int wm = b_local >> 5, r = b_local & 31;
                int mf = r >> 4, oddb = (r >> 3) & 1, r_lane = r & 7;
                int tidt = ((wn << 2) | wm) * 32 + (oddb | (cpair << 1) | (r_lane << 2));
                int slot = mf * 8 + nt;
                g_Tf[(((size_t)t * 256 + tile) * 256 + tidt) * 16 + slot] = __float2half(sT[jj][bl]);
            }
            int k = 20 + jj;
            int u = b_local >> 3, ee = b_local & 7;
            g_Ah[abase + (size_t)k * 128 + (((u ^ (k & 7)) << 3) + ee)] = __float2half(sH[jj][bl]);
        }
        for (int e = tid; e < 20 * 16; e += 256) {
            int k = e >> 4, bl = e & 15;
            int b_local = (b0 & 127) + bc * 16 + bl;
            int u = b_local >> 3, ee = b_local & 7;
            g_Ah[abase + (size_t)k * 128 + (((u ^ (k & 7)) << 3) + ee)] = __float2half(sx[bc * 16 + bl][k]);
        }
        __syncthreads();
    }
    if (tid < 64) {
        int b_local = (b0 & 127) + tid;
        int u = b_local >> 3, ee = b_local & 7;
        g_Ah[abase + (size_t)276 * 128 + (((u ^ 4) << 3) + ee)] = __float2half(1.f);
    }
}

// ============================================================
// k_static: parallel static-pre GEMM for ALL steps (2-pass fp16, off critical path).
// ============================================================
__global__ void __launch_bounds__(256, 2) k_static()
{
    extern __shared__ __align__(16) char sm[];
    __shared__ __align__(8) unsigned long long mbar[2];
    int tile = blockIdx.x, t = blockIdx.y;
    int bt = tile >> 3, ntb = tile & 7;
    int tid = threadIdx.x, lane = tid & 31, wid = tid >> 5;
    int wm = wid & 3, wn = wid >> 2;
    uint32_t smb = smem_u32(sm);
    uint32_t mb[2] = { smem_u32(&mbar[0]), smem_u32(&mbar[1]) };
    if (tid == 0) { MBARRIER_INIT(mb[0], 1); MBARRIER_INIT(mb[1], 1); }
    __syncthreads();
    uint32_t ph[2] = {0, 0};

    const __half* A0  = g_Ah + ((size_t)t * 32 + bt) * KSP * 128;
    const __half* WhT = g_Wh + (size_t)ntb * WROWS * 128;
    const __half* WlT = g_Wl + (size_t)ntb * WROWS * 128;

    int kra = (lane >> 4) * 8 + (lane & 7);
    int ua0 = ((lane >> 3) & 1) + wm * 4;
    int swa = kra & 7;
    int krb = (lane & 7) + ((lane >> 3) & 1) * 8;
    int ub0 = (lane >> 4) + wn * 8;
    int swb = krb & 7;
    uint32_t aoff0 = (uint32_t)(kra * 256);
    uint32_t boff0 = (uint32_t)(krb * 256);

    float acc[2][8][4];
    float* afl = &acc[0][0][0];
    #pragma unroll
    for (int i = 0; i < 64; i++) afl[i] = 0.f;

    auto issue = [&](int stg, int c) {
        if (tid == 0) {
            MBARRIER_EXPECT_TX(mb[stg], 49152u);
            uint32_t d = smb + (uint32_t)stg * STA_STAGE;
            bulkcp(d + OFF_A,  A0  + (size_t)c * 64 * 128, 16384, mb[stg]);
            bulkcp(d + OFF_BH, WhT + (size_t)c * 64 * 128, 16384, mb[stg]);
            bulkcp(d + OFF_BL, WlT + (size_t)c * 64 * 128, 16384, mb[stg]);
        }
    };
    issue(0, 0); issue(1, 1);

    for (int c = 0; c < 5; c++) {
        int stg = c & 1;
        MBARRIER_WAIT_PARITY(mb[stg], ph[stg]); ph[stg] ^= 1;
        uint32_t sb = smb + (uint32_t)stg * STA_STAGE;
        #pragma unroll
        for (int kf = 0; kf < 4; kf++) {
            uint32_t kofs = (uint32_t)(kf * 4096);
            uint32_t ah[2][4], bh[4][4];
            #pragma unroll
            for (int mf = 0; mf < 2; mf++)
                ldsm4t(ah[mf], sb + OFF_A + aoff0 + kofs + (uint32_t)(((ua0 + mf * 2) ^ swa) << 4));
            #pragma unroll
            for (int nf = 0; nf < 4; nf++)
                ldsm4t(bh[nf], sb + OFF_BH + boff0 + kofs + (uint32_t)(((ub0 + nf * 2) ^ swb) << 4));
            #pragma unroll
            for (int mf = 0; mf < 2; mf++)
                #pragma unroll
                for (int nf = 0; nf < 4; nf++) {
                    mma_f16(acc[mf][2 * nf],     ah[mf], bh[nf]);
                    mma_f16(acc[mf][2 * nf + 1], ah[mf], bh[nf] + 2);
                }
            uint32_t bl[4][4];
            #pragma unroll
            for (int nf = 0; nf < 4; nf++)
                ldsm4t(bl[nf], sb + OFF_BL + boff0 + kofs + (uint32_t)(((ub0 + nf * 2) ^ swb) << 4));
            #pragma unroll
            for (int mf = 0; mf < 2; mf++)
                #pragma unroll
                for (int nf = 0; nf < 4; nf++) {
                    mma_f16(acc[mf][2 * nf],     ah[mf], bl[nf]);
                    mma_f16(acc[mf][2 * nf + 1], ah[mf], bl[nf] + 2);
                }
        }
        __syncthreads();
        if (c + 2 < 5) issue(stg, c + 2);
    }

    __half hb[64];
    #pragma unroll
    for (int i = 0; i < 64; i++) hb[i] = __float2half(afl[i]);
    uint4* bp = (uint4*)(g_blob + (((size_t)t * 256 + tile) * 256 + tid) * 64);
    #pragma unroll
    for (int i = 0; i < 8; i++) bp[i] = ((const uint4*)hb)[i];
}

// ============================================================
// k_seq: persistent recurrence, SINGLE-PASS fp16 dyn GEMM, 3-stage ring.
// 256 CTAs (2/SM). acc init from blob; T frag; c in registers.
// Epilogue h staged in smem -> proxy fence -> one 8KB bulk S2G by tid0.
// ============================================================
__global__ void __launch_bounds__(256, 2) k_seq()
{
    extern __shared__ __align__(16) char sm[];
    __shared__ __align__(8) unsigned long long mbar[SEQ_NSTG];
    __shared__ __align__(16) __half hstage[32 * 128];   // 8KB h staging
    int clin = blockIdx.x;
    int bt = clin >> 3, ntb = clin & 7;
    int gslot = bt * 32;
    int tid = threadIdx.x, lane = tid & 31, wid = tid >> 5;
    int wm = wid & 3, wn = wid >> 2;
    uint32_t smb = smem_u32(sm);
    uint32_t hsb = smem_u32(hstage);
    uint32_t mb[SEQ_NSTG];
    #pragma unroll
    for (int i = 0; i < SEQ_NSTG; i++) mb[i] = smem_u32(&mbar[i]);
    if (tid == 0) {
        #pragma unroll
        for (int i = 0; i < SEQ_NSTG; i++) MBARRIER_INIT(mb[i], 1);
    }
    __syncthreads();
    uint32_t ph[SEQ_NSTG] = {0, 0, 0};

    const __half* WhT = g_Wh + (size_t)ntb * WROWS * 128 + (size_t)KSP * 128;  // dyn rows

    int kra = (lane >> 4) * 8 + (lane & 7);
    int ua0 = ((lane >> 3) & 1) + wm * 4;
    int swa = kra & 7;
    int krb = (lane & 7) + ((lane >> 3) & 1) * 8;
    int ub0 = (lane >> 4) + wn * 8;
    int swb = krb & 7;
    uint32_t aoff0 = (uint32_t)(kra * 256);
    uint32_t boff0 = (uint32_t)(krb * 256);

    float acc[2][8][4];
    float* afl = &acc[0][0][0];
    float c_reg[16];
    #pragma unroll
    for (int i = 0; i < 16; i++) c_reg[i] = 0.f;

    int odd = lane & 1, cpair = (lane >> 1) & 1, r_lane = lane >> 2;

    auto compute_chunk = [&](int stg) {
        uint32_t sb = smb + (uint32_t)stg * SEQ_STAGE;
        #pragma unroll
        for (int kf = 0; kf < 4; kf++) {
            uint32_t kofs = (uint32_t)(kf * 4096);
            uint32_t ah[2][4], bh[4][4];
            #pragma unroll
            for (int mf = 0; mf < 2; mf++)
                ldsm4t(ah[mf], sb + OFF_A + aoff0 + kofs + (uint32_t)(((ua0 + mf * 2) ^ swa) << 4));
            #pragma unroll
            for (int nf = 0; nf < 4; nf++)
                ldsm4t(bh[nf], sb + OFF_BH + boff0 + kofs + (uint32_t)(((ub0 + nf * 2) ^ swb) << 4));
            #pragma unroll
            for (int mf = 0; mf < 2; mf++)
                #pragma unroll
                for (int nf = 0; nf < 4; nf++) {
                    mma_f16(acc[mf][2 * nf],     ah[mf], bh[nf]);
                    mma_f16(acc[mf][2 * nf + 1], ah[mf], bh[nf] + 2);
                }
        }
    };

    // epilogue: gates -> c/h; h staged to smem; PROXY FENCE; one bulk S2G by tid0
    auto epilogue = [&](int t, const __half* tv) {
        #pragma unroll
        for (int mf = 0; mf < 2; mf++) {
            int b_local = wm * 32 + mf * 16 + r_lane + (odd ? 8 : 0);
            #pragma unroll
            for (int nt = 0; nt < 8; nt++) {
                float d0 = acc[mf][nt][0], d1 = acc[mf][nt][1];
                float d2 = acc[mf][nt][2], d3 = acc[mf][nt][3];
                float s1 = odd ? d0 : d2;
                float s2 = odd ? d1 : d3;
                float r1 = __shfl_xor_sync(0xffffffffu, s1, 1);
                float r2 = __shfl_xor_sync(0xffffffffu, s2, 1);
                float fi = odd ? r1 : d0;
                float ff = odd ? r2 : d1;
                float fo = odd ? d2 : r1;
                float fg = odd ? d3 : r2;
                int slot = mf * 8 + nt;
                float T = __half2float(tv[slot]);
                float cn = sigmoidf_(ff) * c_reg[slot] + sigmoidf_(fi) * T * tanhf_(fg);
                c_reg[slot] = cn;
                float h = sigmoidf_(fo) * tanhf_(cn);
                int j_local = wn * 16 + nt * 2 + cpair;
                hstage[j_local * 128 + (((b_local >> 3) ^ (j_local & 7)) << 3) + (b_local & 7)]
                    = __float2half(h);
            }
        }
        __syncthreads();
        if (tid == 0) {
            asm volatile("fence.proxy.async.shared::cta;" ::: "memory");
            const __half* gdst = g_Hh + (((size_t)t * 32 + bt) * H + ntb * 32) * 128;
            asm volatile("cp.async.bulk.global.shared::cta.bulk_group [%0], [%1], %2;"
                :: "l"(gdst), "r"(hsb), "r"(8192u) : "memory");
            asm volatile("cp.async.bulk.commit_group;" ::: "memory");
            asm volatile("cp.async.bulk.wait_group 0;" ::: "memory");
        }
    };
    auto arrive = [&](int t) {
        if (tid == 0) {
            asm volatile("membar.gl;" ::: "memory");
            int v = atomicAdd(&g_cnt[gslot], 1);
            if (v == GRP - 1) {
                atomicExch(&g_cnt[gslot], 0);
                __threadfence();
                g_gen[gslot] = t + 1;
            }
        }
    };

    // ---- t = 0: acc = blob[0], no dyn GEMM ----
    {
        uint4 braw[8], traw[2];
        const uint4* bp = (const uint4*)(g_blob + ((size_t)clin * 256 + tid) * 64);
        #pragma unroll
        for (int i = 0; i < 8; i++) braw[i] = bp[i];
        const uint4* tp = (const uint4*)(g_Tf + ((size_t)clin * 256 + tid) * 16);
        traw[0] = tp[0]; traw[1] = tp[1];
        const __half* bh = (const __half*)braw;
        #pragma unroll
        for (int i = 0; i < 64; i++) afl[i] = __half2float(bh[i]);
        epilogue(0, (const __half*)traw);
        arrive(0);
    }

    for (int t = 1; t < SB; t++) {
        const __half* Ad = g_Hh + ((size_t)(t - 1) * 32 + bt) * H * 128;
        // pre-spin: B copies for chunks 0..2 (h-independent); expect covers B now + A later
        if (tid == 0) {
            #pragma unroll
            for (int s = 0; s < 3; s++) {
                MBARRIER_EXPECT_TX(mb[s], 32768u);
                bulkcp(smb + (uint32_t)s * SEQ_STAGE + OFF_BH,
                       WhT + (size_t)s * 64 * 128, 16384, mb[s]);
            }
        }
        // pre-spin: blob + T loads
        uint4 braw[8], traw[2];
        const uint4* bp = (const uint4*)(g_blob + (((size_t)t * 256 + clin) * 256 + tid) * 64);
        #pragma unroll
        for (int i = 0; i < 8; i++) braw[i] = bp[i];
        const uint4* tp = (const uint4*)(g_Tf + (((size_t)t * 256 + clin) * 256 + tid) * 16);
        traw[0] = tp[0]; traw[1] = tp[1];

        // wait for group to publish h[t-1]
        if (tid == 0) { while (g_gen[gslot] < t) __nanosleep(32); }
        __syncthreads();

        // post-spin: A copies for chunks 0..2
        if (tid == 0) {
            #pragma unroll
            for (int s = 0; s < 3; s++)
                bulkcp(smb + (uint32_t)s * SEQ_STAGE + OFF_A,
                       Ad + (size_t)s * 64 * 128, 16384, mb[s]);
        }

        const __half* bh = (const __half*)braw;
        #pragma unroll
        for (int i = 0; i < 64; i++) afl[i] = __half2float(bh[i]);

        for (int c = 0; c < 4; c++) {
            int stg = c % SEQ_NSTG;
            MBARRIER_WAIT_PARITY(mb[stg], ph[stg]); ph[stg] ^= 1;
            compute_chunk(stg);
            __syncthreads();
            if (c + SEQ_NSTG < 4 && tid == 0) {   // only c==0 -> chunk 3 into stage 0
                MBARRIER_EXPECT_TX(mb[stg], 32768u);
                uint32_t d = smb + (uint32_t)stg * SEQ_STAGE;
                bulkcp(d + OFF_A,  Ad  + (size_t)(c + SEQ_NSTG) * 64 * 128, 16384, mb[stg]);
                bulkcp(d + OFF_BH, WhT + (size_t)(c + SEQ_NSTG) * 64 * 128, 16384, mb[stg]);
            }
        }

        epilogue(t, (const __half*)traw);
        if (t + 1 < SB) arrive(t);
    }
}

// ============================================================
// k_out: output heads; reads swizzled tiled g_Hh
// ============================================================
__global__ void k_out(const float* __restrict__ Wc, const float* __restrict__ bc,
                      const float* __restrict__ Wm, const float* __restrict__ bm,
                      float* __restrict__ out)
{
    __shared__ float sh[256][32];
    __shared__ float sl[32][25];
    int t = blockIdx.x;
    int b0 = blockIdx.y * 32;
    int bt = b0 >> 7;
    int tid = threadIdx.x;

    for (int e = tid; e < 256 * 32; e += 256) {
        int jj = e >> 5, bb = e & 31;
        int b_local = (b0 & 127) + bb;
        int u = b_local >> 3, ee = b_local & 7;
        sh[jj][bb] = __half2float(
            g_Hh[(((size_t)t * 32 + bt) * H + jj) * 128 + (((u ^ (jj & 7)) << 3) + ee)]);
    }
    __syncthreads();

    for (int o = tid; o < 32 * 25; o += 256) {
        int r = o / 25, jx = o % 25;
        float s;
        if (jx < 3) {
            s = bc[jx];
            #pragma unroll 8
            for (int k = 0; k < H; k++) s += sh[k][r] * Wc[k * 3 + jx];
        } else {
            int jj = jx - 3;
            s = bm[jj];
            #pragma unroll 8
            for (int k = 0; k < H; k++) s += sh[k][r] * Wm[k * 22 + jj];
        }
        sl[r][jx] = s;
    }
    __syncthreads();

    float* out_cat = out;
    float* out_val = out + (size_t)SB * B * 3;
    for (int o = tid; o < 32 * 25; o += 256) {
        int r = o / 25, jx = o % 25;
        int b = b0 + r;
        if (jx < 3) {
            float l0 = sl[r][0], l1 = sl[r][1], l2 = sl[r][2];
            float mx = fmaxf(l0, fmaxf(l1, l2));
            float e0 = fexp2_((l0 - mx) * LOG2E);
            float e1 = fexp2_((l1 - mx) * LOG2E);
            float e2 = fexp2_((l2 - mx) * LOG2E);
            float inv = frcp_(e0 + e1 + e2);
            float v = (jx == 0 ? e0 : (jx == 1 ? e1 : e2)) * inv;
            out_cat[(size_t)t * B * 3 + (size_t)b * 3 + jx] = v;
        } else {
            out_val[(size_t)t * B * 22 + (size_t)b * 22 + (jx - 3)] = sl[r][jx];
        }
    }
}

// ============================================================
// launch
// ============================================================
extern "C" void kernel_launch(void* const* d_in, const int* in_sizes, int n_in,
                              void* d_out, int out_size)
{
    const float* val_seq = (const float*)d_in[1];
    const float* delta   = (const float*)d_in[2];
    const float* W_d     = (const float*)d_in[3];
    const float* b_d     = (const float*)d_in[4];
    const float* W_xt    = (const float*)d_in[5];
    const float* W_dt    = (const float*)d_in[6];
    const float* b_t     = (const float*)d_in[7];
    const float* W_x_s   = (const float*)d_in[8];
    const float* b_s     = (const float*)d_in[10];
    const float* W_x_p   = (const float*)d_in[11];
    const float* W_h_p   = (const float*)d_in[12];
    const float* W_s_p   = (const float*)d_in[13];
    const float* b_p     = (const float*)d_in[14];
    const float* Wc      = (const float*)d_in[15];
    const float* bcv     = (const float*)d_in[16];
    const float* Wm      = (const float*)d_in[17];
    const float* bm      = (const float*)d_in[18];
    float* out = (float*)d_out;

    cudaFuncSetAttribute(k_static, cudaFuncAttributeMaxDynamicSharedMemorySize, STA_SMEM);
    cudaFuncSetAttribute(k_seq,    cudaFuncAttributeMaxDynamicSharedMemorySize, SEQ_SMEM);

    k_packw<<<(8 * WROWS * 128 + 255) / 256, 256>>>(W_x_p, W_h_p, W_s_p, b_p);
    k_pre<<<dim3(SB, B / 64), 256>>>(val_seq, delta, W_d, b_d, W_xt, W_dt, b_t, W_x_s, b_s);
    k_static<<<dim3(256, SB), 256, STA_SMEM>>>();
    k_seq<<<NCTA, 256, SEQ_SMEM>>>();
    k_out<<<dim3(SB, B / 32), 256>>>(Wc, bcv, Wm, bm, out);
}

// round 15
// speedup vs baseline: 6.2986x; 1.1325x over previous
#include <cuda_runtime.h>
#include <cuda_fp16.h>
#include <math.h>
#include <stdint.h>

#define S    256
#define SB   255
#define B    4096
#define H    256
#define MM   20
#define G4   1024
#define KSP  320        // static K padded to 5*64 (rows 277..319 zero)
#define WROWS 576       // 320 static + 256 dyn
#define NCTA 256
#define NGRP 32
#define GRP  8

// ---------------- scratch (static device globals; total ~1.74GB) ----------------
__device__ __align__(256) __half g_Tf[(size_t)SB*256*256*16];   // [t][tile][tid][slot] frag layout
__device__ __align__(256) __half g_Ah[(size_t)SB*32*KSP*128];   // [t][bt][k][128 swz]
__device__ __align__(256) __half g_Hh[(size_t)SB*32*H*128];     // [t][bt][j][128 swz]
__device__ __align__(256) __half g_Wh[(size_t)8*WROWS*128];     // [ntb][k][128 swz]
__device__ __align__(256) int g_cnt[NGRP * 32];
__device__ __align__(256) volatile int g_gen[NGRP * 32];

// ---- fast-but-accurate transcendentals (MUFU EX2 + RCP; ~1e-6 rel err) ----
__device__ __forceinline__ float fexp2_(float x) {
    float r; asm("ex2.approx.ftz.f32 %0, %1;" : "=f"(r) : "f"(x)); return r;
}
__device__ __forceinline__ float frcp_(float x) {
    float r; asm("rcp.approx.ftz.f32 %0, %1;" : "=f"(r) : "f"(x)); return r;
}
#define LOG2E 1.4426950408889634f
__device__ __forceinline__ float sigmoidf_(float x) {
    return frcp_(1.f + fexp2_(-x * LOG2E));
}
__device__ __forceinline__ float tanhf_(float x) {
    return 1.f - 2.f * frcp_(1.f + fexp2_(2.f * x * LOG2E));
}

__device__ __forceinline__ uint32_t smem_u32(const void* p) {
    uint32_t a;
    asm("{ .reg .u64 t; cvta.to.shared.u64 t, %1; cvt.u32.u64 %0, t; }" : "=r"(a) : "l"(p));
    return a;
}
__device__ __forceinline__ void ldsm4t(uint32_t* r, uint32_t addr) {
    asm volatile("ldmatrix.sync.aligned.m8n8.x4.trans.shared.b16 {%0,%1,%2,%3}, [%4];"
        : "=r"(r[0]), "=r"(r[1]), "=r"(r[2]), "=r"(r[3]) : "r"(addr));
}
__device__ __forceinline__ void mma_f16(float* d, const uint32_t* a, const uint32_t* b) {
    asm volatile("mma.sync.aligned.m16n8k16.row.col.f32.f16.f16.f32 "
        "{%0,%1,%2,%3}, {%4,%5,%6,%7}, {%8,%9}, {%0,%1,%2,%3};"
        : "+f"(d[0]), "+f"(d[1]), "+f"(d[2]), "+f"(d[3])
        : "r"(a[0]), "r"(a[1]), "r"(a[2]), "r"(a[3]), "r"(b[0]), "r"(b[1]));
}
__device__ __forceinline__ void bulkcp(uint32_t dst, const void* src, uint32_t n, uint32_t mbar) {
    asm volatile("cp.async.bulk.shared::cta.global.mbarrier::complete_tx::bytes [%0], [%1], %2, [%3];"
        :: "r"(dst), "l"(src), "r"(n), "r"(mbar) : "memory");
}
#define MBARRIER_INIT(a, c) \
    asm volatile("mbarrier.init.shared.b64 [%0], %1;" :: "r"((uint32_t)(a)), "r"((uint32_t)(c)) : "memory")
#define MBARRIER_EXPECT_TX(a, n) \
    asm volatile("mbarrier.arrive.expect_tx.shared.b64 _, [%0], %1;" :: "r"((uint32_t)(a)), "r"((uint32_t)(n)) : "memory")
#define MBARRIER_WAIT_PARITY(a, ph) do { \
    uint32_t _m = (uint32_t)(a), _p = (uint32_t)(ph), _d; \
    asm volatile("{\n\t.reg .pred p;\n\t" \
        "mbarrier.try_wait.parity.acquire.cta.shared::cta.b64 p, [%1], %2;\n\t" \
        "selp.b32 %0, 1, 0, p;\n\t}" : "=r"(_d) : "r"(_m), "r"(_p) : "memory"); \
    if (!_d) { \
        asm volatile("{\n\t.reg .pred P1;\n\t" \
            "WL_%=:\n\t" \
            "mbarrier.try_wait.parity.acquire.cta.shared::cta.b64 P1, [%0], %1, 0x989680;\n\t" \
            "@P1 bra.uni WD_%=;\n\t" \
            "bra.uni WL_%=;\n\t" \
            "WD_%=:\n\t}" :: "r"(_m), "r"(_p) : "memory"); \
    } \
} while (0)

// k_seq stage: A 16K + Bh 16K, 3-stage ring
#define OFF_A  0
#define OFF_BH 16384
#define SEQ_STAGE 32768
#define SEQ_NSTG  3
#define SEQ_SMEM  (SEQ_NSTG * SEQ_STAGE)  // 98304

// ============================================================
// k_packw: weights -> [ntb][k][128 swz] fp16; resets group barriers.
// rows: 0-19 W_x_p | 20-275 W_s_p | 276 bias | 277-319 zero | 320-575 W_h_p
// ============================================================
__global__ void k_packw(const float* __restrict__ W_x_p, const float* __restrict__ W_h_p,
                        const float* __restrict__ W_s_p, const float* __restrict__ b_p)
{
    int idx = blockIdx.x * blockDim.x + threadIdx.x;
    if (idx < NGRP * 32) { g_cnt[idx] = 0; g_gen[idx] = 0; }
    if (idx >= 8 * WROWS * 128) return;
    int tile = idx / (WROWS * 128);
    int rem  = idx % (WROWS * 128);
    int k    = rem >> 7;
    int col  = rem & 127;
    int np = tile * 128 + col;
    int j = np >> 2, g = np & 3;
    int scol = g * H + j;
    float v;
    if (k < MM)            v = W_x_p[(size_t)k * G4 + scol];
    else if (k < MM + H)   v = W_s_p[(size_t)(k - MM) * G4 + scol];
    else if (k == 276)     v = b_p[scol];
    else if (k < KSP)      v = 0.f;
    else                   v = W_h_p[(size_t)(k - KSP) * G4 + scol];
    int u = col >> 3, e = col & 7;
    g_Wh[((size_t)tile * WROWS + k) * 128 + (((u ^ (k & 7)) << 3) + e)] = __float2half(v);
}

// ============================================================
// k_pre: T into frag layout g_Tf; static A rows into swizzled tiled g_Ah
// grid (SB, B/64), block 256
// ============================================================
__global__ void k_pre(const float* __restrict__ val_seq, const float* __restrict__ delta,
                      const float* __restrict__ W_d,  const float* __restrict__ b_d,
                      const float* __restrict__ W_xt, const float* __restrict__ W_dt,
                      const float* __restrict__ b_t,
                      const float* __restrict__ W_x_s, const float* __restrict__ b_s)
{
    __shared__ float sx[64][20];
    __shared__ float sde[64][32];
    __shared__ float sT[256][16];
    __shared__ float sH[256][16];
    int t = blockIdx.x;
    int b0 = blockIdx.y * 64;
    int bt = b0 >> 7;
    int tid = threadIdx.x;
    size_t abase = ((size_t)t * 32 + bt) * KSP * 128;

    for (int e = tid; e < 64 * 20; e += 256) {
        int b = e / 20, k = e % 20;
        sx[b][k] = val_seq[((size_t)t * B + b0 + b) * MM + k];
    }
    for (int e = tid; e < 64 * 32; e += 256) {
        int b = e >> 5, ee = e & 31;
        float dd = delta[(size_t)t * B + b0 + b];
        sde[b][ee] = tanhf_(dd * W_d[ee] + b_d[ee]);
    }
    __syncthreads();

    int j = tid;
    float wxt[20], wdt[32], wi[20], wo[20], wg[20];
    #pragma unroll
    for (int k = 0; k < 20; k++) wxt[k] = W_xt[k * H + j];
    #pragma unroll
    for (int e = 0; e < 32; e++) wdt[e] = W_dt[e * H + j];
    #pragma unroll
    for (int k = 0; k < 20; k++) {
        wi[k] = W_x_s[k * G4 + j];
        wo[k] = W_x_s[k * G4 + 2 * H + j];
        wg[k] = W_x_s[k * G4 + 3 * H + j];
    }
    float bt_ = b_t[j], bi = b_s[j], bo = b_s[2 * H + j], bg = b_s[3 * H + j];

    for (int bc = 0; bc < 4; bc++) {
        #pragma unroll 1
        for (int bl = 0; bl < 16; bl++) {
            int b = bc * 16 + bl;
            float tx = bt_, td = 0.f, ai = bi, ao = bo, ag = bg;
            #pragma unroll
            for (int k = 0; k < 20; k++) {
                float xv = sx[b][k];
                tx += xv * wxt[k]; ai += xv * wi[k]; ao += xv * wo[k]; ag += xv * wg[k];
            }
            #pragma unroll
            for (int e = 0; e < 32; e++) td += sde[b][e] * wdt[e];
            float T = sigmoidf_(tx + sigmoidf_(td));
            float cns = sigmoidf_(ai) * T * tanhf_(ag);
            sT[j][bl] = T;
            sH[j][bl] = sigmoidf_(ao) * tanhf_(cns);
        }
        __syncthreads();
        for (int e = tid; e < 256 * 16; e += 256) {
            int jj = e >> 4, bl = e & 15;
            int b_local = (b0 & 127) + bc * 16 + bl;
            {
                int tile = bt * 8 + (jj >> 5);
                int wn = (jj >> 4) & 1, j_in = jj & 15, nt = j_in >> 1, cpair = j_in & 1;
                int wm = b_local >> 5, r = b_local & 31;
                int mf = r >> 4, oddb = (r >> 3) & 1, r_lane = r & 7;
                int tidt = ((wn << 2) | wm) * 32 + (oddb | (cpair << 1) | (r_lane << 2));
                int slot = mf * 8 + nt;
                g_Tf[(((size_t)t * 256 + tile) * 256 + tidt) * 16 + slot] = __float2half(sT[jj][bl]);
            }
            int k = 20 + jj;
            int u = b_local >> 3, ee = b_local & 7;
            g_Ah[abase + (size_t)k * 128 + (((u ^ (k & 7)) << 3) + ee)] = __float2half(sH[jj][bl]);
        }
        for (int e = tid; e < 20 * 16; e += 256) {
            int k = e >> 4, bl = e & 15;
            int b_local = (b0 & 127) + bc * 16 + bl;
            int u = b_local >> 3, ee = b_local & 7;
            g_Ah[abase + (size_t)k * 128 + (((u ^ (k & 7)) << 3) + ee)] = __float2half(sx[bc * 16 + bl][k]);
        }
        __syncthreads();
    }
    if (tid < 64) {
        int b_local = (b0 & 127) + tid;
        int u = b_local >> 3, ee = b_local & 7;
        g_Ah[abase + (size_t)276 * 128 + (((u ^ 4) << 3) + ee)] = __float2half(1.f);
    }
}

// ============================================================
// k_seq: persistent recurrence. Per step: dyn GEMM (4 chunks, single-pass)
// accumulating onto register-carried static pre -> epilogue -> arrive ->
// static(t+1) GEMM (5 chunks, overlaps barrier) -> spin.
// 256 CTAs (2/SM). 3-stage 32KB bulk ring shared by both GEMMs.
// ============================================================
__global__ void __launch_bounds__(256, 2) k_seq()
{
    extern __shared__ __align__(16) char sm[];
    __shared__ __align__(8) unsigned long long mbar[SEQ_NSTG];
    __shared__ __align__(16) __half hstage[32 * 128];   // 8KB h staging
    int clin = blockIdx.x;
    int bt = clin >> 3, ntb = clin & 7;
    int gslot = bt * 32;
    int tid = threadIdx.x, lane = tid & 31, wid = tid >> 5;
    int wm = wid & 3, wn = wid >> 2;
    uint32_t smb = smem_u32(sm);
    uint32_t hsb = smem_u32(hstage);
    uint32_t mb[SEQ_NSTG];
    #pragma unroll
    for (int i = 0; i < SEQ_NSTG; i++) mb[i] = smem_u32(&mbar[i]);
    if (tid == 0) {
        #pragma unroll
        for (int i = 0; i < SEQ_NSTG; i++) MBARRIER_INIT(mb[i], 1);
    }
    __syncthreads();
    uint32_t ph[SEQ_NSTG] = {0, 0, 0};
    int gq = 0;   // running chunk counter (stage = gq % 3)

    const __half* Wbase = g_Wh + (size_t)ntb * WROWS * 128;

    int kra = (lane >> 4) * 8 + (lane & 7);
    int ua0 = ((lane >> 3) & 1) + wm * 4;
    int swa = kra & 7;
    int krb = (lane & 7) + ((lane >> 3) & 1) * 8;
    int ub0 = (lane >> 4) + wn * 8;
    int swb = krb & 7;
    uint32_t aoff0 = (uint32_t)(kra * 256);
    uint32_t boff0 = (uint32_t)(krb * 256);

    float acc[2][8][4];
    float* afl = &acc[0][0][0];
    float c_reg[16];
    #pragma unroll
    for (int i = 0; i < 16; i++) c_reg[i] = 0.f;

    int odd = lane & 1, cpair = (lane >> 1) & 1, r_lane = lane >> 2;

    auto issue_chunk = [&](int stg, const __half* aSrc, int wrow) {
        if (tid == 0) {
            MBARRIER_EXPECT_TX(mb[stg], 32768u);
            uint32_t d = smb + (uint32_t)stg * SEQ_STAGE;
            bulkcp(d + OFF_A,  aSrc,                       16384, mb[stg]);
            bulkcp(d + OFF_BH, Wbase + (size_t)wrow * 128, 16384, mb[stg]);
        }
    };
    auto compute_chunk = [&](int stg) {
        uint32_t sb = smb + (uint32_t)stg * SEQ_STAGE;
        #pragma unroll
        for (int kf = 0; kf < 4; kf++) {
            uint32_t kofs = (uint32_t)(kf * 4096);
            uint32_t ah[2][4], bh[4][4];
            #pragma unroll
            for (int mf = 0; mf < 2; mf++)
                ldsm4t(ah[mf], sb + OFF_A + aoff0 + kofs + (uint32_t)(((ua0 + mf * 2) ^ swa) << 4));
            #pragma unroll
            for (int nf = 0; nf < 4; nf++)
                ldsm4t(bh[nf], sb + OFF_BH + boff0 + kofs + (uint32_t)(((ub0 + nf * 2) ^ swb) << 4));
            #pragma unroll
            for (int mf = 0; mf < 2; mf++)
                #pragma unroll
                for (int nf = 0; nf < 4; nf++) {
                    mma_f16(acc[mf][2 * nf],     ah[mf], bh[nf]);
                    mma_f16(acc[mf][2 * nf + 1], ah[mf], bh[nf] + 2);
                }
        }
    };
    auto run_gemm = [&](const __half* A0, int wrow0, int nch) {
        int look = (nch < SEQ_NSTG) ? nch : SEQ_NSTG;
        for (int c = 0; c < look; c++)
            issue_chunk((gq + c) % SEQ_NSTG, A0 + (size_t)c * 64 * 128, wrow0 + c * 64);
        for (int c = 0; c < nch; c++) {
            int stg = (gq + c) % SEQ_NSTG;
            MBARRIER_WAIT_PARITY(mb[stg], ph[stg]); ph[stg] ^= 1;
            compute_chunk(stg);
            __syncthreads();
            if (c + SEQ_NSTG < nch)
                issue_chunk(stg, A0 + (size_t)(c + SEQ_NSTG) * 64 * 128, wrow0 + (c + SEQ_NSTG) * 64);
        }
        gq += nch;
    };

    auto epilogue = [&](int t, const __half* tv) {
        #pragma unroll
        for (int mf = 0; mf < 2; mf++) {
            int b_local = wm * 32 + mf * 16 + r_lane + (odd ? 8 : 0);
            #pragma unroll
            for (int nt = 0; nt < 8; nt++) {
                float d0 = acc[mf][nt][0], d1 = acc[mf][nt][1];
                float d2 = acc[mf][nt][2], d3 = acc[mf][nt][3];
                float s1 = odd ? d0 : d2;
                float s2 = odd ? d1 : d3;
                float r1 = __shfl_xor_sync(0xffffffffu, s1, 1);
                float r2 = __shfl_xor_sync(0xffffffffu, s2, 1);
                float fi = odd ? r1 : d0;
                float ff = odd ? r2 : d1;
                float fo = odd ? d2 : r1;
                float fg = odd ? d3 : r2;
                int slot = mf * 8 + nt;
                float T = __half2float(tv[slot]);
                float cn = sigmoidf_(ff) * c_reg[slot] + sigmoidf_(fi) * T * tanhf_(fg);
                c_reg[slot] = cn;
                float h = sigmoidf_(fo) * tanhf_(cn);
                int j_local = wn * 16 + nt * 2 + cpair;
                hstage[j_local * 128 + (((b_local >> 3) ^ (j_local & 7)) << 3) + (b_local & 7)]
                    = __float2half(h);
            }
        }
        __syncthreads();
        if (tid == 0) {
            asm volatile("fence.proxy.async.shared::cta;" ::: "memory");
            const __half* gdst = g_Hh + (((size_t)t * 32 + bt) * H + ntb * 32) * 128;
            asm volatile("cp.async.bulk.global.shared::cta.bulk_group [%0], [%1], %2;"
                :: "l"(gdst), "r"(hsb), "r"(8192u) : "memory");
            asm volatile("cp.async.bulk.commit_group;" ::: "memory");
            asm volatile("cp.async.bulk.wait_group 0;" ::: "memory");
        }
    };
    auto arrive = [&](int t) {
        if (tid == 0) {
            asm volatile("membar.gl;" ::: "memory");
            int v = atomicAdd(&g_cnt[gslot], 1);
            if (v == GRP - 1) {
                atomicExch(&g_cnt[gslot], 0);
                __threadfence();
                g_gen[gslot] = t + 1;
            }
        }
    };

    // prologue: static preactivation for t=0
    #pragma unroll
    for (int i = 0; i < 64; i++) afl[i] = 0.f;
    run_gemm(g_Ah + (size_t)bt * KSP * 128, 0, 5);

    for (int t = 0; t < SB; t++) {
        // T frag load for this step (hidden under dyn GEMM)
        uint4 traw[2];
        const uint4* tp = (const uint4*)(g_Tf + (((size_t)t * 256 + clin) * 256 + tid) * 16);
        traw[0] = tp[0]; traw[1] = tp[1];

        if (t > 0)
            run_gemm(g_Hh + ((size_t)(t - 1) * 32 + bt) * H * 128, KSP, 4);

        epilogue(t, (const __half*)traw);

        if (t + 1 < SB) {
            arrive(t);
            // static(t+1) overlaps the group barrier wait
            #pragma unroll
            for (int i = 0; i < 64; i++) afl[i] = 0.f;
            run_gemm(g_Ah + ((size_t)(t + 1) * 32 + bt) * KSP * 128, 0, 5);
            if (tid == 0) { while (g_gen[gslot] <= t) __nanosleep(32); }
            __syncthreads();
        }
    }
}

// ============================================================
// k_out: output heads; reads swizzled tiled g_Hh
// ============================================================
__global__ void k_out(const float* __restrict__ Wc, const float* __restrict__ bc,
                      const float* __restrict__ Wm, const float* __restrict__ bm,
                      float* __restrict__ out)
{
    __shared__ float sh[256][32];
    __shared__ float sl[32][25];
    int t = blockIdx.x;
    int b0 = blockIdx.y * 32;
    int bt = b0 >> 7;
    int tid = threadIdx.x;

    for (int e = tid; e < 256 * 32; e += 256) {
        int jj = e >> 5, bb = e & 31;
        int b_local = (b0 & 127) + bb;
        int u = b_local >> 3, ee = b_local & 7;
        sh[jj][bb] = __half2float(
            g_Hh[(((size_t)t * 32 + bt) * H + jj) * 128 + (((u ^ (jj & 7)) << 3) + ee)]);
    }
    __syncthreads();

    for (int o = tid; o < 32 * 25; o += 256) {
        int r = o / 25, jx = o % 25;
        float s;
        if (jx < 3) {
            s = bc[jx];
            #pragma unroll 8
            for (int k = 0; k < H; k++) s += sh[k][r] * Wc[k * 3 + jx];
        } else {
            int jj = jx - 3;
            s = bm[jj];
            #pragma unroll 8
            for (int k = 0; k < H; k++) s += sh[k][r] * Wm[k * 22 + jj];
        }
        sl[r][jx] = s;
    }
    __syncthreads();

    float* out_cat = out;
    float* out_val = out + (size_t)SB * B * 3;
    for (int o = tid; o < 32 * 25; o += 256) {
        int r = o / 25, jx = o % 25;
        int b = b0 + r;
        if (jx < 3) {
            float l0 = sl[r][0], l1 = sl[r][1], l2 = sl[r][2];
            float mx = fmaxf(l0, fmaxf(l1, l2));
            float e0 = fexp2_((l0 - mx) * LOG2E);
            float e1 = fexp2_((l1 - mx) * LOG2E);
            float e2 = fexp2_((l2 - mx) * LOG2E);
            float inv = frcp_(e0 + e1 + e2);
            float v = (jx == 0 ? e0 : (jx == 1 ? e1 : e2)) * inv;
            out_cat[(size_t)t * B * 3 + (size_t)b * 3 + jx] = v;
        } else {
            out_val[(size_t)t * B * 22 + (size_t)b * 22 + (jx - 3)] = sl[r][jx];
        }
    }
}

// ============================================================
// launch
// ============================================================
extern "C" void kernel_launch(void* const* d_in, const int* in_sizes, int n_in,
                              void* d_out, int out_size)
{
    const float* val_seq = (const float*)d_in[1];
    const float* delta   = (const float*)d_in[2];
    const float* W_d     = (const float*)d_in[3];
    const float* b_d     = (const float*)d_in[4];
    const float* W_xt    = (const float*)d_in[5];
    const float* W_dt    = (const float*)d_in[6];
    const float* b_t     = (const float*)d_in[7];
    const float* W_x_s   = (const float*)d_in[8];
    const float* b_s     = (const float*)d_in[10];
    const float* W_x_p   = (const float*)d_in[11];
    const float* W_h_p   = (const float*)d_in[12];
    const float* W_s_p   = (const float*)d_in[13];
    const float* b_p     = (const float*)d_in[14];
    const float* Wc      = (const float*)d_in[15];
    const float* bcv     = (const float*)d_in[16];
    const float* Wm      = (const float*)d_in[17];
    const float* bm      = (const float*)d_in[18];
    float* out = (float*)d_out;

    cudaFuncSetAttribute(k_seq, cudaFuncAttributeMaxDynamicSharedMemorySize, SEQ_SMEM);

    k_packw<<<(8 * WROWS * 128 + 255) / 256, 256>>>(W_x_p, W_h_p, W_s_p, b_p);
    k_pre<<<dim3(SB, B / 64), 256>>>(val_seq, delta, W_d, b_d, W_xt, W_dt, b_t, W_x_s, b_s);
    k_seq<<<NCTA, 256, SEQ_SMEM>>>();
    k_out<<<dim3(SB, B / 32), 256>>>(Wc, bcv, Wm, bm, out);
}

// round 16
// speedup vs baseline: 6.5608x; 1.0416x over previous
#include <cuda_runtime.h>
#include <cuda_fp16.h>
#include <math.h>
#include <stdint.h>

#define S    256
#define SB   255
#define B    4096
#define H    256
#define MM   20
#define G4   1024
#define KSP  320        // static K padded to 5*64 (rows 277..319 zero)
#define WROWS 576       // 320 static + 256 dyn
#define NCTA 256
#define NGRP 32
#define GRP  8

// ---------------- scratch (static device globals; total ~1.74GB) ----------------
__device__ __align__(256) __half g_Tf[(size_t)SB*256*256*16];   // [t][tile][tid][slot] frag layout
__device__ __align__(256) __half g_Ah[(size_t)SB*32*KSP*128];   // [t][bt][k][128 swz]
__device__ __align__(256) __half g_Hh[(size_t)SB*32*H*128];     // [t][bt][j][128 swz]
__device__ __align__(256) __half g_Wh[(size_t)8*WROWS*128];     // [ntb][k][128 swz]
__device__ __align__(256) int g_cnt[NGRP * 32];
__device__ __align__(256) volatile int g_gen[NGRP * 32];

// ---- fast-but-accurate transcendentals (MUFU EX2 + RCP; ~1e-6 rel err) ----
__device__ __forceinline__ float fexp2_(float x) {
    float r; asm("ex2.approx.ftz.f32 %0, %1;" : "=f"(r) : "f"(x)); return r;
}
__device__ __forceinline__ float frcp_(float x) {
    float r; asm("rcp.approx.ftz.f32 %0, %1;" : "=f"(r) : "f"(x)); return r;
}
#define LOG2E 1.4426950408889634f
__device__ __forceinline__ float sigmoidf_(float x) {
    return frcp_(1.f + fexp2_(-x * LOG2E));
}
__device__ __forceinline__ float tanhf_(float x) {
    return 1.f - 2.f * frcp_(1.f + fexp2_(2.f * x * LOG2E));
}

__device__ __forceinline__ uint32_t smem_u32(const void* p) {
    uint32_t a;
    asm("{ .reg .u64 t; cvta.to.shared.u64 t, %1; cvt.u32.u64 %0, t; }" : "=r"(a) : "l"(p));
    return a;
}
__device__ __forceinline__ void ldsm4t(uint32_t* r, uint32_t addr) {
    asm volatile("ldmatrix.sync.aligned.m8n8.x4.trans.shared.b16 {%0,%1,%2,%3}, [%4];"
        : "=r"(r[0]), "=r"(r[1]), "=r"(r[2]), "=r"(r[3]) : "r"(addr));
}
__device__ __forceinline__ void mma_f16(float* d, const uint32_t* a, const uint32_t* b) {
    asm volatile("mma.sync.aligned.m16n8k16.row.col.f32.f16.f16.f32 "
        "{%0,%1,%2,%3}, {%4,%5,%6,%7}, {%8,%9}, {%0,%1,%2,%3};"
        : "+f"(d[0]), "+f"(d[1]), "+f"(d[2]), "+f"(d[3])
        : "r"(a[0]), "r"(a[1]), "r"(a[2]), "r"(a[3]), "r"(b[0]), "r"(b[1]));
}
__device__ __forceinline__ void bulkcp(uint32_t dst, const void* src, uint32_t n, uint32_t mbar) {
    asm volatile("cp.async.bulk.shared::cta.global.mbarrier::complete_tx::bytes [%0], [%1], %2, [%3];"
        :: "r"(dst), "l"(src), "r"(n), "r"(mbar) : "memory");
}
#define MBARRIER_INIT(a, c) \
    asm volatile("mbarrier.init.shared.b64 [%0], %1;" :: "r"((uint32_t)(a)), "r"((uint32_t)(c)) : "memory")
#define MBARRIER_EXPECT_TX(a, n) \
    asm volatile("mbarrier.arrive.expect_tx.shared.b64 _, [%0], %1;" :: "r"((uint32_t)(a)), "r"((uint32_t)(n)) : "memory")
#define MBARRIER_WAIT_PARITY(a, ph) do { \
    uint32_t _m = (uint32_t)(a), _p = (uint32_t)(ph), _d; \
    asm volatile("{\n\t.reg .pred p;\n\t" \
        "mbarrier.try_wait.parity.acquire.cta.shared::cta.b64 p, [%1], %2;\n\t" \
        "selp.b32 %0, 1, 0, p;\n\t}" : "=r"(_d) : "r"(_m), "r"(_p) : "memory"); \
    if (!_d) { \
        asm volatile("{\n\t.reg .pred P1;\n\t" \
            "WL_%=:\n\t" \
            "mbarrier.try_wait.parity.acquire.cta.shared::cta.b64 P1, [%0], %1, 0x989680;\n\t" \
            "@P1 bra.uni WD_%=;\n\t" \
            "bra.uni WL_%=;\n\t" \
            "WD_%=:\n\t}" :: "r"(_m), "r"(_p) : "memory"); \
    } \
} while (0)

// k_seq stage: A 16K + Bh 16K, 3-stage ring
#define OFF_A  0
#define OFF_BH 16384
#define SEQ_STAGE 32768
#define SEQ_NSTG  3
#define SEQ_SMEM  (SEQ_NSTG * SEQ_STAGE)  // 98304

// ============================================================
// k_packw: weights -> [ntb][k][128 swz] fp16; resets group barriers.
// rows: 0-19 W_x_p | 20-275 W_s_p | 276 bias | 277-319 zero | 320-575 W_h_p
// ============================================================
__global__ void k_packw(const float* __restrict__ W_x_p, const float* __restrict__ W_h_p,
                        const float* __restrict__ W_s_p, const float* __restrict__ b_p)
{
    int idx = blockIdx.x * blockDim.x + threadIdx.x;
    if (idx < NGRP * 32) { g_cnt[idx] = 0; g_gen[idx] = 0; }
    if (idx >= 8 * WROWS * 128) return;
    int tile = idx / (WROWS * 128);
    int rem  = idx % (WROWS * 128);
    int k    = rem >> 7;
    int col  = rem & 127;
    int np = tile * 128 + col;
    int j = np >> 2, g = np & 3;
    int scol = g * H + j;
    float v;
    if (k < MM)            v = W_x_p[(size_t)k * G4 + scol];
    else if (k < MM + H)   v = W_s_p[(size_t)(k - MM) * G4 + scol];
    else if (k == 276)     v = b_p[scol];
    else if (k < KSP)      v = 0.f;
    else                   v = W_h_p[(size_t)(k - KSP) * G4 + scol];
    int u = col >> 3, e = col & 7;
    g_Wh[((size_t)tile * WROWS + k) * 128 + (((u ^ (k & 7)) << 3) + e)] = __float2half(v);
}

// ============================================================
// k_pre: T into frag layout g_Tf; static A rows into swizzled tiled g_Ah
// grid (SB, B/64), block 256
// ============================================================
__global__ void k_pre(const float* __restrict__ val_seq, const float* __restrict__ delta,
                      const float* __restrict__ W_d,  const float* __restrict__ b_d,
                      const float* __restrict__ W_xt, const float* __restrict__ W_dt,
                      const float* __restrict__ b_t,
                      const float* __restrict__ W_x_s, const float* __restrict__ b_s)
{
    __shared__ float sx[64][20];
    __shared__ float sde[64][32];
    __shared__ float sT[256][16];
    __shared__ float sH[256][16];
    int t = blockIdx.x;
    int b0 = blockIdx.y * 64;
    int bt = b0 >> 7;
    int tid = threadIdx.x;
    size_t abase = ((size_t)t * 32 + bt) * KSP * 128;

    for (int e = tid; e < 64 * 20; e += 256) {
        int b = e / 20, k = e % 20;
        sx[b][k] = val_seq[((size_t)t * B + b0 + b) * MM + k];
    }
    for (int e = tid; e < 64 * 32; e += 256) {
        int b = e >> 5, ee = e & 31;
        float dd = delta[(size_t)t * B + b0 + b];
        sde[b][ee] = tanhf_(dd * W_d[ee] + b_d[ee]);
    }
    __syncthreads();

    int j = tid;
    float wxt[20], wdt[32], wi[20], wo[20], wg[20];
    #pragma unroll
    for (int k = 0; k < 20; k++) wxt[k] = W_xt[k * H + j];
    #pragma unroll
    for (int e = 0; e < 32; e++) wdt[e] = W_dt[e * H + j];
    #pragma unroll
    for (int k = 0; k < 20; k++) {
        wi[k] = W_x_s[k * G4 + j];
        wo[k] = W_x_s[k * G4 + 2 * H + j];
        wg[k] = W_x_s[k * G4 + 3 * H + j];
    }
    float bt_ = b_t[j], bi = b_s[j], bo = b_s[2 * H + j], bg = b_s[3 * H + j];

    for (int bc = 0; bc < 4; bc++) {
        #pragma unroll 1
        for (int bl = 0; bl < 16; bl++) {
            int b = bc * 16 + bl;
            float tx = bt_, td = 0.f, ai = bi, ao = bo, ag = bg;
            #pragma unroll
            for (int k = 0; k < 20; k++) {
                float xv = sx[b][k];
                tx += xv * wxt[k]; ai += xv * wi[k]; ao += xv * wo[k]; ag += xv * wg[k];
            }
            #pragma unroll
            for (int e = 0; e < 32; e++) td += sde[b][e] * wdt[e];
            float T = sigmoidf_(tx + sigmoidf_(td));
            float cns = sigmoidf_(ai) * T * tanhf_(ag);
            sT[j][bl] = T;
            sH[j][bl] = sigmoidf_(ao) * tanhf_(cns);
        }
        __syncthreads();
        for (int e = tid; e < 256 * 16; e += 256) {
            int jj = e >> 4, bl = e & 15;
            int b_local = (b0 & 127) + bc * 16 + bl;
            {
                int tile = bt * 8 + (jj >> 5);
                int wn = (jj >> 4) & 1, j_in = jj & 15, nt = j_in >> 1, cpair = j_in & 1;
                int wm = b_local >> 5, r = b_local & 31;
                int mf = r >> 4, oddb = (r >> 3) & 1, r_lane = r & 7;
                int tidt = ((wn << 2) | wm) * 32 + (oddb | (cpair << 1) | (r_lane << 2));
                int slot = mf * 8 + nt;
                g_Tf[(((size_t)t * 256 + tile) * 256 + tidt) * 16 + slot] = __float2half(sT[jj][bl]);
            }
            int k = 20 + jj;
            int u = b_local >> 3, ee = b_local & 7;
            g_Ah[abase + (size_t)k * 128 + (((u ^ (k & 7)) << 3) + ee)] = __float2half(sH[jj][bl]);
        }
        for (int e = tid; e < 20 * 16; e += 256) {
            int k = e >> 4, bl = e & 15;
            int b_local = (b0 & 127) + bc * 16 + bl;
            int u = b_local >> 3, ee = b_local & 7;
            g_Ah[abase + (size_t)k * 128 + (((u ^ (k & 7)) << 3) + ee)] = __float2half(sx[bc * 16 + bl][k]);
        }
        __syncthreads();
    }
    if (tid < 64) {
        int b_local = (b0 & 127) + tid;
        int u = b_local >> 3, ee = b_local & 7;
        g_Ah[abase + (size_t)276 * 128 + (((u ^ 4) << 3) + ee)] = __float2half(1.f);
    }
}

// ============================================================
// k_seq: persistent recurrence with producer/publisher warp split.
// Per step: dyn GEMM (4 chunks, copies pre-staged) -> epilogue
//   -> publisher(tid32): S2G h + membar + arrive; producer(tid0): static(t+1)
//   -> pre-issue dyn B -> spin (tid32) -> issue dyn A.
// Static chunk 4 trimmed to 2 kf (rows 288-319 are exact zeros).
// ============================================================
__global__ void __launch_bounds__(256, 2) k_seq()
{
    extern __shared__ __align__(16) char sm[];
    __shared__ __align__(8) unsigned long long mbar[SEQ_NSTG];
    __shared__ __align__(16) __half hstage[32 * 128];   // 8KB h staging
    int clin = blockIdx.x;
    int bt = clin >> 3, ntb = clin & 7;
    int gslot = bt * 32;
    int tid = threadIdx.x, lane = tid & 31, wid = tid >> 5;
    int wm = wid & 3, wn = wid >> 2;
    uint32_t smb = smem_u32(sm);
    uint32_t hsb = smem_u32(hstage);
    uint32_t mb[SEQ_NSTG];
    #pragma unroll
    for (int i = 0; i < SEQ_NSTG; i++) mb[i] = smem_u32(&mbar[i]);
    if (tid == 0) {
        #pragma unroll
        for (int i = 0; i < SEQ_NSTG; i++) MBARRIER_INIT(mb[i], 1);
    }
    __syncthreads();
    uint32_t ph[SEQ_NSTG] = {0, 0, 0};
    int gq = 0;   // running chunk counter (stage = gq % 3)

    const __half* Wbase = g_Wh + (size_t)ntb * WROWS * 128;

    int kra = (lane >> 4) * 8 + (lane & 7);
    int ua0 = ((lane >> 3) & 1) + wm * 4;
    int swa = kra & 7;
    int krb = (lane & 7) + ((lane >> 3) & 1) * 8;
    int ub0 = (lane >> 4) + wn * 8;
    int swb = krb & 7;
    uint32_t aoff0 = (uint32_t)(kra * 256);
    uint32_t boff0 = (uint32_t)(krb * 256);

    float acc[2][8][4];
    float* afl = &acc[0][0][0];
    float c_reg[16];
    #pragma unroll
    for (int i = 0; i < 16; i++) c_reg[i] = 0.f;

    int odd = lane & 1, cpair = (lane >> 1) & 1, r_lane = lane >> 2;

    auto issue_full = [&](int stg, const __half* aSrc, int wrow, uint32_t abytes, uint32_t bbytes) {
        if (tid == 0) {
            MBARRIER_EXPECT_TX(mb[stg], abytes + bbytes);
            uint32_t d = smb + (uint32_t)stg * SEQ_STAGE;
            bulkcp(d + OFF_A,  aSrc,                       abytes, mb[stg]);
            bulkcp(d + OFF_BH, Wbase + (size_t)wrow * 128, bbytes, mb[stg]);
        }
    };
    auto compute_chunk = [&](int stg, int nkf) {
        uint32_t sb = smb + (uint32_t)stg * SEQ_STAGE;
        #pragma unroll 4
        for (int kf = 0; kf < nkf; kf++) {
            uint32_t kofs = (uint32_t)(kf * 4096);
            uint32_t ah[2][4], bh[4][4];
            #pragma unroll
            for (int mf = 0; mf < 2; mf++)
                ldsm4t(ah[mf], sb + OFF_A + aoff0 + kofs + (uint32_t)(((ua0 + mf * 2) ^ swa) << 4));
            #pragma unroll
            for (int nf = 0; nf < 4; nf++)
                ldsm4t(bh[nf], sb + OFF_BH + boff0 + kofs + (uint32_t)(((ub0 + nf * 2) ^ swb) << 4));
            #pragma unroll
            for (int mf = 0; mf < 2; mf++)
                #pragma unroll
                for (int nf = 0; nf < 4; nf++) {
                    mma_f16(acc[mf][2 * nf],     ah[mf], bh[nf]);
                    mma_f16(acc[mf][2 * nf + 1], ah[mf], bh[nf] + 2);
                }
        }
    };

    // dyn GEMM: chunks 0-2 pre-staged (B pre-spin + A post-spin); chunk 3 in-loop
    auto run_dyn = [&](const __half* Ad) {
        for (int c = 0; c < 4; c++) {
            int stg = (gq + c) % SEQ_NSTG;
            MBARRIER_WAIT_PARITY(mb[stg], ph[stg]); ph[stg] ^= 1;
            compute_chunk(stg, 4);
            __syncthreads();
            if (c == 0)
                issue_full((gq + 3) % SEQ_NSTG, Ad + (size_t)3 * 64 * 128, KSP + 192, 16384, 16384);
        }
        gq += 4;
    };
    // static GEMM: 5 chunks, chunk 4 trimmed to 2 kf / 8KB copies
    auto run_static = [&](const __half* A0) {
        for (int c = 0; c < 3; c++)
            issue_full((gq + c) % SEQ_NSTG, A0 + (size_t)c * 64 * 128, c * 64, 16384, 16384);
        for (int c = 0; c < 5; c++) {
            int stg = (gq + c) % SEQ_NSTG;
            MBARRIER_WAIT_PARITY(mb[stg], ph[stg]); ph[stg] ^= 1;
            compute_chunk(stg, (c == 4) ? 2 : 4);
            __syncthreads();
            if (c < 2) {
                int cc = c + 3;
                uint32_t sz = (cc == 4) ? 8192u : 16384u;
                issue_full((gq + cc) % SEQ_NSTG, A0 + (size_t)cc * 64 * 128, cc * 64, sz, sz);
            }
        }
        gq += 5;
    };

    auto epilogue = [&](int t, const __half* tv) {
        #pragma unroll
        for (int mf = 0; mf < 2; mf++) {
            int b_local = wm * 32 + mf * 16 + r_lane + (odd ? 8 : 0);
            #pragma unroll
            for (int nt = 0; nt < 8; nt++) {
                float d0 = acc[mf][nt][0], d1 = acc[mf][nt][1];
                float d2 = acc[mf][nt][2], d3 = acc[mf][nt][3];
                float s1 = odd ? d0 : d2;
                float s2 = odd ? d1 : d3;
                float r1 = __shfl_xor_sync(0xffffffffu, s1, 1);
                float r2 = __shfl_xor_sync(0xffffffffu, s2, 1);
                float fi = odd ? r1 : d0;
                float ff = odd ? r2 : d1;
                float fo = odd ? d2 : r1;
                float fg = odd ? d3 : r2;
                int slot = mf * 8 + nt;
                float T = __half2float(tv[slot]);
                float cn = sigmoidf_(ff) * c_reg[slot] + sigmoidf_(fi) * T * tanhf_(fg);
                c_reg[slot] = cn;
                float h = sigmoidf_(fo) * tanhf_(cn);
                int j_local = wn * 16 + nt * 2 + cpair;
                hstage[j_local * 128 + (((b_local >> 3) ^ (j_local & 7)) << 3) + (b_local & 7)]
                    = __float2half(h);
            }
        }
        __syncthreads();
    };
    // publisher: S2G h + (optionally) release-arrive on the group barrier — tid 32
    auto publish = [&](int t, bool doArrive) {
        if (tid == 32) {
            asm volatile("fence.proxy.async.shared::cta;" ::: "memory");
            const __half* gdst = g_Hh + (((size_t)t * 32 + bt) * H + ntb * 32) * 128;
            asm volatile("cp.async.bulk.global.shared::cta.bulk_group [%0], [%1], %2;"
                :: "l"(gdst), "r"(hsb), "r"(8192u) : "memory");
            asm volatile("cp.async.bulk.commit_group;" ::: "memory");
            asm volatile("cp.async.bulk.wait_group 0;" ::: "memory");
            if (doArrive) {
                asm volatile("membar.gl;" ::: "memory");
                int v = atomicAdd(&g_cnt[gslot], 1);
                if (v == GRP - 1) {
                    atomicExch(&g_cnt[gslot], 0);
                    __threadfence();
                    g_gen[gslot] = t + 1;
                }
            }
        }
    };
    // tail: pre-issue dyn B, spin (tid 32), then issue dyn A for h[t]
    auto stage_next_dyn = [&](int t) {
        if (tid == 0) {
            #pragma unroll
            for (int c = 0; c < 3; c++) {
                int stg = (gq + c) % SEQ_NSTG;
                MBARRIER_EXPECT_TX(mb[stg], 32768u);
                bulkcp(smb + (uint32_t)stg * SEQ_STAGE + OFF_BH,
                       Wbase + (size_t)(KSP + c * 64) * 128, 16384, mb[stg]);
            }
        }
        if (tid == 32) { while (g_gen[gslot] <= t) __nanosleep(32); }
        __syncthreads();
        if (tid == 0) {
            const __half* Ad = g_Hh + ((size_t)t * 32 + bt) * H * 128;
            #pragma unroll
            for (int c = 0; c < 3; c++)
                bulkcp(smb + (uint32_t)((gq + c) % SEQ_NSTG) * SEQ_STAGE + OFF_A,
                       Ad + (size_t)c * 64 * 128, 16384, mb[(gq + c) % SEQ_NSTG]);
        }
    };

    // ---- prologue: static(0) ----
    #pragma unroll
    for (int i = 0; i < 64; i++) afl[i] = 0.f;
    run_static(g_Ah + (size_t)bt * KSP * 128);

    // ---- t = 0 ----
    {
        uint4 traw[2];
        const uint4* tp = (const uint4*)(g_Tf + ((size_t)clin * 256 + tid) * 16);
        traw[0] = tp[0]; traw[1] = tp[1];
        epilogue(0, (const __half*)traw);
        publish(0, true);
        #pragma unroll
        for (int i = 0; i < 64; i++) afl[i] = 0.f;
        run_static(g_Ah + ((size_t)1 * 32 + bt) * KSP * 128);
        stage_next_dyn(0);
    }

    for (int t = 1; t < SB; t++) {
        uint4 traw[2];
        const uint4* tp = (const uint4*)(g_Tf + (((size_t)t * 256 + clin) * 256 + tid) * 16);
        traw[0] = tp[0]; traw[1] = tp[1];

        run_dyn(g_Hh + ((size_t)(t - 1) * 32 + bt) * H * 128);
        epilogue(t, (const __half*)traw);
        publish(t, t + 1 < SB);

        if (t + 1 >= SB) break;
        #pragma unroll
        for (int i = 0; i < 64; i++) afl[i] = 0.f;
        run_static(g_Ah + ((size_t)(t + 1) * 32 + bt) * KSP * 128);
        stage_next_dyn(t);
    }
}

// ============================================================
// k_out: output heads; reads swizzled tiled g_Hh
// ============================================================
__global__ void k_out(const float* __restrict__ Wc, const float* __restrict__ bc,
                      const float* __restrict__ Wm, const float* __restrict__ bm,
                      float* __restrict__ out)
{
    __shared__ float sh[256][32];
    __shared__ float sl[32][25];
    int t = blockIdx.x;
    int b0 = blockIdx.y * 32;
    int bt = b0 >> 7;
    int tid = threadIdx.x;

    for (int e = tid; e < 256 * 32; e += 256) {
        int jj = e >> 5, bb = e & 31;
        int b_local = (b0 & 127) + bb;
        int u = b_local >> 3, ee = b_local & 7;
        sh[jj][bb] = __half2float(
            g_Hh[(((size_t)t * 32 + bt) * H + jj) * 128 + (((u ^ (jj & 7)) << 3) + ee)]);
    }
    __syncthreads();

    for (int o = tid; o < 32 * 25; o += 256) {
        int r = o / 25, jx = o % 25;
        float s;
        if (jx < 3) {
            s = bc[jx];
            #pragma unroll 8
            for (int k = 0; k < H; k++) s += sh[k][r] * Wc[k * 3 + jx];
        } else {
            int jj = jx - 3;
            s = bm[jj];
            #pragma unroll 8
            for (int k = 0; k < H; k++) s += sh[k][r] * Wm[k * 22 + jj];
        }
        sl[r][jx] = s;
    }
    __syncthreads();

    float* out_cat = out;
    float* out_val = out + (size_t)SB * B * 3;
    for (int o = tid; o < 32 * 25; o += 256) {
        int r = o / 25, jx = o % 25;
        int b = b0 + r;
        if (jx < 3) {
            float l0 = sl[r][0], l1 = sl[r][1], l2 = sl[r][2];
            float mx = fmaxf(l0, fmaxf(l1, l2));
            float e0 = fexp2_((l0 - mx) * LOG2E);
            float e1 = fexp2_((l1 - mx) * LOG2E);
            float e2 = fexp2_((l2 - mx) * LOG2E);
            float inv = frcp_(e0 + e1 + e2);
            float v = (jx == 0 ? e0 : (jx == 1 ? e1 : e2)) * inv;
            out_cat[(size_t)t * B * 3 + (size_t)b * 3 + jx] = v;
        } else {
            out_val[(size_t)t * B * 22 + (size_t)b * 22 + (jx - 3)] = sl[r][jx];
        }
    }
}

// ============================================================
// launch
// ============================================================
extern "C" void kernel_launch(void* const* d_in, const int* in_sizes, int n_in,
                              void* d_out, int out_size)
{
    const float* val_seq = (const float*)d_in[1];
    const float* delta   = (const float*)d_in[2];
    const float* W_d     = (const float*)d_in[3];
    const float* b_d     = (const float*)d_in[4];
    const float* W_xt    = (const float*)d_in[5];
    const float* W_dt    = (const float*)d_in[6];
    const float* b_t     = (const float*)d_in[7];
    const float* W_x_s   = (const float*)d_in[8];
    const float* b_s     = (const float*)d_in[10];
    const float* W_x_p   = (const float*)d_in[11];
    const float* W_h_p   = (const float*)d_in[12];
    const float* W_s_p   = (const float*)d_in[13];
    const float* b_p     = (const float*)d_in[14];
    const float* Wc      = (const float*)d_in[15];
    const float* bcv     = (const float*)d_in[16];
    const float* Wm      = (const float*)d_in[17];
    const float* bm      = (const float*)d_in[18];
    float* out = (float*)d_out;

    cudaFuncSetAttribute(k_seq, cudaFuncAttributeMaxDynamicSharedMemorySize, SEQ_SMEM);

    k_packw<<<(8 * WROWS * 128 + 255) / 256, 256>>>(W_x_p, W_h_p, W_s_p, b_p);
    k_pre<<<dim3(SB, B / 64), 256>>>(val_seq, delta, W_d, b_d, W_xt, W_dt, b_t, W_x_s, b_s);
    k_seq<<<NCTA, 256, SEQ_SMEM>>>();
    k_out<<<dim3(SB, B / 32), 256>>>(Wc, bcv, Wm, bm, out);
}